// round 2
// baseline (speedup 1.0000x reference)
#include <cuda_runtime.h>
#include <math.h>

// Problem constants (fixed by the dataset)
#define NN      8000        // nodes
#define ERAW    64000       // raw directed edges
#define ETOT    (ERAW + NN) // + self loops
#define FIN     3201
#define HMAX    1024        // widest hidden (layer1 output H*C = 2*512)

// ---------------- scratch (static device globals; no allocation) -------------
__device__ float g_h0   [(long)NN * FIN];   // normalized input features
__device__ float g_h    [(long)NN * HMAX];  // current hidden state
__device__ float g_xl   [(long)NN * HMAX];
__device__ float g_xr   [(long)NN * HMAX];
__device__ float g_agg  [(long)NN * HMAX];
__device__ float g_e    [(long)ETOT * 2];
__device__ float g_emax [NN * 2];
__device__ float g_denom[NN * 2];
__device__ int   g_src  [ETOT];
__device__ int   g_dst  [ETOT];
__device__ float g_deg  [NN];
__device__ float g_mean [FIN];
__device__ float g_rstd [FIN];
__device__ float g_pred [NN];

// ------------------------------- small utils --------------------------------
__device__ __forceinline__ float atomicMaxFloat(float* addr, float value) {
    int* ai = (int*)addr;
    int old = *ai;
    while (value > __int_as_float(old)) {
        int assumed = old;
        old = atomicCAS(ai, assumed, __float_as_int(value));
        if (old == assumed) break;
    }
    return __int_as_float(old);
}

__global__ void fill_kernel(float* p, float v, long n) {
    long i = (long)blockIdx.x * blockDim.x + threadIdx.x;
    if (i < n) p[i] = v;
}

__global__ void build_edges_kernel(const int* __restrict__ ei, int E) {
    int i = blockIdx.x * blockDim.x + threadIdx.x;
    if (i >= E + NN) return;
    int s, d;
    if (i < E) { s = ei[i]; d = ei[E + i]; }
    else       { s = d = i - E; }
    g_src[i] = s;
    g_dst[i] = d;
    atomicAdd(&g_deg[d], 1.0f);
}

// ------------------------------- batchnorm ----------------------------------
// one thread per feature; rows are coalesced across threads
__global__ void bn_stats_kernel(const float* __restrict__ h, int F) {
    int f = blockIdx.x * blockDim.x + threadIdx.x;
    if (f >= F) return;
    double s = 0.0, s2 = 0.0;
    for (int i = 0; i < NN; i++) {
        float v = h[(long)i * F + f];
        s  += v;
        s2 += (double)v * v;
    }
    double m   = s / NN;
    double var = s2 / NN - m * m;
    g_mean[f] = (float)m;
    g_rstd[f] = rsqrtf((float)var + 1e-5f);
}

__global__ void bn_apply_kernel(const float* __restrict__ in, float* __restrict__ out,
                                const float* __restrict__ gam, const float* __restrict__ bet,
                                int F, int relu) {
    long i = (long)blockIdx.x * blockDim.x + threadIdx.x;
    long total = (long)NN * F;
    if (i >= total) return;
    int f = (int)(i % F);
    float v = (in[i] - g_mean[f]) * g_rstd[f] * gam[f] + bet[f];
    if (relu) v = fmaxf(v, 0.0f);
    out[i] = v;
}

// --------------------------------- SGEMM ------------------------------------
// C[M,N] = A[M,K] @ B[K,N]; 128x128 tile, BK=8, 256 threads, 8x8 per thread
__global__ __launch_bounds__(256) void sgemm_kernel(
    const float* __restrict__ A, const float* __restrict__ B,
    float* __restrict__ C, int M, int N, int K)
{
    __shared__ float As[8][128];
    __shared__ float Bs[8][128];

    int tid = threadIdx.x;
    int tx = tid % 16;          // 0..15 -> N micro
    int ty = tid / 16;          // 0..15 -> M micro
    int row0 = blockIdx.y * 128;
    int col0 = blockIdx.x * 128;

    int ar  = tid >> 1;         // 0..127
    int ak0 = (tid & 1) * 4;    // 0 or 4
    int br  = tid >> 5;         // 0..7
    int bc0 = (tid & 31) * 4;   // 0..124

    float acc[8][8];
    #pragma unroll
    for (int i = 0; i < 8; i++)
        #pragma unroll
        for (int j = 0; j < 8; j++) acc[i][j] = 0.0f;

    for (int k0 = 0; k0 < K; k0 += 8) {
        #pragma unroll
        for (int i = 0; i < 4; i++) {
            int k = k0 + ak0 + i;
            int r = row0 + ar;
            float v = 0.0f;
            if (r < M && k < K) v = A[(long)r * K + k];
            As[ak0 + i][ar] = v;
        }
        #pragma unroll
        for (int i = 0; i < 4; i++) {
            int c = col0 + bc0 + i;
            int k = k0 + br;
            float v = 0.0f;
            if (c < N && k < K) v = B[(long)k * N + c];
            Bs[br][bc0 + i] = v;
        }
        __syncthreads();

        #pragma unroll
        for (int kk = 0; kk < 8; kk++) {
            float ra[8], rb[8];
            #pragma unroll
            for (int i = 0; i < 8; i++) ra[i] = As[kk][ty * 8 + i];
            #pragma unroll
            for (int j = 0; j < 8; j++) rb[j] = Bs[kk][tx * 8 + j];
            #pragma unroll
            for (int i = 0; i < 8; i++)
                #pragma unroll
                for (int j = 0; j < 8; j++)
                    acc[i][j] += ra[i] * rb[j];
        }
        __syncthreads();
    }

    #pragma unroll
    for (int i = 0; i < 8; i++) {
        int r = row0 + ty * 8 + i;
        if (r >= M) continue;
        #pragma unroll
        for (int j = 0; j < 8; j++) {
            int c = col0 + tx * 8 + j;
            if (c < N) C[(long)r * N + c] = acc[i][j];
        }
    }
}

// ------------------------------- GATv2 edge ops ------------------------------
// one warp per (edge, head): e[e,h] = att[h] . leaky_relu(xl[src] + xr[dst])
__global__ void edge_score_kernel(const float* __restrict__ xl, const float* __restrict__ xr,
                                  const float* __restrict__ att, float* __restrict__ esc,
                                  int E, int H, int C) {
    int warp = (blockIdx.x * blockDim.x + threadIdx.x) >> 5;
    int lane = threadIdx.x & 31;
    if (warp >= E * H) return;
    int e = warp / H, h = warp % H;
    const float* pl = xl + (long)g_src[e] * H * C + h * C;
    const float* pr = xr + (long)g_dst[e] * H * C + h * C;
    const float* pa = att + h * C;
    float sum = 0.0f;
    for (int c = lane; c < C; c += 32) {
        float z = pl[c] + pr[c];
        z = (z > 0.0f) ? z : 0.2f * z;
        sum += z * pa[c];
    }
    #pragma unroll
    for (int o = 16; o; o >>= 1) sum += __shfl_xor_sync(0xffffffffu, sum, o);
    if (lane == 0) esc[e * H + h] = sum;
}

__global__ void segmax_kernel(const float* __restrict__ esc, float* __restrict__ emax,
                              int E, int H) {
    int i = blockIdx.x * blockDim.x + threadIdx.x;
    if (i >= E * H) return;
    int e = i / H, h = i % H;
    atomicMaxFloat(&emax[g_dst[e] * H + h], esc[i]);
}

__global__ void expdenom_kernel(float* __restrict__ esc, const float* __restrict__ emax,
                                float* __restrict__ denom, int E, int H) {
    int i = blockIdx.x * blockDim.x + threadIdx.x;
    if (i >= E * H) return;
    int e = i / H, h = i % H;
    float v = expf(esc[i] - emax[g_dst[e] * H + h]);
    esc[i] = v;
    atomicAdd(&denom[g_dst[e] * H + h], v);
}

// one thread per (edge, h*C + c)
__global__ void agg_kernel(const float* __restrict__ xl, const float* __restrict__ ex,
                           const float* __restrict__ denom, float* __restrict__ agg,
                           int E, int H, int C) {
    long idx = (long)blockIdx.x * blockDim.x + threadIdx.x;
    long total = (long)E * H * C;
    if (idx >= total) return;
    int HC = H * C;
    int e   = (int)(idx / HC);
    int rem = (int)(idx % HC);
    int h   = rem / C;
    int d = g_dst[e];
    float alpha = ex[e * H + h] / denom[d * H + h];
    atomicAdd(&agg[(long)d * HC + rem], alpha * xl[(long)g_src[e] * HC + rem]);
}

__global__ void finalize_kernel(const float* __restrict__ agg, const float* __restrict__ bias,
                                float* __restrict__ out, int HC, int relu) {
    long i = (long)blockIdx.x * blockDim.x + threadIdx.x;
    long total = (long)NN * HC;
    if (i >= total) return;
    int n = (int)(i / HC);
    int j = (int)(i % HC);
    float v = agg[i] / g_deg[n] + bias[j];
    if (relu) v = fmaxf(v, 0.0f);
    out[i] = v;
}

// ------------------------------- head + gather -------------------------------
__global__ void head_kernel(const float* __restrict__ h, const float* __restrict__ Wh,
                            const float* __restrict__ bh, float* __restrict__ pred) {
    int warp = (blockIdx.x * blockDim.x + threadIdx.x) >> 5;
    int lane = threadIdx.x & 31;
    if (warp >= NN) return;
    const float* p = h + (long)warp * 512;
    float s = 0.0f;
    for (int c = lane; c < 512; c += 32) s += p[c] * Wh[c];
    #pragma unroll
    for (int o = 16; o; o >>= 1) s += __shfl_xor_sync(0xffffffffu, s, o);
    if (lane == 0) pred[warp] = 1.0f / (1.0f + expf(-(s + bh[0])));
}

__global__ void gather_kernel(const float* __restrict__ pred, const float* __restrict__ y,
                              const int* __restrict__ tidx, float* __restrict__ out, int nt) {
    int i = blockIdx.x * blockDim.x + threadIdx.x;
    if (i >= nt) return;
    int n = tidx[i];
    out[i]      = pred[n];
    out[nt + i] = y[n];
}

// --------------------------------- host side ---------------------------------
static inline long cdiv(long a, long b) { return (a + b - 1) / b; }

extern "C" void kernel_launch(void* const* d_in, const int* in_sizes, int n_in,
                              void* d_out, int out_size) {
    const float* x    = (const float*)d_in[0];
    const int*   ei   = (const int*)  d_in[1];
    const float* y    = (const float*)d_in[2];
    const int*   tidx = (const int*)  d_in[3];
    const float* bn0g = (const float*)d_in[4];
    const float* bn0b = (const float*)d_in[5];
    const float* Wl[4] = { (const float*)d_in[6],  (const float*)d_in[12],
                           (const float*)d_in[18], (const float*)d_in[24] };
    const float* Wr[4] = { (const float*)d_in[7],  (const float*)d_in[13],
                           (const float*)d_in[19], (const float*)d_in[25] };
    const float* att[4] = { (const float*)d_in[8],  (const float*)d_in[14],
                            (const float*)d_in[20], (const float*)d_in[26] };
    const float* bia[4] = { (const float*)d_in[9],  (const float*)d_in[15],
                            (const float*)d_in[21], (const float*)d_in[27] };
    const float* bng[3] = { (const float*)d_in[10], (const float*)d_in[16],
                            (const float*)d_in[22] };
    const float* bnb[3] = { (const float*)d_in[11], (const float*)d_in[17],
                            (const float*)d_in[23] };
    const float* Wh = (const float*)d_in[28];
    const float* bh = (const float*)d_in[29];
    float* out = (float*)d_out;

    int E  = in_sizes[1] / 2;     // 64000
    int nt = in_sizes[3];         // 4000

    float *h0, *h, *xl, *xr, *agg, *esc, *emax, *denom, *deg, *pred;
    int *src_unused;
    cudaGetSymbolAddress((void**)&h0,    g_h0);
    cudaGetSymbolAddress((void**)&h,     g_h);
    cudaGetSymbolAddress((void**)&xl,    g_xl);
    cudaGetSymbolAddress((void**)&xr,    g_xr);
    cudaGetSymbolAddress((void**)&agg,   g_agg);
    cudaGetSymbolAddress((void**)&esc,   g_e);
    cudaGetSymbolAddress((void**)&emax,  g_emax);
    cudaGetSymbolAddress((void**)&denom, g_denom);
    cudaGetSymbolAddress((void**)&deg,   g_deg);
    cudaGetSymbolAddress((void**)&pred,  g_pred);
    (void)src_unused;

    const int T = 256;
    int Etot = E + NN;

    // edges + degree
    fill_kernel<<<cdiv(NN, T), T>>>(deg, 0.0f, NN);
    build_edges_kernel<<<cdiv(Etot, T), T>>>(ei, E);

    // input batchnorm
    bn_stats_kernel<<<cdiv(FIN, T), T>>>(x, FIN);
    bn_apply_kernel<<<cdiv((long)NN * FIN, T), T>>>(x, h0, bn0g, bn0b, FIN, 0);

    const float* cur = h0;
    int dims_in[4]  = { FIN, 1024, 512, 512 };
    int dims_out[4] = { 1024, 512, 512, 512 };
    int heads[4]    = { 2, 1, 1, 1 };

    for (int L = 0; L < 4; L++) {
        int K = dims_in[L], Nc = dims_out[L];
        int H = heads[L], C = Nc / H;
        int HC = Nc;

        // xl = cur @ Wl, xr = cur @ Wr
        {
            dim3 grid(cdiv(Nc, 128), cdiv(NN, 128));
            sgemm_kernel<<<grid, 256>>>(cur, Wl[L], xl, NN, Nc, K);
            sgemm_kernel<<<grid, 256>>>(cur, Wr[L], xr, NN, Nc, K);
        }

        // init segment buffers
        fill_kernel<<<cdiv(NN * H, T), T>>>(emax, -3.0e38f, NN * H);
        fill_kernel<<<cdiv(NN * H, T), T>>>(denom, 0.0f, NN * H);
        fill_kernel<<<cdiv((long)NN * HC, T), T>>>(agg, 0.0f, (long)NN * HC);

        // scores, softmax, aggregate
        edge_score_kernel<<<cdiv((long)Etot * H * 32, T), T>>>(xl, xr, att[L], esc, Etot, H, C);
        segmax_kernel<<<cdiv(Etot * H, T), T>>>(esc, emax, Etot, H);
        expdenom_kernel<<<cdiv(Etot * H, T), T>>>(esc, emax, denom, Etot, H);
        agg_kernel<<<cdiv((long)Etot * HC, T), T>>>(xl, esc, denom, agg, Etot, H, C);

        // mean-aggregate + bias (+ relu on layer 4 which has no BN)
        int relu_here = (L == 3) ? 1 : 0;
        finalize_kernel<<<cdiv((long)NN * HC, T), T>>>(agg, bia[L], h, HC, relu_here);

        // BN + relu for layers 1..3
        if (L < 3) {
            bn_stats_kernel<<<cdiv(HC, T), T>>>(h, HC);
            bn_apply_kernel<<<cdiv((long)NN * HC, T), T>>>(h, h, bng[L], bnb[L], HC, 1);
        }
        cur = h;
    }

    // head + gather
    head_kernel<<<cdiv((long)NN * 32, T), T>>>(h, Wh, bh, pred);
    gather_kernel<<<cdiv(nt, T), T>>>(pred, y, tidx, out, nt);
}

// round 3
// speedup vs baseline: 2.8819x; 2.8819x over previous
#include <cuda_runtime.h>
#include <math.h>

// Problem constants (fixed by the dataset)
#define NN      8000        // nodes
#define MPAD    8064        // padded rows (63 * 128)
#define ERAW    64000
#define ETOT    (ERAW + NN)
#define FIN     3201
#define KPAD    3216        // FIN padded to multiple of 16
#define HMAX    1024

// ---------------- scratch (static device globals; no allocation) -------------
__device__ float g_h0   [(long)MPAD * KPAD];
__device__ float g_h    [(long)MPAD * HMAX];
__device__ float g_xl   [(long)MPAD * HMAX];
__device__ float g_xr   [(long)MPAD * HMAX];
__device__ float g_agg  [(long)NN * HMAX];
__device__ float g_W1lp [(long)KPAD * 1024];
__device__ float g_W1rp [(long)KPAD * 1024];
__device__ float g_e    [(long)ETOT * 2];
__device__ float g_emax [NN * 2];
__device__ float g_denom[NN * 2];
__device__ int   g_src  [ETOT];
__device__ int   g_dst  [ETOT];
__device__ float g_deg  [NN];
__device__ float g_sum  [FIN];
__device__ float g_sumsq[FIN];
__device__ float g_mean [FIN];
__device__ float g_rstd [FIN];
__device__ float g_pred [NN];

// ------------------------------- small utils --------------------------------
__device__ __forceinline__ float atomicMaxFloat(float* addr, float value) {
    int* ai = (int*)addr;
    int old = *ai;
    while (value > __int_as_float(old)) {
        int assumed = old;
        old = atomicCAS(ai, assumed, __float_as_int(value));
        if (old == assumed) break;
    }
    return __int_as_float(old);
}

__global__ void fill_kernel(float* p, float v, long n) {
    long i = (long)blockIdx.x * blockDim.x + threadIdx.x;
    if (i < n) p[i] = v;
}

__global__ void build_edges_kernel(const int* __restrict__ ei, int E) {
    int i = blockIdx.x * blockDim.x + threadIdx.x;
    if (i >= E + NN) return;
    int s, d;
    if (i < E) { s = ei[i]; d = ei[E + i]; }
    else       { s = d = i - E; }
    g_src[i] = s;
    g_dst[i] = d;
    atomicAdd(&g_deg[d], 1.0f);
}

// pad W1 (K=FIN rows) into KPAD rows, zero tail
__global__ void pad_w_kernel(const float* __restrict__ W, float* __restrict__ Wp, int Ncol) {
    long i = (long)blockIdx.x * blockDim.x + threadIdx.x;
    long total = (long)KPAD * Ncol;
    if (i >= total) return;
    int r = (int)(i / Ncol);
    int c = (int)(i % Ncol);
    Wp[i] = (r < FIN) ? W[(long)r * Ncol + c] : 0.0f;
}

// zero h0 pad columns [FIN, KPAD) for all MPAD rows
__global__ void zero_h0_padcols_kernel() {
    int i = blockIdx.x * blockDim.x + threadIdx.x;
    const int PC = KPAD - FIN;
    int total = MPAD * PC;
    if (i >= total) return;
    int r = i / PC, c = FIN + i % PC;
    g_h0[(long)r * KPAD + c] = 0.0f;
}

// ------------------------------- batchnorm ----------------------------------
#define BN_CHUNKS 20
#define BN_ROWS   (NN / BN_CHUNKS)   // 400

__global__ void bn_partial_kernel(const float* __restrict__ h, int F, int stride) {
    int f = blockIdx.x * blockDim.x + threadIdx.x;
    if (f >= F) return;
    int r0 = blockIdx.y * BN_ROWS;
    float s = 0.0f, s2 = 0.0f;
    for (int r = r0; r < r0 + BN_ROWS; r++) {
        float v = h[(long)r * stride + f];
        s += v;
        s2 += v * v;
    }
    atomicAdd(&g_sum[f], s);
    atomicAdd(&g_sumsq[f], s2);
}

__global__ void bn_final_kernel(int F) {
    int f = blockIdx.x * blockDim.x + threadIdx.x;
    if (f >= F) return;
    float m = g_sum[f] / (float)NN;
    float var = g_sumsq[f] / (float)NN - m * m;
    g_mean[f] = m;
    g_rstd[f] = rsqrtf(var + 1e-5f);
}

__global__ void bn_apply_kernel(const float* __restrict__ in, int sin,
                                float* __restrict__ out, int sout,
                                const float* __restrict__ gam, const float* __restrict__ bet,
                                int F, int relu) {
    long i = (long)blockIdx.x * blockDim.x + threadIdx.x;
    long total = (long)NN * F;
    if (i >= total) return;
    int n = (int)(i / F);
    int f = (int)(i % F);
    float v = (in[(long)n * sin + f] - g_mean[f]) * g_rstd[f] * gam[f] + bet[f];
    if (relu) v = fmaxf(v, 0.0f);
    out[(long)n * sout + f] = v;
}

// --------------------------------- SGEMM ------------------------------------
// C[M,N] = A[M,K] @ B[K,N].  Requires M%128==0, N%128==0, K%16==0 (all padded).
// 128x128 tile, BK=16, 256 threads, 8x8 per thread, register-staged double buffer.
__global__ __launch_bounds__(256) void sgemm128(
    const float* __restrict__ A, const float* __restrict__ B,
    float* __restrict__ C, int N, int K)
{
    __shared__ float As[2][16][128];
    __shared__ float Bs[2][16][128];

    const int tid = threadIdx.x;
    const int tx = tid & 15;
    const int ty = tid >> 4;
    const long row0 = (long)blockIdx.y * 128;
    const long col0 = (long)blockIdx.x * 128;

    const int arow = tid >> 2;         // 0..63
    const int ak   = (tid & 3) << 2;   // 0,4,8,12
    const int bk   = tid >> 5;         // 0..7
    const int bcol = (tid & 31) << 2;  // 0..124

    const float* Ap0 = A + (row0 + arow) * K + ak;
    const float* Ap1 = A + (row0 + arow + 64) * K + ak;
    const float* Bp0 = B + (long)bk * N + col0 + bcol;
    const float* Bp1 = B + (long)(bk + 8) * N + col0 + bcol;

    float acc[8][8];
    #pragma unroll
    for (int i = 0; i < 8; i++)
        #pragma unroll
        for (int j = 0; j < 8; j++) acc[i][j] = 0.0f;

    float4 a0 = *(const float4*)Ap0;
    float4 a1 = *(const float4*)Ap1;
    float4 b0 = *(const float4*)Bp0;
    float4 b1 = *(const float4*)Bp1;

    As[0][ak + 0][arow] = a0.x; As[0][ak + 1][arow] = a0.y;
    As[0][ak + 2][arow] = a0.z; As[0][ak + 3][arow] = a0.w;
    As[0][ak + 0][arow + 64] = a1.x; As[0][ak + 1][arow + 64] = a1.y;
    As[0][ak + 2][arow + 64] = a1.z; As[0][ak + 3][arow + 64] = a1.w;
    *(float4*)&Bs[0][bk][bcol]     = b0;
    *(float4*)&Bs[0][bk + 8][bcol] = b1;
    __syncthreads();

    int buf = 0;
    const int ntile = K >> 4;

    for (int t = 1; t < ntile; t++) {
        Ap0 += 16; Ap1 += 16;
        Bp0 += (long)16 * N; Bp1 += (long)16 * N;
        a0 = *(const float4*)Ap0;
        a1 = *(const float4*)Ap1;
        b0 = *(const float4*)Bp0;
        b1 = *(const float4*)Bp1;

        #pragma unroll
        for (int kk = 0; kk < 16; kk++) {
            float ra[8], rb[8];
            *(float4*)(ra)     = *(const float4*)&As[buf][kk][ty * 8];
            *(float4*)(ra + 4) = *(const float4*)&As[buf][kk][ty * 8 + 4];
            *(float4*)(rb)     = *(const float4*)&Bs[buf][kk][tx * 8];
            *(float4*)(rb + 4) = *(const float4*)&Bs[buf][kk][tx * 8 + 4];
            #pragma unroll
            for (int i = 0; i < 8; i++)
                #pragma unroll
                for (int j = 0; j < 8; j++)
                    acc[i][j] += ra[i] * rb[j];
        }

        int nb = buf ^ 1;
        As[nb][ak + 0][arow] = a0.x; As[nb][ak + 1][arow] = a0.y;
        As[nb][ak + 2][arow] = a0.z; As[nb][ak + 3][arow] = a0.w;
        As[nb][ak + 0][arow + 64] = a1.x; As[nb][ak + 1][arow + 64] = a1.y;
        As[nb][ak + 2][arow + 64] = a1.z; As[nb][ak + 3][arow + 64] = a1.w;
        *(float4*)&Bs[nb][bk][bcol]     = b0;
        *(float4*)&Bs[nb][bk + 8][bcol] = b1;
        __syncthreads();
        buf = nb;
    }

    #pragma unroll
    for (int kk = 0; kk < 16; kk++) {
        float ra[8], rb[8];
        *(float4*)(ra)     = *(const float4*)&As[buf][kk][ty * 8];
        *(float4*)(ra + 4) = *(const float4*)&As[buf][kk][ty * 8 + 4];
        *(float4*)(rb)     = *(const float4*)&Bs[buf][kk][tx * 8];
        *(float4*)(rb + 4) = *(const float4*)&Bs[buf][kk][tx * 8 + 4];
        #pragma unroll
        for (int i = 0; i < 8; i++)
            #pragma unroll
            for (int j = 0; j < 8; j++)
                acc[i][j] += ra[i] * rb[j];
    }

    #pragma unroll
    for (int i = 0; i < 8; i++) {
        float* Cp = C + (row0 + ty * 8 + i) * N + col0 + tx * 8;
        *(float4*)Cp       = make_float4(acc[i][0], acc[i][1], acc[i][2], acc[i][3]);
        *(float4*)(Cp + 4) = make_float4(acc[i][4], acc[i][5], acc[i][6], acc[i][7]);
    }
}

// ------------------------------- GATv2 edge ops ------------------------------
__global__ void edge_score_kernel(const float* __restrict__ xl, const float* __restrict__ xr,
                                  const float* __restrict__ att, float* __restrict__ esc,
                                  int E, int H, int C) {
    int warp = (blockIdx.x * blockDim.x + threadIdx.x) >> 5;
    int lane = threadIdx.x & 31;
    if (warp >= E * H) return;
    int e = warp / H, h = warp % H;
    const float* pl = xl + (long)g_src[e] * H * C + h * C;
    const float* pr = xr + (long)g_dst[e] * H * C + h * C;
    const float* pa = att + h * C;
    float sum = 0.0f;
    for (int c = lane; c < C; c += 32) {
        float z = pl[c] + pr[c];
        z = (z > 0.0f) ? z : 0.2f * z;
        sum += z * pa[c];
    }
    #pragma unroll
    for (int o = 16; o; o >>= 1) sum += __shfl_xor_sync(0xffffffffu, sum, o);
    if (lane == 0) esc[e * H + h] = sum;
}

__global__ void segmax_kernel(const float* __restrict__ esc, float* __restrict__ emax,
                              int E, int H) {
    int i = blockIdx.x * blockDim.x + threadIdx.x;
    if (i >= E * H) return;
    int e = i / H, h = i % H;
    atomicMaxFloat(&emax[g_dst[e] * H + h], esc[i]);
}

__global__ void expdenom_kernel(float* __restrict__ esc, const float* __restrict__ emax,
                                float* __restrict__ denom, int E, int H) {
    int i = blockIdx.x * blockDim.x + threadIdx.x;
    if (i >= E * H) return;
    int e = i / H, h = i % H;
    float v = expf(esc[i] - emax[g_dst[e] * H + h]);
    esc[i] = v;
    atomicAdd(&denom[g_dst[e] * H + h], v);
}

__global__ void agg_kernel(const float* __restrict__ xl, const float* __restrict__ ex,
                           const float* __restrict__ denom, float* __restrict__ agg,
                           int E, int H, int C) {
    long idx = (long)blockIdx.x * blockDim.x + threadIdx.x;
    long total = (long)E * H * C;
    if (idx >= total) return;
    int HC = H * C;
    int e   = (int)(idx / HC);
    int rem = (int)(idx % HC);
    int h   = rem / C;
    int d = g_dst[e];
    float alpha = ex[e * H + h] / denom[d * H + h];
    atomicAdd(&agg[(long)d * HC + rem], alpha * xl[(long)g_src[e] * HC + rem]);
}

__global__ void finalize_kernel(const float* __restrict__ agg, const float* __restrict__ bias,
                                float* __restrict__ out, int HC, int relu) {
    long i = (long)blockIdx.x * blockDim.x + threadIdx.x;
    long total = (long)NN * HC;
    if (i >= total) return;
    int n = (int)(i / HC);
    int j = (int)(i % HC);
    float v = agg[i] / g_deg[n] + bias[j];
    if (relu) v = fmaxf(v, 0.0f);
    out[i] = v;
}

// ------------------------------- head + gather -------------------------------
__global__ void head_kernel(const float* __restrict__ h, const float* __restrict__ Wh,
                            const float* __restrict__ bh, float* __restrict__ pred) {
    int warp = (blockIdx.x * blockDim.x + threadIdx.x) >> 5;
    int lane = threadIdx.x & 31;
    if (warp >= NN) return;
    const float* p = h + (long)warp * 512;
    float s = 0.0f;
    for (int c = lane; c < 512; c += 32) s += p[c] * Wh[c];
    #pragma unroll
    for (int o = 16; o; o >>= 1) s += __shfl_xor_sync(0xffffffffu, s, o);
    if (lane == 0) pred[warp] = 1.0f / (1.0f + expf(-(s + bh[0])));
}

__global__ void gather_kernel(const float* __restrict__ pred, const float* __restrict__ y,
                              const int* __restrict__ tidx, float* __restrict__ out, int nt) {
    int i = blockIdx.x * blockDim.x + threadIdx.x;
    if (i >= nt) return;
    int n = tidx[i];
    out[i]      = pred[n];
    out[nt + i] = y[n];
}

// --------------------------------- host side ---------------------------------
static inline long cdiv(long a, long b) { return (a + b - 1) / b; }

extern "C" void kernel_launch(void* const* d_in, const int* in_sizes, int n_in,
                              void* d_out, int out_size) {
    const float* x    = (const float*)d_in[0];
    const int*   ei   = (const int*)  d_in[1];
    const float* y    = (const float*)d_in[2];
    const int*   tidx = (const int*)  d_in[3];
    const float* bn0g = (const float*)d_in[4];
    const float* bn0b = (const float*)d_in[5];
    const float* Wl[4] = { (const float*)d_in[6],  (const float*)d_in[12],
                           (const float*)d_in[18], (const float*)d_in[24] };
    const float* Wr[4] = { (const float*)d_in[7],  (const float*)d_in[13],
                           (const float*)d_in[19], (const float*)d_in[25] };
    const float* att[4] = { (const float*)d_in[8],  (const float*)d_in[14],
                            (const float*)d_in[20], (const float*)d_in[26] };
    const float* bia[4] = { (const float*)d_in[9],  (const float*)d_in[15],
                            (const float*)d_in[21], (const float*)d_in[27] };
    const float* bng[3] = { (const float*)d_in[10], (const float*)d_in[16],
                            (const float*)d_in[22] };
    const float* bnb[3] = { (const float*)d_in[11], (const float*)d_in[17],
                            (const float*)d_in[23] };
    const float* Wh = (const float*)d_in[28];
    const float* bh = (const float*)d_in[29];
    float* out = (float*)d_out;

    int E  = in_sizes[1] / 2;     // 64000
    int nt = in_sizes[3];         // 4000

    float *h0, *h, *xl, *xr, *agg, *esc, *emax, *denom, *deg, *pred;
    float *w1lp, *w1rp, *sum, *sumsq;
    cudaGetSymbolAddress((void**)&h0,    g_h0);
    cudaGetSymbolAddress((void**)&h,     g_h);
    cudaGetSymbolAddress((void**)&xl,    g_xl);
    cudaGetSymbolAddress((void**)&xr,    g_xr);
    cudaGetSymbolAddress((void**)&agg,   g_agg);
    cudaGetSymbolAddress((void**)&esc,   g_e);
    cudaGetSymbolAddress((void**)&emax,  g_emax);
    cudaGetSymbolAddress((void**)&denom, g_denom);
    cudaGetSymbolAddress((void**)&deg,   g_deg);
    cudaGetSymbolAddress((void**)&pred,  g_pred);
    cudaGetSymbolAddress((void**)&w1lp,  g_W1lp);
    cudaGetSymbolAddress((void**)&w1rp,  g_W1rp);
    cudaGetSymbolAddress((void**)&sum,   g_sum);
    cudaGetSymbolAddress((void**)&sumsq, g_sumsq);

    const int T = 256;
    int Etot = E + NN;

    // edges + degree
    fill_kernel<<<cdiv(NN, T), T>>>(deg, 0.0f, NN);
    build_edges_kernel<<<cdiv(Etot, T), T>>>(ei, E);

    // pad layer-1 weights to KPAD rows
    pad_w_kernel<<<cdiv((long)KPAD * 1024, T), T>>>(Wl[0], w1lp, 1024);
    pad_w_kernel<<<cdiv((long)KPAD * 1024, T), T>>>(Wr[0], w1rp, 1024);

    // h0 pad regions: pad columns + pad rows
    zero_h0_padcols_kernel<<<cdiv((long)MPAD * (KPAD - FIN), T), T>>>();
    fill_kernel<<<cdiv((long)(MPAD - NN) * KPAD, T), T>>>(h0 + (long)NN * KPAD, 0.0f,
                                                          (long)(MPAD - NN) * KPAD);

    // input batchnorm: x (stride FIN) -> h0 (stride KPAD)
    fill_kernel<<<cdiv(FIN, T), T>>>(sum, 0.0f, FIN);
    fill_kernel<<<cdiv(FIN, T), T>>>(sumsq, 0.0f, FIN);
    {
        dim3 grid(cdiv(FIN, T), BN_CHUNKS);
        bn_partial_kernel<<<grid, T>>>(x, FIN, FIN);
    }
    bn_final_kernel<<<cdiv(FIN, T), T>>>(FIN);
    bn_apply_kernel<<<cdiv((long)NN * FIN, T), T>>>(x, FIN, h0, KPAD, bn0g, bn0b, FIN, 0);

    const float* cur = h0;
    int lda[4]      = { KPAD, 1024, 512, 512 };  // K of each GEMM (padded)
    int dims_out[4] = { 1024, 512, 512, 512 };
    int heads[4]    = { 2, 1, 1, 1 };
    const float* WlL[4] = { w1lp, Wl[1], Wl[2], Wl[3] };
    const float* WrL[4] = { w1rp, Wr[1], Wr[2], Wr[3] };

    for (int L = 0; L < 4; L++) {
        int K = lda[L], Nc = dims_out[L];
        int H = heads[L], C = Nc / H;
        int HC = Nc;

        // xl = cur @ Wl, xr = cur @ Wr (padded: no bounds checks)
        {
            dim3 grid(Nc / 128, MPAD / 128);
            sgemm128<<<grid, 256>>>(cur, WlL[L], xl, Nc, K);
            sgemm128<<<grid, 256>>>(cur, WrL[L], xr, Nc, K);
        }

        // init segment buffers
        fill_kernel<<<cdiv(NN * H, T), T>>>(emax, -3.0e38f, NN * H);
        fill_kernel<<<cdiv(NN * H, T), T>>>(denom, 0.0f, NN * H);
        fill_kernel<<<cdiv((long)NN * HC, T), T>>>(agg, 0.0f, (long)NN * HC);

        // scores, softmax, aggregate
        edge_score_kernel<<<cdiv((long)Etot * H * 32, T), T>>>(xl, xr, att[L], esc, Etot, H, C);
        segmax_kernel<<<cdiv(Etot * H, T), T>>>(esc, emax, Etot, H);
        expdenom_kernel<<<cdiv(Etot * H, T), T>>>(esc, emax, denom, Etot, H);
        agg_kernel<<<cdiv((long)Etot * HC, T), T>>>(xl, esc, denom, agg, Etot, H, C);

        // mean-aggregate + bias (+ relu on layer 4 which has no BN)
        int relu_here = (L == 3) ? 1 : 0;
        finalize_kernel<<<cdiv((long)NN * HC, T), T>>>(agg, bia[L], h, HC, relu_here);

        // zero h pad rows for next layer's GEMM input
        fill_kernel<<<cdiv((long)(MPAD - NN) * HC, T), T>>>(h + (long)NN * HC, 0.0f,
                                                            (long)(MPAD - NN) * HC);

        // BN + relu for layers 1..3
        if (L < 3) {
            fill_kernel<<<cdiv(HC, T), T>>>(sum, 0.0f, HC);
            fill_kernel<<<cdiv(HC, T), T>>>(sumsq, 0.0f, HC);
            dim3 grid(cdiv(HC, T), BN_CHUNKS);
            bn_partial_kernel<<<grid, T>>>(h, HC, HC);
            bn_final_kernel<<<cdiv(HC, T), T>>>(HC);
            bn_apply_kernel<<<cdiv((long)NN * HC, T), T>>>(h, HC, h, HC, bng[L], bnb[L], HC, 1);
        }
        cur = h;
    }

    // head + gather
    head_kernel<<<cdiv((long)NN * 32, T), T>>>(h, Wh, bh, pred);
    gather_kernel<<<cdiv(nt, T), T>>>(pred, y, tidx, out, nt);
}

// round 5
// speedup vs baseline: 4.6695x; 1.6203x over previous
#include <cuda_runtime.h>
#include <cuda_bf16.h>
#include <math.h>
#include <stdint.h>

// Problem constants (fixed by the dataset)
#define NN      8000        // nodes
#define MPAD    8064        // padded rows (63 * 128)
#define ERAW    64000
#define ETOT    (ERAW + NN)
#define FIN     3201
#define K2MAX   3264        // FIN padded to multiple of 64
#define HMAX    1024

// ---------------- scratch (static device globals; no allocation) -------------
__device__ float g_h    [(long)NN * HMAX];
__device__ float g_xl   [(long)MPAD * HMAX];
__device__ float g_xr   [(long)MPAD * HMAX];
__device__ float g_agg  [(long)NN * HMAX];
__device__ __nv_bfloat16 g_Ahi [(long)MPAD * K2MAX];
__device__ __nv_bfloat16 g_Alo [(long)MPAD * K2MAX];
__device__ __nv_bfloat16 g_Btlhi[(long)HMAX * K2MAX];
__device__ __nv_bfloat16 g_Btllo[(long)HMAX * K2MAX];
__device__ __nv_bfloat16 g_Btrhi[(long)HMAX * K2MAX];
__device__ __nv_bfloat16 g_Btrlo[(long)HMAX * K2MAX];
__device__ float g_e    [(long)ETOT * 2];
__device__ float g_emax [NN * 2];
__device__ float g_denom[NN * 2];
__device__ int   g_src  [ETOT];
__device__ int   g_dst  [ETOT];
__device__ float g_deg  [NN];
__device__ float g_sum  [FIN];
__device__ float g_sumsq[FIN];
__device__ float g_mean [FIN];
__device__ float g_rstd [FIN];
__device__ float g_pred [NN];

// ------------------------------ PTX helpers ----------------------------------
__device__ __forceinline__ uint32_t smem_u32(const void* p) {
    uint32_t a;
    asm("{ .reg .u64 t; cvta.to.shared.u64 t, %1; cvt.u32.u64 %0, t; }"
        : "=r"(a) : "l"(p));
    return a;
}

__device__ __forceinline__ void cp_async16(uint32_t dst, const void* src) {
    asm volatile("cp.async.ca.shared.global [%0], [%1], 16;"
                 :: "r"(dst), "l"(src) : "memory");
}
__device__ __forceinline__ void cp_commit() {
    asm volatile("cp.async.commit_group;" ::: "memory");
}
template<int NG> __device__ __forceinline__ void cp_wait() {
    asm volatile("cp.async.wait_group %0;" :: "n"(NG) : "memory");
}

// mma.sync m16n8k16 bf16 with fp32 accumulate (baseline PTX, works on sm_103)
__device__ __forceinline__ void mma16816(float* c, uint32_t a0, uint32_t a1,
                                         uint32_t a2, uint32_t a3,
                                         uint32_t b0, uint32_t b1) {
    asm volatile(
        "mma.sync.aligned.m16n8k16.row.col.f32.bf16.bf16.f32 "
        "{%0,%1,%2,%3}, {%4,%5,%6,%7}, {%8,%9}, {%0,%1,%2,%3};"
        : "+f"(c[0]), "+f"(c[1]), "+f"(c[2]), "+f"(c[3])
        : "r"(a0), "r"(a1), "r"(a2), "r"(a3), "r"(b0), "r"(b1));
}

// ------------------------------- small utils --------------------------------
__device__ __forceinline__ float atomicMaxFloat(float* addr, float value) {
    int* ai = (int*)addr;
    int old = *ai;
    while (value > __int_as_float(old)) {
        int assumed = old;
        old = atomicCAS(ai, assumed, __float_as_int(value));
        if (old == assumed) break;
    }
    return __int_as_float(old);
}

__global__ void fill_kernel(float* p, float v, long n) {
    long i = (long)blockIdx.x * blockDim.x + threadIdx.x;
    if (i < n) p[i] = v;
}

__global__ void build_edges_kernel(const int* __restrict__ ei, int E) {
    int i = blockIdx.x * blockDim.x + threadIdx.x;
    if (i >= E + NN) return;
    int s, d;
    if (i < E) { s = ei[i]; d = ei[E + i]; }
    else       { s = d = i - E; }
    g_src[i] = s;
    g_dst[i] = d;
    atomicAdd(&g_deg[d], 1.0f);
}

__device__ __forceinline__ void split2(float v, __nv_bfloat16& h, __nv_bfloat16& l) {
    h = __float2bfloat16(v);
    l = __float2bfloat16(v - __bfloat162float(h));
}

// W [Kin x Ncol] fp32 -> Bt_hi/lo [Ncol x K2] bf16 (transposed, zero-padded in K)
__global__ void transpose_split_kernel(const float* __restrict__ W, int Kin, int Ncol, int K2,
                                       __nv_bfloat16* __restrict__ hi,
                                       __nv_bfloat16* __restrict__ lo) {
    __shared__ float tile[32][33];
    int k0 = blockIdx.x * 32;
    int n0 = blockIdx.y * 32;
    int tx = threadIdx.x, ty = threadIdx.y;
    #pragma unroll
    for (int j = 0; j < 4; j++) {
        int k = k0 + ty + 8 * j;
        float v = 0.0f;
        if (k < Kin) v = W[(long)k * Ncol + n0 + tx];
        tile[ty + 8 * j][tx] = v;
    }
    __syncthreads();
    #pragma unroll
    for (int j = 0; j < 4; j++) {
        int n = n0 + ty + 8 * j;
        float v = tile[tx][ty + 8 * j];
        __nv_bfloat16 h, l;
        split2(v, h, l);
        long idx = (long)n * K2 + k0 + tx;
        hi[idx] = h;
        lo[idx] = l;
    }
}

// ------------------------------- batchnorm ----------------------------------
#define BN_CHUNKS 20
#define BN_ROWS   (NN / BN_CHUNKS)

__global__ void bn_partial_kernel(const float* __restrict__ h, int F, int stride) {
    int f = blockIdx.x * blockDim.x + threadIdx.x;
    if (f >= F) return;
    int r0 = blockIdx.y * BN_ROWS;
    float s = 0.0f, s2 = 0.0f;
    for (int r = r0; r < r0 + BN_ROWS; r++) {
        float v = h[(long)r * stride + f];
        s += v;
        s2 += v * v;
    }
    atomicAdd(&g_sum[f], s);
    atomicAdd(&g_sumsq[f], s2);
}

__global__ void bn_final_kernel(int F) {
    int f = blockIdx.x * blockDim.x + threadIdx.x;
    if (f >= F) return;
    float m = g_sum[f] / (float)NN;
    float var = g_sumsq[f] / (float)NN - m * m;
    g_mean[f] = m;
    g_rstd[f] = rsqrtf(var + 1e-5f);
}

// BN-apply + optional relu + bf16 hi/lo split + padding, writing [MPAD x K2]
__global__ void bn_apply_split_kernel(const float* __restrict__ in, int Fin, int K2,
                                      const float* __restrict__ gam, const float* __restrict__ bet,
                                      int relu,
                                      __nv_bfloat16* __restrict__ hi,
                                      __nv_bfloat16* __restrict__ lo) {
    long i = (long)blockIdx.x * blockDim.x + threadIdx.x;
    long total = (long)MPAD * K2;
    if (i >= total) return;
    int row = (int)(i / K2);
    int col = (int)(i % K2);
    float v = 0.0f;
    if (row < NN && col < Fin) {
        v = (in[(long)row * Fin + col] - g_mean[col]) * g_rstd[col] * gam[col] + bet[col];
        if (relu) v = fmaxf(v, 0.0f);
    }
    __nv_bfloat16 h, l;
    split2(v, h, l);
    hi[i] = h;
    lo[i] = l;
}

// --------------------- mma.sync split-bf16 GEMM (x3 terms) -------------------
// C[MPAD,N] = A[MPAD,K2] @ W[K2,N]; A hi/lo [M,K] row-major, Bt = W^T hi/lo [N,K].
// CTA tile 128x128, 8 warps of 64x32, BK=32 double-buffered via cp.async.
#define STR       40                        // smem row stride in bf16 (pad 32->40)
#define BUF_B     (128 * STR * 2)           // 10240 bytes per [128 x STR] buffer
#define A_HI_OFF  0
#define A_LO_OFF  (2 * BUF_B)
#define B_HI_OFF  (4 * BUF_B)
#define B_LO_OFF  (6 * BUF_B)
#define GSMEM     (8 * BUF_B)               // 81920 bytes

__global__ __launch_bounds__(256) void gemm_mma_split(
    const __nv_bfloat16* __restrict__ Ahi, const __nv_bfloat16* __restrict__ Alo,
    const __nv_bfloat16* __restrict__ Bhi, const __nv_bfloat16* __restrict__ Blo,
    float* __restrict__ C, int N, int K2)
{
    extern __shared__ char sm[];
    uint32_t sb = smem_u32(sm);
    const int tid = threadIdx.x;
    const int wid = tid >> 5, lane = tid & 31;
    const int wm = wid & 1, wn = wid >> 1;         // warp: 64 rows x 32 cols
    const int g = lane >> 2, q = lane & 3;
    const long row0 = (long)blockIdx.y * 128;
    const long col0 = (long)blockIdx.x * 128;

    float acc[4][4][4];
    #pragma unroll
    for (int i = 0; i < 4; i++)
        #pragma unroll
        for (int j = 0; j < 4; j++)
            #pragma unroll
            for (int t = 0; t < 4; t++) acc[i][j][t] = 0.0f;

    const int NS = K2 >> 5;   // BK = 32

    // ---- stage loader ----
    auto issue = [&](int s, int buf) {
        int k0 = s << 5;
        #pragma unroll
        for (int it = 0; it < 2; it++) {
            int c = tid + (it << 8);            // 0..511
            int row = c >> 2;
            int kc = (c & 3) * 8;               // bf16 offset, 16B chunks
            uint32_t so = (uint32_t)(buf * BUF_B + row * (STR * 2) + kc * 2);
            long ga = (row0 + row) * K2 + k0 + kc;
            long gb = (col0 + row) * K2 + k0 + kc;
            cp_async16(sb + A_HI_OFF + so, Ahi + ga);
            cp_async16(sb + A_LO_OFF + so, Alo + ga);
            cp_async16(sb + B_HI_OFF + so, Bhi + gb);
            cp_async16(sb + B_LO_OFF + so, Blo + gb);
        }
        cp_commit();
    };

    issue(0, 0);

    for (int s = 0; s < NS; s++) {
        int buf = s & 1;
        if (s + 1 < NS) { issue(s + 1, buf ^ 1); cp_wait<1>(); }
        else            { cp_wait<0>(); }
        __syncthreads();

        const char* aHi = sm + A_HI_OFF + buf * BUF_B;
        const char* aLo = sm + A_LO_OFF + buf * BUF_B;
        const char* bHi = sm + B_HI_OFF + buf * BUF_B;
        const char* bLo = sm + B_LO_OFF + buf * BUF_B;

        #pragma unroll
        for (int kk = 0; kk < 2; kk++) {
            int kb = kk * 16 + 2 * q;           // bf16 col of this lane's pair
            // B fragments for 4 n-tiles (hi & lo)
            uint32_t Bh[4][2], Bl[4][2];
            #pragma unroll
            for (int j = 0; j < 4; j++) {
                int n = wn * 32 + j * 8 + g;
                const char* ph = bHi + n * (STR * 2);
                const char* pl = bLo + n * (STR * 2);
                Bh[j][0] = *(const uint32_t*)(ph + kb * 2);
                Bh[j][1] = *(const uint32_t*)(ph + (kb + 8) * 2);
                Bl[j][0] = *(const uint32_t*)(pl + kb * 2);
                Bl[j][1] = *(const uint32_t*)(pl + (kb + 8) * 2);
            }
            #pragma unroll
            for (int i = 0; i < 4; i++) {
                int r0i = wm * 64 + i * 16 + g;
                const char* p0 = aHi + r0i * (STR * 2);
                const char* p1 = aHi + (r0i + 8) * (STR * 2);
                uint32_t ah0 = *(const uint32_t*)(p0 + kb * 2);
                uint32_t ah1 = *(const uint32_t*)(p1 + kb * 2);
                uint32_t ah2 = *(const uint32_t*)(p0 + (kb + 8) * 2);
                uint32_t ah3 = *(const uint32_t*)(p1 + (kb + 8) * 2);
                const char* q0 = aLo + r0i * (STR * 2);
                const char* q1 = aLo + (r0i + 8) * (STR * 2);
                uint32_t al0 = *(const uint32_t*)(q0 + kb * 2);
                uint32_t al1 = *(const uint32_t*)(q1 + kb * 2);
                uint32_t al2 = *(const uint32_t*)(q0 + (kb + 8) * 2);
                uint32_t al3 = *(const uint32_t*)(q1 + (kb + 8) * 2);
                #pragma unroll
                for (int j = 0; j < 4; j++) {
                    mma16816(acc[i][j], ah0, ah1, ah2, ah3, Bh[j][0], Bh[j][1]);
                    mma16816(acc[i][j], ah0, ah1, ah2, ah3, Bl[j][0], Bl[j][1]);
                    mma16816(acc[i][j], al0, al1, al2, al3, Bh[j][0], Bh[j][1]);
                }
            }
        }
        __syncthreads();
    }

    // epilogue
    #pragma unroll
    for (int i = 0; i < 4; i++) {
        long r = row0 + wm * 64 + i * 16 + g;
        #pragma unroll
        for (int j = 0; j < 4; j++) {
            long cc = col0 + wn * 32 + j * 8 + 2 * q;
            *(float2*)(C + r * N + cc)       = make_float2(acc[i][j][0], acc[i][j][1]);
            *(float2*)(C + (r + 8) * N + cc) = make_float2(acc[i][j][2], acc[i][j][3]);
        }
    }
}

// ------------------------------- GATv2 edge ops ------------------------------
__global__ void edge_score_kernel(const float* __restrict__ xl, const float* __restrict__ xr,
                                  const float* __restrict__ att, float* __restrict__ esc,
                                  int E, int H, int C) {
    int warp = (blockIdx.x * blockDim.x + threadIdx.x) >> 5;
    int lane = threadIdx.x & 31;
    if (warp >= E * H) return;
    int e = warp / H, h = warp % H;
    const float* pl = xl + (long)g_src[e] * H * C + h * C;
    const float* pr = xr + (long)g_dst[e] * H * C + h * C;
    const float* pa = att + h * C;
    float sum = 0.0f;
    for (int c = lane; c < C; c += 32) {
        float z = pl[c] + pr[c];
        z = (z > 0.0f) ? z : 0.2f * z;
        sum += z * pa[c];
    }
    #pragma unroll
    for (int o = 16; o; o >>= 1) sum += __shfl_xor_sync(0xffffffffu, sum, o);
    if (lane == 0) esc[e * H + h] = sum;
}

__global__ void segmax_kernel(const float* __restrict__ esc, float* __restrict__ emax,
                              int E, int H) {
    int i = blockIdx.x * blockDim.x + threadIdx.x;
    if (i >= E * H) return;
    int e = i / H, h = i % H;
    atomicMaxFloat(&emax[g_dst[e] * H + h], esc[i]);
}

__global__ void expdenom_kernel(float* __restrict__ esc, const float* __restrict__ emax,
                                float* __restrict__ denom, int E, int H) {
    int i = blockIdx.x * blockDim.x + threadIdx.x;
    if (i >= E * H) return;
    int e = i / H, h = i % H;
    float v = expf(esc[i] - emax[g_dst[e] * H + h]);
    esc[i] = v;
    atomicAdd(&denom[g_dst[e] * H + h], v);
}

__global__ void agg_kernel(const float* __restrict__ xl, const float* __restrict__ ex,
                           const float* __restrict__ denom, float* __restrict__ agg,
                           int E, int H, int C) {
    long idx = (long)blockIdx.x * blockDim.x + threadIdx.x;
    long total = (long)E * H * C;
    if (idx >= total) return;
    int HC = H * C;
    int e   = (int)(idx / HC);
    int rem = (int)(idx % HC);
    int h   = rem / C;
    int d = g_dst[e];
    float alpha = ex[e * H + h] / denom[d * H + h];
    atomicAdd(&agg[(long)d * HC + rem], alpha * xl[(long)g_src[e] * HC + rem]);
}

__global__ void finalize_kernel(const float* __restrict__ agg, const float* __restrict__ bias,
                                float* __restrict__ out, int HC, int relu) {
    long i = (long)blockIdx.x * blockDim.x + threadIdx.x;
    long total = (long)NN * HC;
    if (i >= total) return;
    int n = (int)(i / HC);
    int j = (int)(i % HC);
    float v = agg[i] / g_deg[n] + bias[j];
    if (relu) v = fmaxf(v, 0.0f);
    out[i] = v;
}

// ------------------------------- head + gather -------------------------------
__global__ void head_kernel(const float* __restrict__ h, const float* __restrict__ Wh,
                            const float* __restrict__ bh, float* __restrict__ pred) {
    int warp = (blockIdx.x * blockDim.x + threadIdx.x) >> 5;
    int lane = threadIdx.x & 31;
    if (warp >= NN) return;
    const float* p = h + (long)warp * 512;
    float s = 0.0f;
    for (int c = lane; c < 512; c += 32) s += p[c] * Wh[c];
    #pragma unroll
    for (int o = 16; o; o >>= 1) s += __shfl_xor_sync(0xffffffffu, s, o);
    if (lane == 0) pred[warp] = 1.0f / (1.0f + expf(-(s + bh[0])));
}

__global__ void gather_kernel(const float* __restrict__ pred, const float* __restrict__ y,
                              const int* __restrict__ tidx, float* __restrict__ out, int nt) {
    int i = blockIdx.x * blockDim.x + threadIdx.x;
    if (i >= nt) return;
    int n = tidx[i];
    out[i]      = pred[n];
    out[nt + i] = y[n];
}

// --------------------------------- host side ---------------------------------
static inline long cdiv(long a, long b) { return (a + b - 1) / b; }

extern "C" void kernel_launch(void* const* d_in, const int* in_sizes, int n_in,
                              void* d_out, int out_size) {
    const float* x    = (const float*)d_in[0];
    const int*   ei   = (const int*)  d_in[1];
    const float* y    = (const float*)d_in[2];
    const int*   tidx = (const int*)  d_in[3];
    const float* bn0g = (const float*)d_in[4];
    const float* bn0b = (const float*)d_in[5];
    const float* Wl[4] = { (const float*)d_in[6],  (const float*)d_in[12],
                           (const float*)d_in[18], (const float*)d_in[24] };
    const float* Wr[4] = { (const float*)d_in[7],  (const float*)d_in[13],
                           (const float*)d_in[19], (const float*)d_in[25] };
    const float* att[4] = { (const float*)d_in[8],  (const float*)d_in[14],
                            (const float*)d_in[20], (const float*)d_in[26] };
    const float* bia[4] = { (const float*)d_in[9],  (const float*)d_in[15],
                            (const float*)d_in[21], (const float*)d_in[27] };
    const float* bng[3] = { (const float*)d_in[10], (const float*)d_in[16],
                            (const float*)d_in[22] };
    const float* bnb[3] = { (const float*)d_in[11], (const float*)d_in[17],
                            (const float*)d_in[23] };
    const float* Wh = (const float*)d_in[28];
    const float* bh = (const float*)d_in[29];
    float* out = (float*)d_out;

    int E  = in_sizes[1] / 2;     // 64000
    int nt = in_sizes[3];         // 4000

    float *h, *xl, *xr, *agg, *esc, *emax, *denom, *deg, *pred, *sum, *sumsq;
    __nv_bfloat16 *ahi, *alo, *btlhi, *btllo, *btrhi, *btrlo;
    cudaGetSymbolAddress((void**)&h,     g_h);
    cudaGetSymbolAddress((void**)&xl,    g_xl);
    cudaGetSymbolAddress((void**)&xr,    g_xr);
    cudaGetSymbolAddress((void**)&agg,   g_agg);
    cudaGetSymbolAddress((void**)&esc,   g_e);
    cudaGetSymbolAddress((void**)&emax,  g_emax);
    cudaGetSymbolAddress((void**)&denom, g_denom);
    cudaGetSymbolAddress((void**)&deg,   g_deg);
    cudaGetSymbolAddress((void**)&pred,  g_pred);
    cudaGetSymbolAddress((void**)&sum,   g_sum);
    cudaGetSymbolAddress((void**)&sumsq, g_sumsq);
    cudaGetSymbolAddress((void**)&ahi,   g_Ahi);
    cudaGetSymbolAddress((void**)&alo,   g_Alo);
    cudaGetSymbolAddress((void**)&btlhi, g_Btlhi);
    cudaGetSymbolAddress((void**)&btllo, g_Btllo);
    cudaGetSymbolAddress((void**)&btrhi, g_Btrhi);
    cudaGetSymbolAddress((void**)&btrlo, g_Btrlo);

    cudaFuncSetAttribute(gemm_mma_split, cudaFuncAttributeMaxDynamicSharedMemorySize, GSMEM);

    const int T = 256;
    int Etot = E + NN;

    // edges + degree
    fill_kernel<<<cdiv(NN, T), T>>>(deg, 0.0f, NN);
    build_edges_kernel<<<cdiv(Etot, T), T>>>(ei, E);

    int Kin [4] = { FIN, 1024, 512, 512 };
    int K2s [4] = { K2MAX, 1024, 512, 512 };
    int Ncs [4] = { 1024, 512, 512, 512 };
    int heads[4] = { 2, 1, 1, 1 };

    for (int L = 0; L < 4; L++) {
        int KI = Kin[L], K2 = K2s[L], Nc = Ncs[L];
        int H = heads[L], C = Nc / H;
        int HC = Nc;

        // weight transpose + split
        {
            dim3 grid(K2 / 32, Nc / 32), blk(32, 8);
            transpose_split_kernel<<<grid, blk>>>(Wl[L], KI, Nc, K2, btlhi, btllo);
            transpose_split_kernel<<<grid, blk>>>(Wr[L], KI, Nc, K2, btrhi, btrlo);
        }

        // BN (train-mode stats) + relu(for L>0) + split + pad into A_hi/A_lo
        {
            const float* src = (L == 0) ? x : h;
            const float* g = (L == 0) ? bn0g : bng[L - 1];
            const float* b = (L == 0) ? bn0b : bnb[L - 1];
            int relu = (L == 0) ? 0 : 1;
            fill_kernel<<<cdiv(KI, T), T>>>(sum, 0.0f, KI);
            fill_kernel<<<cdiv(KI, T), T>>>(sumsq, 0.0f, KI);
            dim3 grid(cdiv(KI, T), BN_CHUNKS);
            bn_partial_kernel<<<grid, T>>>(src, KI, KI);
            bn_final_kernel<<<cdiv(KI, T), T>>>(KI);
            bn_apply_split_kernel<<<cdiv((long)MPAD * K2, T), T>>>(src, KI, K2, g, b, relu,
                                                                   ahi, alo);
        }

        // xl = A @ Wl, xr = A @ Wr via mma.sync split-bf16
        {
            dim3 grid(Nc / 128, MPAD / 128);
            gemm_mma_split<<<grid, 256, GSMEM>>>(ahi, alo, btlhi, btllo, xl, Nc, K2);
            gemm_mma_split<<<grid, 256, GSMEM>>>(ahi, alo, btrhi, btrlo, xr, Nc, K2);
        }

        // init segment buffers
        fill_kernel<<<cdiv(NN * H, T), T>>>(emax, -3.0e38f, NN * H);
        fill_kernel<<<cdiv(NN * H, T), T>>>(denom, 0.0f, NN * H);
        fill_kernel<<<cdiv((long)NN * HC, T), T>>>(agg, 0.0f, (long)NN * HC);

        // scores, softmax, aggregate
        edge_score_kernel<<<cdiv((long)Etot * H * 32, T), T>>>(xl, xr, att[L], esc, Etot, H, C);
        segmax_kernel<<<cdiv(Etot * H, T), T>>>(esc, emax, Etot, H);
        expdenom_kernel<<<cdiv(Etot * H, T), T>>>(esc, emax, denom, Etot, H);
        agg_kernel<<<cdiv((long)Etot * HC, T), T>>>(xl, esc, denom, agg, Etot, H, C);

        // mean-aggregate + bias (+ relu on layer 4 which has no BN)
        int relu_here = (L == 3) ? 1 : 0;
        finalize_kernel<<<cdiv((long)NN * HC, T), T>>>(agg, bia[L], h, HC, relu_here);
    }

    // head + gather
    head_kernel<<<cdiv((long)NN * 32, T), T>>>(h, Wh, bh, pred);
    gather_kernel<<<cdiv(nt, T), T>>>(pred, y, tidx, out, nt);
}

// round 6
// speedup vs baseline: 7.2353x; 1.5495x over previous
#include <cuda_runtime.h>
#include <cuda_bf16.h>
#include <math.h>
#include <stdint.h>

// Problem constants (fixed by the dataset)
#define NN      8000
#define MPAD    8064        // 63 * 128
#define ERAW    64000
#define ETOT    (ERAW + NN)
#define FIN     3201
#define K2MAX   3264        // FIN padded to multiple of 64
#define HMAX    1024
#define BN_CHUNKS 20
#define BN_ROWS   (NN / BN_CHUNKS)

// ---------------- scratch (static device globals; no allocation) -------------
__device__ float g_h    [(long)NN * HMAX];
__device__ float g_xl   [(long)MPAD * HMAX];
__device__ float g_xr   [(long)MPAD * HMAX];
__device__ __nv_bfloat16 g_Ahi [(long)MPAD * K2MAX];
__device__ __nv_bfloat16 g_Alo [(long)MPAD * K2MAX];
__device__ __nv_bfloat16 g_Btlhi[(long)HMAX * K2MAX];
__device__ __nv_bfloat16 g_Btllo[(long)HMAX * K2MAX];
__device__ __nv_bfloat16 g_Btrhi[(long)HMAX * K2MAX];
__device__ __nv_bfloat16 g_Btrlo[(long)HMAX * K2MAX];
__device__ float g_e    [(long)ETOT * 2];
__device__ float g_alpha[(long)ETOT * 2];
__device__ int   g_src  [ETOT];
__device__ int   g_dst  [ETOT];
__device__ int   g_cnt  [NN];
__device__ int   g_cur  [NN];
__device__ int   g_off  [NN + 1];
__device__ int   g_csrc [ETOT];
__device__ int   g_ceid [ETOT];
__device__ float g_bnp1 [BN_CHUNKS * K2MAX];
__device__ float g_bnp2 [BN_CHUNKS * K2MAX];
__device__ float g_mean [FIN];
__device__ float g_rstd [FIN];
__device__ float g_pred [NN];

// ------------------------------ PTX helpers ----------------------------------
__device__ __forceinline__ uint32_t smem_u32(const void* p) {
    uint32_t a;
    asm("{ .reg .u64 t; cvta.to.shared.u64 t, %1; cvt.u32.u64 %0, t; }"
        : "=r"(a) : "l"(p));
    return a;
}
__device__ __forceinline__ void cp_async16(uint32_t dst, const void* src) {
    asm volatile("cp.async.ca.shared.global [%0], [%1], 16;"
                 :: "r"(dst), "l"(src) : "memory");
}
__device__ __forceinline__ void cp_commit() {
    asm volatile("cp.async.commit_group;" ::: "memory");
}
template<int NG> __device__ __forceinline__ void cp_wait() {
    asm volatile("cp.async.wait_group %0;" :: "n"(NG) : "memory");
}
__device__ __forceinline__ void mma16816(float* c, const uint32_t* a,
                                         uint32_t b0, uint32_t b1) {
    asm volatile(
        "mma.sync.aligned.m16n8k16.row.col.f32.bf16.bf16.f32 "
        "{%0,%1,%2,%3}, {%4,%5,%6,%7}, {%8,%9}, {%0,%1,%2,%3};"
        : "+f"(c[0]), "+f"(c[1]), "+f"(c[2]), "+f"(c[3])
        : "r"(a[0]), "r"(a[1]), "r"(a[2]), "r"(a[3]), "r"(b0), "r"(b1));
}
__device__ __forceinline__ void ldm_x4(uint32_t* r, uint32_t addr) {
    asm volatile("ldmatrix.sync.aligned.m8n8.x4.shared.b16 {%0,%1,%2,%3}, [%4];"
                 : "=r"(r[0]), "=r"(r[1]), "=r"(r[2]), "=r"(r[3]) : "r"(addr));
}

// ------------------------------- small utils --------------------------------
__global__ void fill_int_kernel(int* p, int v, int n) {
    int i = blockIdx.x * blockDim.x + threadIdx.x;
    if (i < n) p[i] = v;
}

__global__ void build_edges_kernel(const int* __restrict__ ei, int E) {
    int i = blockIdx.x * blockDim.x + threadIdx.x;
    if (i >= E + NN) return;
    int s, d;
    if (i < E) { s = ei[i]; d = ei[E + i]; }
    else       { s = d = i - E; }
    g_src[i] = s;
    g_dst[i] = d;
    atomicAdd(&g_cnt[d], 1);
}

// single-block exclusive scan over g_cnt -> g_off
__global__ void scan_kernel() {
    __shared__ int part[256];
    int tid = threadIdx.x;
    const int CH = (NN + 255) / 256;
    int base = tid * CH;
    int s = 0;
    for (int i = 0; i < CH; i++) { int n = base + i; if (n < NN) s += g_cnt[n]; }
    part[tid] = s;
    __syncthreads();
    if (tid == 0) {
        int acc = 0;
        for (int i = 0; i < 256; i++) { int t = part[i]; part[i] = acc; acc += t; }
    }
    __syncthreads();
    int acc = part[tid];
    for (int i = 0; i < CH; i++) {
        int n = base + i;
        if (n < NN) { g_off[n] = acc; acc += g_cnt[n]; }
    }
    if (tid == 255) g_off[NN] = acc;
}

__global__ void scatter_kernel(const int* __restrict__ ei, int E) {
    int i = blockIdx.x * blockDim.x + threadIdx.x;
    if (i >= E + NN) return;
    int s, d;
    if (i < E) { s = ei[i]; d = ei[E + i]; }
    else       { s = d = i - E; }
    int pos = g_off[d] + atomicAdd(&g_cur[d], 1);
    g_csrc[pos] = s;
    g_ceid[pos] = i;
}

__device__ __forceinline__ void split2(float v, __nv_bfloat16& h, __nv_bfloat16& l) {
    h = __float2bfloat16(v);
    l = __float2bfloat16(v - __bfloat162float(h));
}

// W [Kin x Ncol] fp32 -> Bt_hi/lo [Ncol x K2] bf16 (transposed, zero-padded in K)
__global__ void transpose_split_kernel(const float* __restrict__ W, int Kin, int Ncol, int K2,
                                       __nv_bfloat16* __restrict__ hi,
                                       __nv_bfloat16* __restrict__ lo) {
    __shared__ float tile[32][33];
    int k0 = blockIdx.x * 32;
    int n0 = blockIdx.y * 32;
    int tx = threadIdx.x, ty = threadIdx.y;
    #pragma unroll
    for (int j = 0; j < 4; j++) {
        int k = k0 + ty + 8 * j;
        float v = 0.0f;
        if (k < Kin) v = W[(long)k * Ncol + n0 + tx];
        tile[ty + 8 * j][tx] = v;
    }
    __syncthreads();
    #pragma unroll
    for (int j = 0; j < 4; j++) {
        int n = n0 + ty + 8 * j;
        float v = tile[tx][ty + 8 * j];
        __nv_bfloat16 h, l;
        split2(v, h, l);
        long idx = (long)n * K2 + k0 + tx;
        hi[idx] = h;
        lo[idx] = l;
    }
}

// ------------------------------- batchnorm ----------------------------------
__global__ void bn_partial_kernel(const float* __restrict__ h, int F, int stride) {
    int f = blockIdx.x * blockDim.x + threadIdx.x;
    if (f >= F) return;
    int r0 = blockIdx.y * BN_ROWS;
    float s = 0.0f, s2 = 0.0f;
    for (int r = r0; r < r0 + BN_ROWS; r++) {
        float v = h[(long)r * stride + f];
        s += v;
        s2 += v * v;
    }
    g_bnp1[blockIdx.y * F + f] = s;
    g_bnp2[blockIdx.y * F + f] = s2;
}

__global__ void bn_final_kernel(int F) {
    int f = blockIdx.x * blockDim.x + threadIdx.x;
    if (f >= F) return;
    float s = 0.0f, s2 = 0.0f;
    #pragma unroll
    for (int c = 0; c < BN_CHUNKS; c++) { s += g_bnp1[c * F + f]; s2 += g_bnp2[c * F + f]; }
    float m = s / (float)NN;
    float var = s2 / (float)NN - m * m;
    g_mean[f] = m;
    g_rstd[f] = rsqrtf(var + 1e-5f);
}

// BN-apply + optional relu + bf16 hi/lo split + padding, writing [MPAD x K2]
__global__ void bn_apply_split_kernel(const float* __restrict__ in, int Fin, int K2,
                                      const float* __restrict__ gam, const float* __restrict__ bet,
                                      int relu,
                                      __nv_bfloat16* __restrict__ hi,
                                      __nv_bfloat16* __restrict__ lo) {
    long i = (long)blockIdx.x * blockDim.x + threadIdx.x;
    long total = (long)MPAD * K2;
    if (i >= total) return;
    int row = (int)(i / K2);
    int col = (int)(i % K2);
    float v = 0.0f;
    if (row < NN && col < Fin) {
        v = (in[(long)row * Fin + col] - g_mean[col]) * g_rstd[col] * gam[col] + bet[col];
        if (relu) v = fmaxf(v, 0.0f);
    }
    __nv_bfloat16 h, l;
    split2(v, h, l);
    hi[i] = h;
    lo[i] = l;
}

// --------------------- mma.sync split-bf16 GEMM (x3 terms) -------------------
#define STR       40
#define BUF_B     (128 * STR * 2)
#define A_HI_OFF  0
#define A_LO_OFF  (2 * BUF_B)
#define B_HI_OFF  (4 * BUF_B)
#define B_LO_OFF  (6 * BUF_B)
#define GSMEM     (8 * BUF_B)

__global__ __launch_bounds__(256) void gemm_mma_split(
    const __nv_bfloat16* __restrict__ Ahi, const __nv_bfloat16* __restrict__ Alo,
    const __nv_bfloat16* __restrict__ Bhi, const __nv_bfloat16* __restrict__ Blo,
    float* __restrict__ C, int N, int K2)
{
    extern __shared__ char sm[];
    uint32_t sb = smem_u32(sm);
    const int tid = threadIdx.x;
    const int wid = tid >> 5, lane = tid & 31;
    const int wm = wid & 1, wn = wid >> 1;
    const int g = lane >> 2, q = lane & 3;
    const long row0 = (long)blockIdx.y * 128;
    const long col0 = (long)blockIdx.x * 128;

    float acc[4][4][4];
    #pragma unroll
    for (int i = 0; i < 4; i++)
        #pragma unroll
        for (int j = 0; j < 4; j++)
            #pragma unroll
            for (int t = 0; t < 4; t++) acc[i][j][t] = 0.0f;

    const int NS = K2 >> 5;

    auto issue = [&](int s, int buf) {
        int k0 = s << 5;
        #pragma unroll
        for (int it = 0; it < 2; it++) {
            int c = tid + (it << 8);
            int row = c >> 2;
            int kc = (c & 3) * 8;
            uint32_t so = (uint32_t)(buf * BUF_B + row * (STR * 2) + kc * 2);
            long ga = (row0 + row) * K2 + k0 + kc;
            long gb = (col0 + row) * K2 + k0 + kc;
            cp_async16(sb + A_HI_OFF + so, Ahi + ga);
            cp_async16(sb + A_LO_OFF + so, Alo + ga);
            cp_async16(sb + B_HI_OFF + so, Bhi + gb);
            cp_async16(sb + B_LO_OFF + so, Blo + gb);
        }
        cp_commit();
    };

    // ldmatrix per-lane address offsets (within a buffer)
    const uint32_t aoff = (uint32_t)((wm * 64 + (lane & 15)) * (STR * 2) + (lane >> 4) * 16);
    const uint32_t boff = (uint32_t)((wn * 32 + ((lane >> 4) & 1) * 8 + (lane & 7)) * (STR * 2)
                                     + ((lane >> 3) & 1) * 16);

    issue(0, 0);

    for (int s = 0; s < NS; s++) {
        int buf = s & 1;
        if (s + 1 < NS) { issue(s + 1, buf ^ 1); cp_wait<1>(); }
        else            { cp_wait<0>(); }
        __syncthreads();

        uint32_t ahi_b = sb + A_HI_OFF + buf * BUF_B;
        uint32_t alo_b = sb + A_LO_OFF + buf * BUF_B;
        uint32_t bhi_b = sb + B_HI_OFF + buf * BUF_B;
        uint32_t blo_b = sb + B_LO_OFF + buf * BUF_B;

        #pragma unroll
        for (int kk = 0; kk < 2; kk++) {
            uint32_t kByte = (uint32_t)(kk * 32);      // 16 bf16
            uint32_t Bh[8], Bl[8];
            #pragma unroll
            for (int jp = 0; jp < 2; jp++) {
                uint32_t off = boff + kByte + (uint32_t)(jp * 16 * (STR * 2));
                ldm_x4(&Bh[jp * 4], bhi_b + off);
                ldm_x4(&Bl[jp * 4], blo_b + off);
            }
            #pragma unroll
            for (int i = 0; i < 4; i++) {
                uint32_t off = aoff + kByte + (uint32_t)(i * 16 * (STR * 2));
                uint32_t ah[4], al[4];
                ldm_x4(ah, ahi_b + off);
                ldm_x4(al, alo_b + off);
                #pragma unroll
                for (int j = 0; j < 4; j++) mma16816(acc[i][j], ah, Bh[2*j], Bh[2*j+1]);
                #pragma unroll
                for (int j = 0; j < 4; j++) mma16816(acc[i][j], ah, Bl[2*j], Bl[2*j+1]);
                #pragma unroll
                for (int j = 0; j < 4; j++) mma16816(acc[i][j], al, Bh[2*j], Bh[2*j+1]);
            }
        }
        __syncthreads();
    }

    #pragma unroll
    for (int i = 0; i < 4; i++) {
        long r = row0 + wm * 64 + i * 16 + g;
        #pragma unroll
        for (int j = 0; j < 4; j++) {
            long cc = col0 + wn * 32 + j * 8 + 2 * q;
            *(float2*)(C + r * N + cc)       = make_float2(acc[i][j][0], acc[i][j][1]);
            *(float2*)(C + (r + 8) * N + cc) = make_float2(acc[i][j][2], acc[i][j][3]);
        }
    }
}

// ------------------------------- GATv2 edge ops ------------------------------
__global__ void edge_score_kernel(const float* __restrict__ xl, const float* __restrict__ xr,
                                  const float* __restrict__ att, float* __restrict__ esc,
                                  int E, int H, int C) {
    int warp = (blockIdx.x * blockDim.x + threadIdx.x) >> 5;
    int lane = threadIdx.x & 31;
    if (warp >= E * H) return;
    int e = warp / H, h = warp % H;
    const float* pl = xl + (long)g_src[e] * H * C + h * C;
    const float* pr = xr + (long)g_dst[e] * H * C + h * C;
    const float* pa = att + h * C;
    float sum = 0.0f;
    for (int c = lane * 4; c < C; c += 128) {
        float4 a = *(const float4*)(pl + c);
        float4 b = *(const float4*)(pr + c);
        float4 w = *(const float4*)(pa + c);
        float z0 = a.x + b.x; z0 = (z0 > 0.f) ? z0 : 0.2f * z0;
        float z1 = a.y + b.y; z1 = (z1 > 0.f) ? z1 : 0.2f * z1;
        float z2 = a.z + b.z; z2 = (z2 > 0.f) ? z2 : 0.2f * z2;
        float z3 = a.w + b.w; z3 = (z3 > 0.f) ? z3 : 0.2f * z3;
        sum += z0 * w.x + z1 * w.y + z2 * w.z + z3 * w.w;
    }
    #pragma unroll
    for (int o = 16; o; o >>= 1) sum += __shfl_xor_sync(0xffffffffu, sum, o);
    if (lane == 0) esc[e * H + h] = sum;
}

// per-(node,head) softmax over incoming edges; folds 1/deg for mean-aggr
__global__ void softmax_kernel(const float* __restrict__ esc, float* __restrict__ alpha, int H) {
    int i = blockIdx.x * blockDim.x + threadIdx.x;
    if (i >= NN * H) return;
    int n = i / H, h = i % H;
    int st = g_off[n], en = g_off[n + 1];
    float mx = -3.0e38f;
    for (int p = st; p < en; p++) mx = fmaxf(mx, esc[g_ceid[p] * H + h]);
    float sum = 0.0f;
    for (int p = st; p < en; p++) {
        float v = expf(esc[g_ceid[p] * H + h] - mx);
        alpha[p * H + h] = v;
        sum += v;
    }
    float inv = 1.0f / (sum * (float)(en - st));
    for (int p = st; p < en; p++) alpha[p * H + h] *= inv;
}

// fused gather + weighted-mean aggregate + bias (+relu): block=(node, head)
__global__ __launch_bounds__(128) void aggfin_kernel(
    const float* __restrict__ xl, const float* __restrict__ alpha,
    const float* __restrict__ bias, float* __restrict__ out,
    int H, int C, int relu)
{
    __shared__ int   ssrc[64];
    __shared__ float sal[64];
    int n = blockIdx.x;
    int h = blockIdx.y;
    int HC = H * C;
    int f0 = h * C + threadIdx.x * 4;
    int st = g_off[n], en = g_off[n + 1];

    float4 acc = make_float4(0.f, 0.f, 0.f, 0.f);
    for (int c0 = st; c0 < en; c0 += 64) {
        int cnt = min(64, en - c0);
        if ((int)threadIdx.x < cnt) {
            ssrc[threadIdx.x] = g_csrc[c0 + threadIdx.x];
            sal[threadIdx.x]  = alpha[(c0 + threadIdx.x) * H + h];
        }
        __syncthreads();
        for (int j = 0; j < cnt; j++) {
            float a = sal[j];
            float4 v = *(const float4*)(xl + (long)ssrc[j] * HC + f0);
            acc.x += a * v.x; acc.y += a * v.y; acc.z += a * v.z; acc.w += a * v.w;
        }
        __syncthreads();
    }
    float4 b = *(const float4*)(bias + f0);
    acc.x += b.x; acc.y += b.y; acc.z += b.z; acc.w += b.w;
    if (relu) {
        acc.x = fmaxf(acc.x, 0.f); acc.y = fmaxf(acc.y, 0.f);
        acc.z = fmaxf(acc.z, 0.f); acc.w = fmaxf(acc.w, 0.f);
    }
    *(float4*)(out + (long)n * HC + f0) = acc;
}

// ------------------------------- head + gather -------------------------------
__global__ void head_kernel(const float* __restrict__ h, const float* __restrict__ Wh,
                            const float* __restrict__ bh, float* __restrict__ pred) {
    int warp = (blockIdx.x * blockDim.x + threadIdx.x) >> 5;
    int lane = threadIdx.x & 31;
    if (warp >= NN) return;
    const float* p = h + (long)warp * 512;
    float s = 0.0f;
    for (int c = lane * 4; c < 512; c += 128) {
        float4 v = *(const float4*)(p + c);
        float4 w = *(const float4*)(Wh + c);
        s += v.x * w.x + v.y * w.y + v.z * w.z + v.w * w.w;
    }
    #pragma unroll
    for (int o = 16; o; o >>= 1) s += __shfl_xor_sync(0xffffffffu, s, o);
    if (lane == 0) pred[warp] = 1.0f / (1.0f + expf(-(s + bh[0])));
}

__global__ void gather_kernel(const float* __restrict__ pred, const float* __restrict__ y,
                              const int* __restrict__ tidx, float* __restrict__ out, int nt) {
    int i = blockIdx.x * blockDim.x + threadIdx.x;
    if (i >= nt) return;
    int n = tidx[i];
    out[i]      = pred[n];
    out[nt + i] = y[n];
}

// --------------------------------- host side ---------------------------------
static inline long cdiv(long a, long b) { return (a + b - 1) / b; }

extern "C" void kernel_launch(void* const* d_in, const int* in_sizes, int n_in,
                              void* d_out, int out_size) {
    const float* x    = (const float*)d_in[0];
    const int*   ei   = (const int*)  d_in[1];
    const float* y    = (const float*)d_in[2];
    const int*   tidx = (const int*)  d_in[3];
    const float* bn0g = (const float*)d_in[4];
    const float* bn0b = (const float*)d_in[5];
    const float* Wl[4] = { (const float*)d_in[6],  (const float*)d_in[12],
                           (const float*)d_in[18], (const float*)d_in[24] };
    const float* Wr[4] = { (const float*)d_in[7],  (const float*)d_in[13],
                           (const float*)d_in[19], (const float*)d_in[25] };
    const float* att[4] = { (const float*)d_in[8],  (const float*)d_in[14],
                            (const float*)d_in[20], (const float*)d_in[26] };
    const float* bia[4] = { (const float*)d_in[9],  (const float*)d_in[15],
                            (const float*)d_in[21], (const float*)d_in[27] };
    const float* bng[3] = { (const float*)d_in[10], (const float*)d_in[16],
                            (const float*)d_in[22] };
    const float* bnb[3] = { (const float*)d_in[11], (const float*)d_in[17],
                            (const float*)d_in[23] };
    const float* Wh = (const float*)d_in[28];
    const float* bh = (const float*)d_in[29];
    float* out = (float*)d_out;

    int E  = in_sizes[1] / 2;
    int nt = in_sizes[3];

    float *h, *xl, *xr, *esc, *alpha, *pred;
    int *cnt, *cur;
    __nv_bfloat16 *ahi, *alo, *btlhi, *btllo, *btrhi, *btrlo;
    cudaGetSymbolAddress((void**)&h,     g_h);
    cudaGetSymbolAddress((void**)&xl,    g_xl);
    cudaGetSymbolAddress((void**)&xr,    g_xr);
    cudaGetSymbolAddress((void**)&esc,   g_e);
    cudaGetSymbolAddress((void**)&alpha, g_alpha);
    cudaGetSymbolAddress((void**)&pred,  g_pred);
    cudaGetSymbolAddress((void**)&cnt,   g_cnt);
    cudaGetSymbolAddress((void**)&cur,   g_cur);
    cudaGetSymbolAddress((void**)&ahi,   g_Ahi);
    cudaGetSymbolAddress((void**)&alo,   g_Alo);
    cudaGetSymbolAddress((void**)&btlhi, g_Btlhi);
    cudaGetSymbolAddress((void**)&btllo, g_Btllo);
    cudaGetSymbolAddress((void**)&btrhi, g_Btrhi);
    cudaGetSymbolAddress((void**)&btrlo, g_Btrlo);

    cudaFuncSetAttribute(gemm_mma_split, cudaFuncAttributeMaxDynamicSharedMemorySize, GSMEM);

    const int T = 256;
    int Etot = E + NN;

    // edges -> CSR (once per launch)
    fill_int_kernel<<<cdiv(NN, T), T>>>(cnt, 0, NN);
    fill_int_kernel<<<cdiv(NN, T), T>>>(cur, 0, NN);
    build_edges_kernel<<<cdiv(Etot, T), T>>>(ei, E);
    scan_kernel<<<1, 256>>>();
    scatter_kernel<<<cdiv(Etot, T), T>>>(ei, E);

    int Kin [4] = { FIN, 1024, 512, 512 };
    int K2s [4] = { K2MAX, 1024, 512, 512 };
    int Ncs [4] = { 1024, 512, 512, 512 };
    int heads[4] = { 2, 1, 1, 1 };

    for (int L = 0; L < 4; L++) {
        int KI = Kin[L], K2 = K2s[L], Nc = Ncs[L];
        int H = heads[L], C = Nc / H;

        // weight transpose + split
        {
            dim3 grid(K2 / 32, Nc / 32), blk(32, 8);
            transpose_split_kernel<<<grid, blk>>>(Wl[L], KI, Nc, K2, btlhi, btllo);
            transpose_split_kernel<<<grid, blk>>>(Wr[L], KI, Nc, K2, btrhi, btrlo);
        }

        // BN stats + apply/split/pad
        {
            const float* src = (L == 0) ? x : h;
            const float* g = (L == 0) ? bn0g : bng[L - 1];
            const float* b = (L == 0) ? bn0b : bnb[L - 1];
            int relu = (L == 0) ? 0 : 1;
            dim3 grid(cdiv(KI, T), BN_CHUNKS);
            bn_partial_kernel<<<grid, T>>>(src, KI, KI);
            bn_final_kernel<<<cdiv(KI, T), T>>>(KI);
            bn_apply_split_kernel<<<cdiv((long)MPAD * K2, T), T>>>(src, KI, K2, g, b, relu,
                                                                   ahi, alo);
        }

        // GEMMs
        {
            dim3 grid(Nc / 128, MPAD / 128);
            gemm_mma_split<<<grid, 256, GSMEM>>>(ahi, alo, btlhi, btllo, xl, Nc, K2);
            gemm_mma_split<<<grid, 256, GSMEM>>>(ahi, alo, btrhi, btrlo, xr, Nc, K2);
        }

        // attention: scores -> per-node softmax -> fused aggregate
        edge_score_kernel<<<cdiv((long)Etot * H * 32, T), T>>>(xl, xr, att[L], esc, Etot, H, C);
        softmax_kernel<<<cdiv(NN * H, T), T>>>(esc, alpha, H);
        {
            dim3 grid(NN, H);
            int relu_here = (L == 3) ? 1 : 0;
            aggfin_kernel<<<grid, 128>>>(xl, alpha, bia[L], h, H, C, relu_here);
        }
    }

    head_kernel<<<cdiv((long)NN * 32, T), T>>>(h, Wh, bh, pred);
    gather_kernel<<<cdiv(nt, T), T>>>(pred, y, tidx, out, nt);
}

// round 7
// speedup vs baseline: 9.9649x; 1.3773x over previous
#include <cuda_runtime.h>
#include <cuda_fp16.h>
#include <math.h>
#include <stdint.h>

// Problem constants (fixed by the dataset)
#define NN      8000
#define MPAD    8064        // 63 * 128
#define ERAW    64000
#define ETOT    (ERAW + NN)
#define FIN     3201
#define K2MAX   3264        // FIN padded to multiple of 64
#define HMAX    1024
#define BN_CHUNKS 20
#define BN_ROWS   (NN / BN_CHUNKS)

// ---------------- scratch (static device globals; no allocation) -------------
__device__ float g_h    [(long)NN * HMAX];
__device__ float g_xl   [(long)MPAD * HMAX];
__device__ float g_xr   [(long)MPAD * HMAX];
__device__ __half g_Ah   [(long)MPAD * K2MAX];
__device__ __half g_Btlhi[(long)HMAX * K2MAX];
__device__ __half g_Btllo[(long)HMAX * K2MAX];
__device__ __half g_Btrhi[(long)HMAX * K2MAX];
__device__ __half g_Btrlo[(long)HMAX * K2MAX];
__device__ float g_e    [(long)ETOT * 2];
__device__ float g_alpha[(long)ETOT * 2];
__device__ int   g_src  [ETOT];
__device__ int   g_dst  [ETOT];
__device__ int   g_cnt  [NN];
__device__ int   g_cur  [NN];
__device__ int   g_off  [NN + 1];
__device__ int   g_csrc [ETOT];
__device__ int   g_ceid [ETOT];
__device__ float g_bnp1 [BN_CHUNKS * K2MAX];
__device__ float g_bnp2 [BN_CHUNKS * K2MAX];
__device__ float g_mean [FIN];
__device__ float g_rstd [FIN];
__device__ float g_pred [NN];

// ------------------------------ PTX helpers ----------------------------------
__device__ __forceinline__ uint32_t smem_u32(const void* p) {
    uint32_t a;
    asm("{ .reg .u64 t; cvta.to.shared.u64 t, %1; cvt.u32.u64 %0, t; }"
        : "=r"(a) : "l"(p));
    return a;
}
__device__ __forceinline__ void cp_async16(uint32_t dst, const void* src) {
    asm volatile("cp.async.ca.shared.global [%0], [%1], 16;"
                 :: "r"(dst), "l"(src) : "memory");
}
__device__ __forceinline__ void cp_commit() {
    asm volatile("cp.async.commit_group;" ::: "memory");
}
template<int NG> __device__ __forceinline__ void cp_wait() {
    asm volatile("cp.async.wait_group %0;" :: "n"(NG) : "memory");
}
__device__ __forceinline__ void mma16816(float* c, const uint32_t* a,
                                         uint32_t b0, uint32_t b1) {
    asm volatile(
        "mma.sync.aligned.m16n8k16.row.col.f32.f16.f16.f32 "
        "{%0,%1,%2,%3}, {%4,%5,%6,%7}, {%8,%9}, {%0,%1,%2,%3};"
        : "+f"(c[0]), "+f"(c[1]), "+f"(c[2]), "+f"(c[3])
        : "r"(a[0]), "r"(a[1]), "r"(a[2]), "r"(a[3]), "r"(b0), "r"(b1));
}
__device__ __forceinline__ void ldm_x4(uint32_t* r, uint32_t addr) {
    asm volatile("ldmatrix.sync.aligned.m8n8.x4.shared.b16 {%0,%1,%2,%3}, [%4];"
                 : "=r"(r[0]), "=r"(r[1]), "=r"(r[2]), "=r"(r[3]) : "r"(addr));
}

// ------------------------------- small utils --------------------------------
__global__ void fill_int_kernel(int* p, int v, int n) {
    int i = blockIdx.x * blockDim.x + threadIdx.x;
    if (i < n) p[i] = v;
}

__global__ void build_edges_kernel(const int* __restrict__ ei, int E) {
    int i = blockIdx.x * blockDim.x + threadIdx.x;
    if (i >= E + NN) return;
    int s, d;
    if (i < E) { s = ei[i]; d = ei[E + i]; }
    else       { s = d = i - E; }
    g_src[i] = s;
    g_dst[i] = d;
    atomicAdd(&g_cnt[d], 1);
}

// single-block exclusive scan over g_cnt -> g_off (shfl-based)
__global__ void scan_kernel() {
    __shared__ int wsum[8];
    int tid = threadIdx.x;
    int lane = tid & 31, wid = tid >> 5;
    const int CH = (NN + 255) / 256;
    int base = tid * CH;
    int s = 0;
    for (int i = 0; i < CH; i++) { int n = base + i; if (n < NN) s += g_cnt[n]; }
    int own = s;
    #pragma unroll
    for (int o = 1; o < 32; o <<= 1) {
        int v = __shfl_up_sync(0xffffffffu, s, o);
        if (lane >= o) s += v;
    }
    if (lane == 31) wsum[wid] = s;
    __syncthreads();
    if (wid == 0 && lane < 8) {
        int w = wsum[lane];
        #pragma unroll
        for (int o = 1; o < 8; o <<= 1) {
            int v = __shfl_up_sync(0xffu, w, o);
            if (lane >= o) w += v;
        }
        wsum[lane] = w - wsum[lane];   // exclusive
    }
    __syncthreads();
    int acc = wsum[wid] + s - own;     // exclusive prefix for this thread
    for (int i = 0; i < CH; i++) {
        int n = base + i;
        if (n < NN) { g_off[n] = acc; acc += g_cnt[n]; }
    }
    if (tid == 255) g_off[NN] = acc;
}

__global__ void scatter_kernel(const int* __restrict__ ei, int E) {
    int i = blockIdx.x * blockDim.x + threadIdx.x;
    if (i >= E + NN) return;
    int s, d;
    if (i < E) { s = ei[i]; d = ei[E + i]; }
    else       { s = d = i - E; }
    int pos = g_off[d] + atomicAdd(&g_cur[d], 1);
    g_csrc[pos] = s;
    g_ceid[pos] = i;
}

__device__ __forceinline__ void split2h(float v, __half& h, __half& l) {
    h = __float2half(v);
    l = __float2half(v - __half2float(h));
}

// W [Kin x Ncol] fp32 -> Bt_hi/lo [Ncol x K2] fp16 (transposed, zero-padded in K)
__global__ void transpose_split_kernel(const float* __restrict__ W, int Kin, int Ncol, int K2,
                                       __half* __restrict__ hi, __half* __restrict__ lo) {
    __shared__ float tile[32][33];
    int k0 = blockIdx.x * 32;
    int n0 = blockIdx.y * 32;
    int tx = threadIdx.x, ty = threadIdx.y;
    #pragma unroll
    for (int j = 0; j < 4; j++) {
        int k = k0 + ty + 8 * j;
        float v = 0.0f;
        if (k < Kin) v = W[(long)k * Ncol + n0 + tx];
        tile[ty + 8 * j][tx] = v;
    }
    __syncthreads();
    #pragma unroll
    for (int j = 0; j < 4; j++) {
        int n = n0 + ty + 8 * j;
        float v = tile[tx][ty + 8 * j];
        __half h, l;
        split2h(v, h, l);
        long idx = (long)n * K2 + k0 + tx;
        hi[idx] = h;
        lo[idx] = l;
    }
}

// ------------------------------- batchnorm ----------------------------------
__global__ void bn_partial_kernel(const float* __restrict__ h, int F, int stride) {
    int f = blockIdx.x * blockDim.x + threadIdx.x;
    if (f >= F) return;
    int r0 = blockIdx.y * BN_ROWS;
    float s = 0.0f, s2 = 0.0f;
    for (int r = r0; r < r0 + BN_ROWS; r++) {
        float v = h[(long)r * stride + f];
        s += v;
        s2 += v * v;
    }
    g_bnp1[blockIdx.y * F + f] = s;
    g_bnp2[blockIdx.y * F + f] = s2;
}

__global__ void bn_final_kernel(int F) {
    int f = blockIdx.x * blockDim.x + threadIdx.x;
    if (f >= F) return;
    float s = 0.0f, s2 = 0.0f;
    #pragma unroll
    for (int c = 0; c < BN_CHUNKS; c++) { s += g_bnp1[c * F + f]; s2 += g_bnp2[c * F + f]; }
    float m = s / (float)NN;
    float var = s2 / (float)NN - m * m;
    g_mean[f] = m;
    g_rstd[f] = rsqrtf(var + 1e-5f);
}

// BN-apply + optional relu + fp16 quantize + padding, writing A [MPAD x K2]
__global__ void bn_apply_half_kernel(const float* __restrict__ in, int Fin, int K2,
                                     const float* __restrict__ gam, const float* __restrict__ bet,
                                     int relu, __half* __restrict__ A) {
    long i = (long)blockIdx.x * blockDim.x + threadIdx.x;
    long total = (long)MPAD * K2;
    if (i >= total) return;
    int row = (int)(i / K2);
    int col = (int)(i % K2);
    float v = 0.0f;
    if (row < NN && col < Fin) {
        v = (in[(long)row * Fin + col] - g_mean[col]) * g_rstd[col] * gam[col] + bet[col];
        if (relu) v = fmaxf(v, 0.0f);
    }
    A[i] = __float2half(v);
}

// ---------------- mma.sync fp16 GEMM, 2 terms (A * (Bh + Bl)) ----------------
#define STR       40
#define STR2      (STR * 2)
#define BUF_B     (128 * STR2)
#define A_OFF     0
#define B_HI_OFF  (2 * BUF_B)
#define B_LO_OFF  (4 * BUF_B)
#define GSMEM     (6 * BUF_B)               // 61440 bytes

__global__ __launch_bounds__(256) void gemm_fp16_2t(
    const __half* __restrict__ Ah,
    const __half* __restrict__ Bhi, const __half* __restrict__ Blo,
    float* __restrict__ C, int N, int K2)
{
    extern __shared__ char sm[];
    uint32_t sb = smem_u32(sm);
    const int tid = threadIdx.x;
    const int wid = tid >> 5, lane = tid & 31;
    const int wm = wid & 1, wn = wid >> 1;
    const int g = lane >> 2, q = lane & 3;
    const long row0 = (long)blockIdx.y * 128;
    const long col0 = (long)blockIdx.x * 128;

    float acc[4][4][4];
    #pragma unroll
    for (int i = 0; i < 4; i++)
        #pragma unroll
        for (int j = 0; j < 4; j++)
            #pragma unroll
            for (int t = 0; t < 4; t++) acc[i][j][t] = 0.0f;

    const int NS = K2 >> 5;

    auto issue = [&](int s, int buf) {
        int k0 = s << 5;
        #pragma unroll
        for (int it = 0; it < 2; it++) {
            int c = tid + (it << 8);
            int row = c >> 2;
            int kc = (c & 3) * 8;
            uint32_t so = (uint32_t)(buf * BUF_B + row * STR2 + kc * 2);
            long ga = (row0 + row) * K2 + k0 + kc;
            long gb = (col0 + row) * K2 + k0 + kc;
            cp_async16(sb + A_OFF + so, Ah + ga);
            cp_async16(sb + B_HI_OFF + so, Bhi + gb);
            cp_async16(sb + B_LO_OFF + so, Blo + gb);
        }
        cp_commit();
    };

    const uint32_t aoff = (uint32_t)((wm * 64 + (lane & 15)) * STR2 + (lane >> 4) * 16);
    const uint32_t boff = (uint32_t)((wn * 32 + ((lane >> 4) & 1) * 8 + (lane & 7)) * STR2
                                     + ((lane >> 3) & 1) * 16);

    issue(0, 0);

    for (int s = 0; s < NS; s++) {
        int buf = s & 1;
        if (s + 1 < NS) { issue(s + 1, buf ^ 1); cp_wait<1>(); }
        else            { cp_wait<0>(); }
        __syncthreads();

        uint32_t a_b   = sb + A_OFF + buf * BUF_B;
        uint32_t bhi_b = sb + B_HI_OFF + buf * BUF_B;
        uint32_t blo_b = sb + B_LO_OFF + buf * BUF_B;

        #pragma unroll
        for (int kk = 0; kk < 2; kk++) {
            uint32_t kByte = (uint32_t)(kk * 32);
            uint32_t Bh[8], Bl[8];
            #pragma unroll
            for (int jp = 0; jp < 2; jp++) {
                uint32_t off = boff + kByte + (uint32_t)(jp * 16 * STR2);
                ldm_x4(&Bh[jp * 4], bhi_b + off);
                ldm_x4(&Bl[jp * 4], blo_b + off);
            }
            #pragma unroll
            for (int i = 0; i < 4; i++) {
                uint32_t off = aoff + kByte + (uint32_t)(i * 16 * STR2);
                uint32_t ah[4];
                ldm_x4(ah, a_b + off);
                #pragma unroll
                for (int j = 0; j < 4; j++) mma16816(acc[i][j], ah, Bh[2*j], Bh[2*j+1]);
                #pragma unroll
                for (int j = 0; j < 4; j++) mma16816(acc[i][j], ah, Bl[2*j], Bl[2*j+1]);
            }
        }
        __syncthreads();
    }

    #pragma unroll
    for (int i = 0; i < 4; i++) {
        long r = row0 + wm * 64 + i * 16 + g;
        #pragma unroll
        for (int j = 0; j < 4; j++) {
            long cc = col0 + wn * 32 + j * 8 + 2 * q;
            *(float2*)(C + r * N + cc)       = make_float2(acc[i][j][0], acc[i][j][1]);
            *(float2*)(C + (r + 8) * N + cc) = make_float2(acc[i][j][2], acc[i][j][3]);
        }
    }
}

// ------------------------------- GATv2 edge ops ------------------------------
__global__ void edge_score_kernel(const float* __restrict__ xl, const float* __restrict__ xr,
                                  const float* __restrict__ att, float* __restrict__ esc,
                                  int E, int H, int C) {
    int warp = (blockIdx.x * blockDim.x + threadIdx.x) >> 5;
    int lane = threadIdx.x & 31;
    if (warp >= E * H) return;
    int e = warp / H, h = warp % H;
    const float* pl = xl + (long)g_src[e] * H * C + h * C;
    const float* pr = xr + (long)g_dst[e] * H * C + h * C;
    const float* pa = att + h * C;
    float sum = 0.0f;
    for (int c = lane * 4; c < C; c += 128) {
        float4 a = *(const float4*)(pl + c);
        float4 b = *(const float4*)(pr + c);
        float4 w = *(const float4*)(pa + c);
        float z0 = a.x + b.x; z0 = (z0 > 0.f) ? z0 : 0.2f * z0;
        float z1 = a.y + b.y; z1 = (z1 > 0.f) ? z1 : 0.2f * z1;
        float z2 = a.z + b.z; z2 = (z2 > 0.f) ? z2 : 0.2f * z2;
        float z3 = a.w + b.w; z3 = (z3 > 0.f) ? z3 : 0.2f * z3;
        sum += z0 * w.x + z1 * w.y + z2 * w.z + z3 * w.w;
    }
    #pragma unroll
    for (int o = 16; o; o >>= 1) sum += __shfl_xor_sync(0xffffffffu, sum, o);
    if (lane == 0) esc[e * H + h] = sum;
}

// per-(node,head) softmax over incoming edges; folds 1/deg for mean-aggr
__global__ void softmax_kernel(const float* __restrict__ esc, float* __restrict__ alpha, int H) {
    int i = blockIdx.x * blockDim.x + threadIdx.x;
    if (i >= NN * H) return;
    int n = i / H, h = i % H;
    int st = g_off[n], en = g_off[n + 1];
    float mx = -3.0e38f;
    for (int p = st; p < en; p++) mx = fmaxf(mx, esc[g_ceid[p] * H + h]);
    float sum = 0.0f;
    for (int p = st; p < en; p++) {
        float v = expf(esc[g_ceid[p] * H + h] - mx);
        alpha[p * H + h] = v;
        sum += v;
    }
    float inv = 1.0f / (sum * (float)(en - st));
    for (int p = st; p < en; p++) alpha[p * H + h] *= inv;
}

// fused gather + weighted-mean aggregate + bias (+relu): block=(node, head)
__global__ __launch_bounds__(128) void aggfin_kernel(
    const float* __restrict__ xl, const float* __restrict__ alpha,
    const float* __restrict__ bias, float* __restrict__ out,
    int H, int C, int relu)
{
    __shared__ int   ssrc[64];
    __shared__ float sal[64];
    int n = blockIdx.x;
    int h = blockIdx.y;
    int HC = H * C;
    int f0 = h * C + threadIdx.x * 4;
    int st = g_off[n], en = g_off[n + 1];

    float4 acc = make_float4(0.f, 0.f, 0.f, 0.f);
    for (int c0 = st; c0 < en; c0 += 64) {
        int cnt = min(64, en - c0);
        if ((int)threadIdx.x < cnt) {
            ssrc[threadIdx.x] = g_csrc[c0 + threadIdx.x];
            sal[threadIdx.x]  = alpha[(c0 + threadIdx.x) * H + h];
        }
        __syncthreads();
        for (int j = 0; j < cnt; j++) {
            float a = sal[j];
            float4 v = *(const float4*)(xl + (long)ssrc[j] * HC + f0);
            acc.x += a * v.x; acc.y += a * v.y; acc.z += a * v.z; acc.w += a * v.w;
        }
        __syncthreads();
    }
    float4 b = *(const float4*)(bias + f0);
    acc.x += b.x; acc.y += b.y; acc.z += b.z; acc.w += b.w;
    if (relu) {
        acc.x = fmaxf(acc.x, 0.f); acc.y = fmaxf(acc.y, 0.f);
        acc.z = fmaxf(acc.z, 0.f); acc.w = fmaxf(acc.w, 0.f);
    }
    *(float4*)(out + (long)n * HC + f0) = acc;
}

// ------------------------------- head + gather -------------------------------
__global__ void head_kernel(const float* __restrict__ h, const float* __restrict__ Wh,
                            const float* __restrict__ bh, float* __restrict__ pred) {
    int warp = (blockIdx.x * blockDim.x + threadIdx.x) >> 5;
    int lane = threadIdx.x & 31;
    if (warp >= NN) return;
    const float* p = h + (long)warp * 512;
    float s = 0.0f;
    for (int c = lane * 4; c < 512; c += 128) {
        float4 v = *(const float4*)(p + c);
        float4 w = *(const float4*)(Wh + c);
        s += v.x * w.x + v.y * w.y + v.z * w.z + v.w * w.w;
    }
    #pragma unroll
    for (int o = 16; o; o >>= 1) s += __shfl_xor_sync(0xffffffffu, s, o);
    if (lane == 0) pred[warp] = 1.0f / (1.0f + expf(-(s + bh[0])));
}

__global__ void gather_kernel(const float* __restrict__ pred, const float* __restrict__ y,
                              const int* __restrict__ tidx, float* __restrict__ out, int nt) {
    int i = blockIdx.x * blockDim.x + threadIdx.x;
    if (i >= nt) return;
    int n = tidx[i];
    out[i]      = pred[n];
    out[nt + i] = y[n];
}

// --------------------------------- host side ---------------------------------
static inline long cdiv(long a, long b) { return (a + b - 1) / b; }

extern "C" void kernel_launch(void* const* d_in, const int* in_sizes, int n_in,
                              void* d_out, int out_size) {
    const float* x    = (const float*)d_in[0];
    const int*   ei   = (const int*)  d_in[1];
    const float* y    = (const float*)d_in[2];
    const int*   tidx = (const int*)  d_in[3];
    const float* bn0g = (const float*)d_in[4];
    const float* bn0b = (const float*)d_in[5];
    const float* Wl[4] = { (const float*)d_in[6],  (const float*)d_in[12],
                           (const float*)d_in[18], (const float*)d_in[24] };
    const float* Wr[4] = { (const float*)d_in[7],  (const float*)d_in[13],
                           (const float*)d_in[19], (const float*)d_in[25] };
    const float* att[4] = { (const float*)d_in[8],  (const float*)d_in[14],
                            (const float*)d_in[20], (const float*)d_in[26] };
    const float* bia[4] = { (const float*)d_in[9],  (const float*)d_in[15],
                            (const float*)d_in[21], (const float*)d_in[27] };
    const float* bng[3] = { (const float*)d_in[10], (const float*)d_in[16],
                            (const float*)d_in[22] };
    const float* bnb[3] = { (const float*)d_in[11], (const float*)d_in[17],
                            (const float*)d_in[23] };
    const float* Wh = (const float*)d_in[28];
    const float* bh = (const float*)d_in[29];
    float* out = (float*)d_out;

    int E  = in_sizes[1] / 2;
    int nt = in_sizes[3];

    float *h, *xl, *xr, *esc, *alpha, *pred;
    int *cnt, *cur;
    __half *ah, *btlhi, *btllo, *btrhi, *btrlo;
    cudaGetSymbolAddress((void**)&h,     g_h);
    cudaGetSymbolAddress((void**)&xl,    g_xl);
    cudaGetSymbolAddress((void**)&xr,    g_xr);
    cudaGetSymbolAddress((void**)&esc,   g_e);
    cudaGetSymbolAddress((void**)&alpha, g_alpha);
    cudaGetSymbolAddress((void**)&pred,  g_pred);
    cudaGetSymbolAddress((void**)&cnt,   g_cnt);
    cudaGetSymbolAddress((void**)&cur,   g_cur);
    cudaGetSymbolAddress((void**)&ah,    g_Ah);
    cudaGetSymbolAddress((void**)&btlhi, g_Btlhi);
    cudaGetSymbolAddress((void**)&btllo, g_Btllo);
    cudaGetSymbolAddress((void**)&btrhi, g_Btrhi);
    cudaGetSymbolAddress((void**)&btrlo, g_Btrlo);

    cudaFuncSetAttribute(gemm_fp16_2t, cudaFuncAttributeMaxDynamicSharedMemorySize, GSMEM);

    const int T = 256;
    int Etot = E + NN;

    // edges -> CSR (once per launch)
    fill_int_kernel<<<cdiv(NN, T), T>>>(cnt, 0, NN);
    fill_int_kernel<<<cdiv(NN, T), T>>>(cur, 0, NN);
    build_edges_kernel<<<cdiv(Etot, T), T>>>(ei, E);
    scan_kernel<<<1, 256>>>();
    scatter_kernel<<<cdiv(Etot, T), T>>>(ei, E);

    int Kin [4] = { FIN, 1024, 512, 512 };
    int K2s [4] = { K2MAX, 1024, 512, 512 };
    int Ncs [4] = { 1024, 512, 512, 512 };
    int heads[4] = { 2, 1, 1, 1 };

    for (int L = 0; L < 4; L++) {
        int KI = Kin[L], K2 = K2s[L], Nc = Ncs[L];
        int H = heads[L], C = Nc / H;

        // weight transpose + split (fp16 hi/lo)
        {
            dim3 grid(K2 / 32, Nc / 32), blk(32, 8);
            transpose_split_kernel<<<grid, blk>>>(Wl[L], KI, Nc, K2, btlhi, btllo);
            transpose_split_kernel<<<grid, blk>>>(Wr[L], KI, Nc, K2, btrhi, btrlo);
        }

        // BN stats + apply/quantize/pad
        {
            const float* src = (L == 0) ? x : h;
            const float* g = (L == 0) ? bn0g : bng[L - 1];
            const float* b = (L == 0) ? bn0b : bnb[L - 1];
            int relu = (L == 0) ? 0 : 1;
            dim3 grid(cdiv(KI, T), BN_CHUNKS);
            bn_partial_kernel<<<grid, T>>>(src, KI, KI);
            bn_final_kernel<<<cdiv(KI, T), T>>>(KI);
            bn_apply_half_kernel<<<cdiv((long)MPAD * K2, T), T>>>(src, KI, K2, g, b, relu, ah);
        }

        // GEMMs: xl = A @ Wl, xr = A @ Wr
        {
            dim3 grid(Nc / 128, MPAD / 128);
            gemm_fp16_2t<<<grid, 256, GSMEM>>>(ah, btlhi, btllo, xl, Nc, K2);
            gemm_fp16_2t<<<grid, 256, GSMEM>>>(ah, btrhi, btrlo, xr, Nc, K2);
        }

        // attention: scores -> per-node softmax -> fused aggregate
        edge_score_kernel<<<cdiv((long)Etot * H * 32, T), T>>>(xl, xr, att[L], esc, Etot, H, C);
        softmax_kernel<<<cdiv(NN * H, T), T>>>(esc, alpha, H);
        {
            dim3 grid(NN, H);
            int relu_here = (L == 3) ? 1 : 0;
            aggfin_kernel<<<grid, 128>>>(xl, alpha, bia[L], h, H, C, relu_here);
        }
    }

    head_kernel<<<cdiv((long)NN * 32, T), T>>>(h, Wh, bh, pred);
    gather_kernel<<<cdiv(nt, T), T>>>(pred, y, tidx, out, nt);
}

// round 8
// speedup vs baseline: 12.5410x; 1.2585x over previous
#include <cuda_runtime.h>
#include <cuda_fp16.h>
#include <math.h>
#include <stdint.h>

// Problem constants (fixed by the dataset)
#define NN      8000
#define MPAD    8064        // 63 * 128
#define ERAW    64000
#define ETOT    (ERAW + NN)
#define FIN     3201
#define K2MAX   3264        // FIN padded to multiple of 64
#define HMAX    1024
#define BN_CHUNKS 20
#define BN_ROWS   (NN / BN_CHUNKS)

// ---------------- scratch (static device globals; no allocation) -------------
__device__ float g_h    [(long)NN * HMAX];
__device__ float g_xl   [(long)MPAD * HMAX];
__device__ float g_xr   [(long)MPAD * HMAX];
__device__ __half g_Ah  [(long)MPAD * K2MAX];
__device__ __half g_Btl [(long)HMAX * K2MAX];
__device__ __half g_Btr [(long)HMAX * K2MAX];
__device__ float g_e    [(long)ETOT * 2];
__device__ float g_alpha[(long)ETOT * 2];
__device__ int   g_src  [ETOT];
__device__ int   g_dst  [ETOT];
__device__ int   g_cnt  [NN + 32];     // padded for int4 scan reads
__device__ int   g_cur  [NN];
__device__ int   g_off  [NN + 1];
__device__ int   g_csrc [ETOT];
__device__ int   g_ceid [ETOT];
__device__ float g_bnp1 [BN_CHUNKS * K2MAX];
__device__ float g_bnp2 [BN_CHUNKS * K2MAX];
__device__ float g_mean [FIN];
__device__ float g_rstd [FIN];
__device__ float g_pred [NN];

// ------------------------------ PTX helpers ----------------------------------
__device__ __forceinline__ uint32_t smem_u32(const void* p) {
    uint32_t a;
    asm("{ .reg .u64 t; cvta.to.shared.u64 t, %1; cvt.u32.u64 %0, t; }"
        : "=r"(a) : "l"(p));
    return a;
}
__device__ __forceinline__ void cp_async16(uint32_t dst, const void* src) {
    asm volatile("cp.async.ca.shared.global [%0], [%1], 16;"
                 :: "r"(dst), "l"(src) : "memory");
}
__device__ __forceinline__ void cp_commit() {
    asm volatile("cp.async.commit_group;" ::: "memory");
}
template<int NG> __device__ __forceinline__ void cp_wait() {
    asm volatile("cp.async.wait_group %0;" :: "n"(NG) : "memory");
}
__device__ __forceinline__ void mma16816(float* c, const uint32_t* a,
                                         uint32_t b0, uint32_t b1) {
    asm volatile(
        "mma.sync.aligned.m16n8k16.row.col.f32.f16.f16.f32 "
        "{%0,%1,%2,%3}, {%4,%5,%6,%7}, {%8,%9}, {%0,%1,%2,%3};"
        : "+f"(c[0]), "+f"(c[1]), "+f"(c[2]), "+f"(c[3])
        : "r"(a[0]), "r"(a[1]), "r"(a[2]), "r"(a[3]), "r"(b0), "r"(b1));
}
__device__ __forceinline__ void ldm_x4(uint32_t* r, uint32_t addr) {
    asm volatile("ldmatrix.sync.aligned.m8n8.x4.shared.b16 {%0,%1,%2,%3}, [%4];"
                 : "=r"(r[0]), "=r"(r[1]), "=r"(r[2]), "=r"(r[3]) : "r"(addr));
}

// ------------------------------- small utils --------------------------------
__global__ void fill_int_kernel(int* p, int v, int n) {
    int i = blockIdx.x * blockDim.x + threadIdx.x;
    if (i < n) p[i] = v;
}

__global__ void build_edges_kernel(const int* __restrict__ ei, int E) {
    int i = blockIdx.x * blockDim.x + threadIdx.x;
    if (i >= E + NN) return;
    int s, d;
    if (i < E) { s = ei[i]; d = ei[E + i]; }
    else       { s = d = i - E; }
    g_src[i] = s;
    g_dst[i] = d;
    atomicAdd(&g_cnt[d], 1);
}

// single-block exclusive scan over g_cnt -> g_off (shfl + vectorized loads)
__global__ void scan_kernel() {
    __shared__ int wsum[8];
    int tid = threadIdx.x;
    int lane = tid & 31, wid = tid >> 5;
    const int CH = 32;                  // NN/256 = 31.25 -> 32 (g_cnt padded with zeros)
    int base = tid * CH;
    int vals[CH];
    #pragma unroll
    for (int i = 0; i < CH / 4; i++) {
        int4 v = *(const int4*)&g_cnt[base + i * 4];
        vals[i * 4 + 0] = v.x; vals[i * 4 + 1] = v.y;
        vals[i * 4 + 2] = v.z; vals[i * 4 + 3] = v.w;
    }
    int s = 0;
    #pragma unroll
    for (int i = 0; i < CH; i++) s += vals[i];
    int own = s;
    #pragma unroll
    for (int o = 1; o < 32; o <<= 1) {
        int v = __shfl_up_sync(0xffffffffu, s, o);
        if (lane >= o) s += v;
    }
    if (lane == 31) wsum[wid] = s;
    __syncthreads();
    if (wid == 0 && lane < 8) {
        int w = wsum[lane];
        #pragma unroll
        for (int o = 1; o < 8; o <<= 1) {
            int v = __shfl_up_sync(0xffu, w, o);
            if (lane >= o) w += v;
        }
        wsum[lane] = w - wsum[lane];   // exclusive
    }
    __syncthreads();
    int acc = wsum[wid] + s - own;
    #pragma unroll
    for (int i = 0; i < CH; i++) {
        int n = base + i;
        if (n < NN) { g_off[n] = acc; acc += vals[i]; }
    }
    if (tid == 255) g_off[NN] = acc;
}

__global__ void scatter_kernel(const int* __restrict__ ei, int E) {
    int i = blockIdx.x * blockDim.x + threadIdx.x;
    if (i >= E + NN) return;
    int s, d;
    if (i < E) { s = ei[i]; d = ei[E + i]; }
    else       { s = d = i - E; }
    int pos = g_off[d] + atomicAdd(&g_cur[d], 1);
    g_csrc[pos] = s;
    g_ceid[pos] = i;
}

// W [Kin x Ncol] fp32 -> Bt [Ncol x K2] fp16 (transposed, zero-padded in K)
__global__ void transpose_half_kernel(const float* __restrict__ W, int Kin, int Ncol, int K2,
                                      __half* __restrict__ o) {
    __shared__ float tile[32][33];
    int k0 = blockIdx.x * 32;
    int n0 = blockIdx.y * 32;
    int tx = threadIdx.x, ty = threadIdx.y;
    #pragma unroll
    for (int j = 0; j < 4; j++) {
        int k = k0 + ty + 8 * j;
        float v = 0.0f;
        if (k < Kin) v = W[(long)k * Ncol + n0 + tx];
        tile[ty + 8 * j][tx] = v;
    }
    __syncthreads();
    #pragma unroll
    for (int j = 0; j < 4; j++) {
        int n = n0 + ty + 8 * j;
        o[(long)n * K2 + k0 + tx] = __float2half(tile[tx][ty + 8 * j]);
    }
}

// ------------------------------- batchnorm ----------------------------------
__global__ void bn_partial_kernel(const float* __restrict__ h, int F, int stride) {
    int f = blockIdx.x * blockDim.x + threadIdx.x;
    if (f >= F) return;
    int r0 = blockIdx.y * BN_ROWS;
    float s = 0.0f, s2 = 0.0f;
    for (int r = r0; r < r0 + BN_ROWS; r++) {
        float v = h[(long)r * stride + f];
        s += v;
        s2 += v * v;
    }
    g_bnp1[blockIdx.y * F + f] = s;
    g_bnp2[blockIdx.y * F + f] = s2;
}

__global__ void bn_final_kernel(int F) {
    int f = blockIdx.x * blockDim.x + threadIdx.x;
    if (f >= F) return;
    float s = 0.0f, s2 = 0.0f;
    #pragma unroll
    for (int c = 0; c < BN_CHUNKS; c++) { s += g_bnp1[c * F + f]; s2 += g_bnp2[c * F + f]; }
    float m = s / (float)NN;
    float var = s2 / (float)NN - m * m;
    g_mean[f] = m;
    g_rstd[f] = rsqrtf(var + 1e-5f);
}

// BN-apply + optional relu + fp16 quantize + padding, writing A [MPAD x K2]
__global__ void bn_apply_half_kernel(const float* __restrict__ in, int Fin, int K2,
                                     const float* __restrict__ gam, const float* __restrict__ bet,
                                     int relu, __half* __restrict__ A) {
    long i = (long)blockIdx.x * blockDim.x + threadIdx.x;
    long total = (long)MPAD * K2;
    if (i >= total) return;
    int row = (int)(i / K2);
    int col = (int)(i % K2);
    float v = 0.0f;
    if (row < NN && col < Fin) {
        v = (in[(long)row * Fin + col] - g_mean[col]) * g_rstd[col] * gam[col] + bet[col];
        if (relu) v = fmaxf(v, 0.0f);
    }
    A[i] = __float2half(v);
}

// --------------------------- mma.sync fp16 GEMM ------------------------------
#define STR       40
#define STR2      (STR * 2)
#define BUF_B     (128 * STR2)
#define A_OFF     0
#define B_OFF     (2 * BUF_B)
#define GSMEM     (4 * BUF_B)               // 40960 bytes

__global__ __launch_bounds__(256) void gemm_fp16(
    const __half* __restrict__ Ah, const __half* __restrict__ Bt,
    float* __restrict__ C, int N, int K2)
{
    extern __shared__ char sm[];
    uint32_t sb = smem_u32(sm);
    const int tid = threadIdx.x;
    const int wid = tid >> 5, lane = tid & 31;
    const int wm = wid & 1, wn = wid >> 1;
    const int g = lane >> 2, q = lane & 3;
    const long row0 = (long)blockIdx.y * 128;
    const long col0 = (long)blockIdx.x * 128;

    float acc[4][4][4];
    #pragma unroll
    for (int i = 0; i < 4; i++)
        #pragma unroll
        for (int j = 0; j < 4; j++)
            #pragma unroll
            for (int t = 0; t < 4; t++) acc[i][j][t] = 0.0f;

    const int NS = K2 >> 5;

    auto issue = [&](int s, int buf) {
        int k0 = s << 5;
        #pragma unroll
        for (int it = 0; it < 2; it++) {
            int c = tid + (it << 8);
            int row = c >> 2;
            int kc = (c & 3) * 8;
            uint32_t so = (uint32_t)(buf * BUF_B + row * STR2 + kc * 2);
            long ga = (row0 + row) * K2 + k0 + kc;
            long gb = (col0 + row) * K2 + k0 + kc;
            cp_async16(sb + A_OFF + so, Ah + ga);
            cp_async16(sb + B_OFF + so, Bt + gb);
        }
        cp_commit();
    };

    const uint32_t aoff = (uint32_t)((wm * 64 + (lane & 15)) * STR2 + (lane >> 4) * 16);
    const uint32_t boff = (uint32_t)((wn * 32 + ((lane >> 4) & 1) * 8 + (lane & 7)) * STR2
                                     + ((lane >> 3) & 1) * 16);

    issue(0, 0);

    for (int s = 0; s < NS; s++) {
        int buf = s & 1;
        if (s + 1 < NS) { issue(s + 1, buf ^ 1); cp_wait<1>(); }
        else            { cp_wait<0>(); }
        __syncthreads();

        uint32_t a_b = sb + A_OFF + buf * BUF_B;
        uint32_t b_b = sb + B_OFF + buf * BUF_B;

        #pragma unroll
        for (int kk = 0; kk < 2; kk++) {
            uint32_t kByte = (uint32_t)(kk * 32);
            uint32_t Bf[8];
            #pragma unroll
            for (int jp = 0; jp < 2; jp++) {
                uint32_t off = boff + kByte + (uint32_t)(jp * 16 * STR2);
                ldm_x4(&Bf[jp * 4], b_b + off);
            }
            #pragma unroll
            for (int i = 0; i < 4; i++) {
                uint32_t off = aoff + kByte + (uint32_t)(i * 16 * STR2);
                uint32_t af[4];
                ldm_x4(af, a_b + off);
                #pragma unroll
                for (int j = 0; j < 4; j++) mma16816(acc[i][j], af, Bf[2*j], Bf[2*j+1]);
            }
        }
        __syncthreads();
    }

    #pragma unroll
    for (int i = 0; i < 4; i++) {
        long r = row0 + wm * 64 + i * 16 + g;
        #pragma unroll
        for (int j = 0; j < 4; j++) {
            long cc = col0 + wn * 32 + j * 8 + 2 * q;
            *(float2*)(C + r * N + cc)       = make_float2(acc[i][j][0], acc[i][j][1]);
            *(float2*)(C + (r + 8) * N + cc) = make_float2(acc[i][j][2], acc[i][j][3]);
        }
    }
}

// ------------------------------- GATv2 edge ops ------------------------------
__global__ void edge_score_kernel(const float* __restrict__ xl, const float* __restrict__ xr,
                                  const float* __restrict__ att, float* __restrict__ esc,
                                  int E, int H, int C) {
    int warp = (blockIdx.x * blockDim.x + threadIdx.x) >> 5;
    int lane = threadIdx.x & 31;
    if (warp >= E * H) return;
    int e = warp / H, h = warp % H;
    const float* pl = xl + (long)g_src[e] * H * C + h * C;
    const float* pr = xr + (long)g_dst[e] * H * C + h * C;
    const float* pa = att + h * C;
    float sum = 0.0f;
    for (int c = lane * 4; c < C; c += 128) {
        float4 a = *(const float4*)(pl + c);
        float4 b = *(const float4*)(pr + c);
        float4 w = *(const float4*)(pa + c);
        float z0 = a.x + b.x; z0 = (z0 > 0.f) ? z0 : 0.2f * z0;
        float z1 = a.y + b.y; z1 = (z1 > 0.f) ? z1 : 0.2f * z1;
        float z2 = a.z + b.z; z2 = (z2 > 0.f) ? z2 : 0.2f * z2;
        float z3 = a.w + b.w; z3 = (z3 > 0.f) ? z3 : 0.2f * z3;
        sum += z0 * w.x + z1 * w.y + z2 * w.z + z3 * w.w;
    }
    #pragma unroll
    for (int o = 16; o; o >>= 1) sum += __shfl_xor_sync(0xffffffffu, sum, o);
    if (lane == 0) esc[e * H + h] = sum;
}

// per-(node,head) softmax over incoming edges; folds 1/deg for mean-aggr
__global__ void softmax_kernel(const float* __restrict__ esc, float* __restrict__ alpha, int H) {
    int i = blockIdx.x * blockDim.x + threadIdx.x;
    if (i >= NN * H) return;
    int n = i / H, h = i % H;
    int st = g_off[n], en = g_off[n + 1];
    float mx = -3.0e38f;
    for (int p = st; p < en; p++) mx = fmaxf(mx, esc[g_ceid[p] * H + h]);
    float sum = 0.0f;
    for (int p = st; p < en; p++) {
        float v = expf(esc[g_ceid[p] * H + h] - mx);
        alpha[p * H + h] = v;
        sum += v;
    }
    float inv = 1.0f / (sum * (float)(en - st));
    for (int p = st; p < en; p++) alpha[p * H + h] *= inv;
}

// fused gather + weighted-mean aggregate + bias (+relu): block=(node, head)
__global__ __launch_bounds__(128) void aggfin_kernel(
    const float* __restrict__ xl, const float* __restrict__ alpha,
    const float* __restrict__ bias, float* __restrict__ out,
    int H, int C, int relu)
{
    __shared__ int   ssrc[64];
    __shared__ float sal[64];
    int n = blockIdx.x;
    int h = blockIdx.y;
    int HC = H * C;
    int f0 = h * C + threadIdx.x * 4;
    int st = g_off[n], en = g_off[n + 1];

    float4 acc = make_float4(0.f, 0.f, 0.f, 0.f);
    for (int c0 = st; c0 < en; c0 += 64) {
        int cnt = min(64, en - c0);
        if ((int)threadIdx.x < cnt) {
            ssrc[threadIdx.x] = g_csrc[c0 + threadIdx.x];
            sal[threadIdx.x]  = alpha[(c0 + threadIdx.x) * H + h];
        }
        __syncthreads();
        for (int j = 0; j < cnt; j++) {
            float a = sal[j];
            float4 v = *(const float4*)(xl + (long)ssrc[j] * HC + f0);
            acc.x += a * v.x; acc.y += a * v.y; acc.z += a * v.z; acc.w += a * v.w;
        }
        __syncthreads();
    }
    float4 b = *(const float4*)(bias + f0);
    acc.x += b.x; acc.y += b.y; acc.z += b.z; acc.w += b.w;
    if (relu) {
        acc.x = fmaxf(acc.x, 0.f); acc.y = fmaxf(acc.y, 0.f);
        acc.z = fmaxf(acc.z, 0.f); acc.w = fmaxf(acc.w, 0.f);
    }
    *(float4*)(out + (long)n * HC + f0) = acc;
}

// ------------------------------- head + gather -------------------------------
__global__ void head_kernel(const float* __restrict__ h, const float* __restrict__ Wh,
                            const float* __restrict__ bh, float* __restrict__ pred) {
    int warp = (blockIdx.x * blockDim.x + threadIdx.x) >> 5;
    int lane = threadIdx.x & 31;
    if (warp >= NN) return;
    const float* p = h + (long)warp * 512;
    float s = 0.0f;
    for (int c = lane * 4; c < 512; c += 128) {
        float4 v = *(const float4*)(p + c);
        float4 w = *(const float4*)(Wh + c);
        s += v.x * w.x + v.y * w.y + v.z * w.z + v.w * w.w;
    }
    #pragma unroll
    for (int o = 16; o; o >>= 1) s += __shfl_xor_sync(0xffffffffu, s, o);
    if (lane == 0) pred[warp] = 1.0f / (1.0f + expf(-(s + bh[0])));
}

__global__ void gather_kernel(const float* __restrict__ pred, const float* __restrict__ y,
                              const int* __restrict__ tidx, float* __restrict__ out, int nt) {
    int i = blockIdx.x * blockDim.x + threadIdx.x;
    if (i >= nt) return;
    int n = tidx[i];
    out[i]      = pred[n];
    out[nt + i] = y[n];
}

// --------------------------------- host side ---------------------------------
static inline long cdiv(long a, long b) { return (a + b - 1) / b; }

extern "C" void kernel_launch(void* const* d_in, const int* in_sizes, int n_in,
                              void* d_out, int out_size) {
    const float* x    = (const float*)d_in[0];
    const int*   ei   = (const int*)  d_in[1];
    const float* y    = (const float*)d_in[2];
    const int*   tidx = (const int*)  d_in[3];
    const float* bn0g = (const float*)d_in[4];
    const float* bn0b = (const float*)d_in[5];
    const float* Wl[4] = { (const float*)d_in[6],  (const float*)d_in[12],
                           (const float*)d_in[18], (const float*)d_in[24] };
    const float* Wr[4] = { (const float*)d_in[7],  (const float*)d_in[13],
                           (const float*)d_in[19], (const float*)d_in[25] };
    const float* att[4] = { (const float*)d_in[8],  (const float*)d_in[14],
                            (const float*)d_in[20], (const float*)d_in[26] };
    const float* bia[4] = { (const float*)d_in[9],  (const float*)d_in[15],
                            (const float*)d_in[21], (const float*)d_in[27] };
    const float* bng[3] = { (const float*)d_in[10], (const float*)d_in[16],
                            (const float*)d_in[22] };
    const float* bnb[3] = { (const float*)d_in[11], (const float*)d_in[17],
                            (const float*)d_in[23] };
    const float* Wh = (const float*)d_in[28];
    const float* bh = (const float*)d_in[29];
    float* out = (float*)d_out;

    int E  = in_sizes[1] / 2;
    int nt = in_sizes[3];

    float *h, *xl, *xr, *esc, *alpha, *pred;
    int *cnt, *cur;
    __half *ah, *btl, *btr;
    cudaGetSymbolAddress((void**)&h,     g_h);
    cudaGetSymbolAddress((void**)&xl,    g_xl);
    cudaGetSymbolAddress((void**)&xr,    g_xr);
    cudaGetSymbolAddress((void**)&esc,   g_e);
    cudaGetSymbolAddress((void**)&alpha, g_alpha);
    cudaGetSymbolAddress((void**)&pred,  g_pred);
    cudaGetSymbolAddress((void**)&cnt,   g_cnt);
    cudaGetSymbolAddress((void**)&cur,   g_cur);
    cudaGetSymbolAddress((void**)&ah,    g_Ah);
    cudaGetSymbolAddress((void**)&btl,   g_Btl);
    cudaGetSymbolAddress((void**)&btr,   g_Btr);

    cudaFuncSetAttribute(gemm_fp16, cudaFuncAttributeMaxDynamicSharedMemorySize, GSMEM);

    const int T = 256;
    int Etot = E + NN;

    // edges -> CSR (once per launch)
    fill_int_kernel<<<cdiv(NN + 32, T), T>>>(cnt, 0, NN + 32);
    fill_int_kernel<<<cdiv(NN, T), T>>>(cur, 0, NN);
    build_edges_kernel<<<cdiv(Etot, T), T>>>(ei, E);
    scan_kernel<<<1, 256>>>();
    scatter_kernel<<<cdiv(Etot, T), T>>>(ei, E);

    int Kin [4] = { FIN, 1024, 512, 512 };
    int K2s [4] = { K2MAX, 1024, 512, 512 };
    int Ncs [4] = { 1024, 512, 512, 512 };
    int heads[4] = { 2, 1, 1, 1 };

    for (int L = 0; L < 4; L++) {
        int KI = Kin[L], K2 = K2s[L], Nc = Ncs[L];
        int H = heads[L], C = Nc / H;

        // weight transpose -> fp16
        {
            dim3 grid(K2 / 32, Nc / 32), blk(32, 8);
            transpose_half_kernel<<<grid, blk>>>(Wl[L], KI, Nc, K2, btl);
            transpose_half_kernel<<<grid, blk>>>(Wr[L], KI, Nc, K2, btr);
        }

        // BN stats + apply/quantize/pad
        {
            const float* src = (L == 0) ? x : h;
            const float* g = (L == 0) ? bn0g : bng[L - 1];
            const float* b = (L == 0) ? bn0b : bnb[L - 1];
            int relu = (L == 0) ? 0 : 1;
            dim3 grid(cdiv(KI, T), BN_CHUNKS);
            bn_partial_kernel<<<grid, T>>>(src, KI, KI);
            bn_final_kernel<<<cdiv(KI, T), T>>>(KI);
            bn_apply_half_kernel<<<cdiv((long)MPAD * K2, T), T>>>(src, KI, K2, g, b, relu, ah);
        }

        // GEMMs: xl = A @ Wl, xr = A @ Wr
        {
            dim3 grid(Nc / 128, MPAD / 128);
            gemm_fp16<<<grid, 256, GSMEM>>>(ah, btl, xl, Nc, K2);
            gemm_fp16<<<grid, 256, GSMEM>>>(ah, btr, xr, Nc, K2);
        }

        // attention: scores -> per-node softmax -> fused aggregate
        edge_score_kernel<<<cdiv((long)Etot * H * 32, T), T>>>(xl, xr, att[L], esc, Etot, H, C);
        softmax_kernel<<<cdiv(NN * H, T), T>>>(esc, alpha, H);
        {
            dim3 grid(NN, H);
            int relu_here = (L == 3) ? 1 : 0;
            aggfin_kernel<<<grid, 128>>>(xl, alpha, bia[L], h, H, C, relu_here);
        }
    }

    head_kernel<<<cdiv((long)NN * 32, T), T>>>(h, Wh, bh, pred);
    gather_kernel<<<cdiv(nt, T), T>>>(pred, y, tidx, out, nt);
}

// round 10
// speedup vs baseline: 14.0566x; 1.1208x over previous
#include <cuda_runtime.h>
#include <cuda_fp16.h>
#include <math.h>
#include <stdint.h>

// Problem constants (fixed by the dataset)
#define NN      8000
#define MPAD    8064        // 63 * 128
#define ERAW    64000
#define ETOT    (ERAW + NN)
#define FIN     3201
#define K2MAX   3264        // FIN padded to multiple of 64
#define HMAX    1024
#define BN_CHUNKS 20
#define BN_ROWS   (NN / BN_CHUNKS)

// ---------------- scratch (static device globals; no allocation) -------------
__device__ float  g_h    [(long)NN * HMAX];
__device__ __half g_xl   [(long)MPAD * HMAX];
__device__ __half g_xr   [(long)MPAD * HMAX];
__device__ __half g_Ah   [(long)MPAD * K2MAX];
__device__ __half g_Btl  [(long)HMAX * K2MAX];
__device__ __half g_Btr  [(long)HMAX * K2MAX];
__device__ float  g_e    [(long)ETOT * 2];
__device__ float  g_alpha[(long)ETOT * 2];
__device__ int    g_src  [ETOT];
__device__ int    g_dst  [ETOT];
__device__ int    g_cnt  [NN + 32];
__device__ int    g_cur  [NN];
__device__ int    g_off  [NN + 1];
__device__ int    g_csrc [ETOT];
__device__ int    g_ceid [ETOT];
__device__ float  g_bnp1 [BN_CHUNKS * K2MAX];
__device__ float  g_bnp2 [BN_CHUNKS * K2MAX];
__device__ float  g_mean [FIN];
__device__ float  g_rstd [FIN];
__device__ float  g_pred [NN];

// ------------------------------ PTX helpers ----------------------------------
__device__ __forceinline__ uint32_t smem_u32(const void* p) {
    uint32_t a;
    asm("{ .reg .u64 t; cvta.to.shared.u64 t, %1; cvt.u32.u64 %0, t; }"
        : "=r"(a) : "l"(p));
    return a;
}
__device__ __forceinline__ void cp_async16(uint32_t dst, const void* src) {
    asm volatile("cp.async.ca.shared.global [%0], [%1], 16;"
                 :: "r"(dst), "l"(src) : "memory");
}
__device__ __forceinline__ void cp_commit() {
    asm volatile("cp.async.commit_group;" ::: "memory");
}
template<int NG> __device__ __forceinline__ void cp_wait() {
    asm volatile("cp.async.wait_group %0;" :: "n"(NG) : "memory");
}
__device__ __forceinline__ void mma16816(float* c, const uint32_t* a,
                                         uint32_t b0, uint32_t b1) {
    asm volatile(
        "mma.sync.aligned.m16n8k16.row.col.f32.f16.f16.f32 "
        "{%0,%1,%2,%3}, {%4,%5,%6,%7}, {%8,%9}, {%0,%1,%2,%3};"
        : "+f"(c[0]), "+f"(c[1]), "+f"(c[2]), "+f"(c[3])
        : "r"(a[0]), "r"(a[1]), "r"(a[2]), "r"(a[3]), "r"(b0), "r"(b1));
}
__device__ __forceinline__ void ldm_x4(uint32_t* r, uint32_t addr) {
    asm volatile("ldmatrix.sync.aligned.m8n8.x4.shared.b16 {%0,%1,%2,%3}, [%4];"
                 : "=r"(r[0]), "=r"(r[1]), "=r"(r[2]), "=r"(r[3]) : "r"(addr));
}

// ------------------------------- small utils --------------------------------
__global__ void fill_int_kernel(int* p, int v, int n) {
    int i = blockIdx.x * blockDim.x + threadIdx.x;
    if (i < n) p[i] = v;
}

__global__ void build_edges_kernel(const int* __restrict__ ei, int E) {
    int i = blockIdx.x * blockDim.x + threadIdx.x;
    if (i >= E + NN) return;
    int s, d;
    if (i < E) { s = ei[i]; d = ei[E + i]; }
    else       { s = d = i - E; }
    g_src[i] = s;
    g_dst[i] = d;
    atomicAdd(&g_cnt[d], 1);
}

// single-block exclusive scan over g_cnt -> g_off (shfl + vectorized loads)
__global__ void scan_kernel() {
    __shared__ int wsum[8];
    int tid = threadIdx.x;
    int lane = tid & 31, wid = tid >> 5;
    const int CH = 32;
    int base = tid * CH;
    int vals[CH];
    #pragma unroll
    for (int i = 0; i < CH / 4; i++) {
        int4 v = *(const int4*)&g_cnt[base + i * 4];
        vals[i * 4 + 0] = v.x; vals[i * 4 + 1] = v.y;
        vals[i * 4 + 2] = v.z; vals[i * 4 + 3] = v.w;
    }
    int s = 0;
    #pragma unroll
    for (int i = 0; i < CH; i++) s += vals[i];
    int own = s;
    #pragma unroll
    for (int o = 1; o < 32; o <<= 1) {
        int v = __shfl_up_sync(0xffffffffu, s, o);
        if (lane >= o) s += v;
    }
    if (lane == 31) wsum[wid] = s;
    __syncthreads();
    if (wid == 0 && lane < 8) {
        int w = wsum[lane];
        #pragma unroll
        for (int o = 1; o < 8; o <<= 1) {
            int v = __shfl_up_sync(0xffu, w, o);
            if (lane >= o) w += v;
        }
        wsum[lane] = w - wsum[lane];
    }
    __syncthreads();
    int acc = wsum[wid] + s - own;
    #pragma unroll
    for (int i = 0; i < CH; i++) {
        int n = base + i;
        if (n < NN) { g_off[n] = acc; acc += vals[i]; }
    }
    if (tid == 255) g_off[NN] = acc;
}

__global__ void scatter_kernel(const int* __restrict__ ei, int E) {
    int i = blockIdx.x * blockDim.x + threadIdx.x;
    if (i >= E + NN) return;
    int s, d;
    if (i < E) { s = ei[i]; d = ei[E + i]; }
    else       { s = d = i - E; }
    int pos = g_off[d] + atomicAdd(&g_cur[d], 1);
    g_csrc[pos] = s;
    g_ceid[pos] = i;
}

// W [Kin x Ncol] fp32 -> Bt [Ncol x K2] fp16 (transposed, zero-padded in K)
__global__ void transpose_half_kernel(const float* __restrict__ W, int Kin, int Ncol, int K2,
                                      __half* __restrict__ o) {
    __shared__ float tile[32][33];
    int k0 = blockIdx.x * 32;
    int n0 = blockIdx.y * 32;
    int tx = threadIdx.x, ty = threadIdx.y;
    #pragma unroll
    for (int j = 0; j < 4; j++) {
        int k = k0 + ty + 8 * j;
        float v = 0.0f;
        if (k < Kin) v = W[(long)k * Ncol + n0 + tx];
        tile[ty + 8 * j][tx] = v;
    }
    __syncthreads();
    #pragma unroll
    for (int j = 0; j < 4; j++) {
        int n = n0 + ty + 8 * j;
        o[(long)n * K2 + k0 + tx] = __float2half(tile[tx][ty + 8 * j]);
    }
}

// ------------------------------- batchnorm ----------------------------------
__global__ void bn_partial_kernel(const float* __restrict__ h, int F, int stride) {
    int f = blockIdx.x * blockDim.x + threadIdx.x;
    if (f >= F) return;
    int r0 = blockIdx.y * BN_ROWS;
    float s = 0.0f, s2 = 0.0f;
    for (int r = r0; r < r0 + BN_ROWS; r++) {
        float v = h[(long)r * stride + f];
        s += v;
        s2 += v * v;
    }
    g_bnp1[blockIdx.y * F + f] = s;
    g_bnp2[blockIdx.y * F + f] = s2;
}

__global__ void bn_final_kernel(int F) {
    int f = blockIdx.x * blockDim.x + threadIdx.x;
    if (f >= F) return;
    float s = 0.0f, s2 = 0.0f;
    #pragma unroll
    for (int c = 0; c < BN_CHUNKS; c++) { s += g_bnp1[c * F + f]; s2 += g_bnp2[c * F + f]; }
    float m = s / (float)NN;
    float var = s2 / (float)NN - m * m;
    g_mean[f] = m;
    g_rstd[f] = rsqrtf(var + 1e-5f);
}

// BN-apply + optional relu + fp16 quantize + padding, writing A [MPAD x K2]
__global__ void bn_apply_half_kernel(const float* __restrict__ in, int Fin, int K2,
                                     const float* __restrict__ gam, const float* __restrict__ bet,
                                     int relu, __half* __restrict__ A) {
    long i = (long)blockIdx.x * blockDim.x + threadIdx.x;
    long total = (long)MPAD * K2;
    if (i >= total) return;
    int row = (int)(i / K2);
    int col = (int)(i % K2);
    float v = 0.0f;
    if (row < NN && col < Fin) {
        v = (in[(long)row * Fin + col] - g_mean[col]) * g_rstd[col] * gam[col] + bet[col];
        if (relu) v = fmaxf(v, 0.0f);
    }
    A[i] = __float2half(v);
}

// ------------------ mma.sync fp16 GEMM, fused xl/xr (z-dim) ------------------
#define STR       40
#define STR2      (STR * 2)
#define BUF_B     (128 * STR2)
#define A_OFF     0
#define B_OFF     (2 * BUF_B)
#define GSMEM     (4 * BUF_B)               // 40960 bytes

__global__ __launch_bounds__(256) void gemm_fp16_dual(
    const __half* __restrict__ Ah,
    const __half* __restrict__ Bt0, const __half* __restrict__ Bt1,
    __half* __restrict__ C0, __half* __restrict__ C1, int N, int K2)
{
    extern __shared__ char sm[];
    uint32_t sb = smem_u32(sm);
    const int tid = threadIdx.x;
    const int wid = tid >> 5, lane = tid & 31;
    const int wm = wid & 1, wn = wid >> 1;
    const int g = lane >> 2, q = lane & 3;
    const long row0 = (long)blockIdx.y * 128;
    const long col0 = (long)blockIdx.x * 128;
    const __half* Bt = blockIdx.z ? Bt1 : Bt0;
    __half* C = blockIdx.z ? C1 : C0;

    float acc[4][4][4];
    #pragma unroll
    for (int i = 0; i < 4; i++)
        #pragma unroll
        for (int j = 0; j < 4; j++)
            #pragma unroll
            for (int t = 0; t < 4; t++) acc[i][j][t] = 0.0f;

    const int NS = K2 >> 5;

    auto issue = [&](int s, int buf) {
        int k0 = s << 5;
        #pragma unroll
        for (int it = 0; it < 2; it++) {
            int c = tid + (it << 8);
            int row = c >> 2;
            int kc = (c & 3) * 8;
            uint32_t so = (uint32_t)(buf * BUF_B + row * STR2 + kc * 2);
            long ga = (row0 + row) * K2 + k0 + kc;
            long gb = (col0 + row) * K2 + k0 + kc;
            cp_async16(sb + A_OFF + so, Ah + ga);
            cp_async16(sb + B_OFF + so, Bt + gb);
        }
        cp_commit();
    };

    const uint32_t aoff = (uint32_t)((wm * 64 + (lane & 15)) * STR2 + (lane >> 4) * 16);
    const uint32_t boff = (uint32_t)((wn * 32 + ((lane >> 4) & 1) * 8 + (lane & 7)) * STR2
                                     + ((lane >> 3) & 1) * 16);

    issue(0, 0);

    for (int s = 0; s < NS; s++) {
        int buf = s & 1;
        if (s + 1 < NS) { issue(s + 1, buf ^ 1); cp_wait<1>(); }
        else            { cp_wait<0>(); }
        __syncthreads();

        uint32_t a_b = sb + A_OFF + buf * BUF_B;
        uint32_t b_b = sb + B_OFF + buf * BUF_B;

        #pragma unroll
        for (int kk = 0; kk < 2; kk++) {
            uint32_t kByte = (uint32_t)(kk * 32);
            uint32_t Bf[8];
            #pragma unroll
            for (int jp = 0; jp < 2; jp++) {
                uint32_t off = boff + kByte + (uint32_t)(jp * 16 * STR2);
                ldm_x4(&Bf[jp * 4], b_b + off);
            }
            #pragma unroll
            for (int i = 0; i < 4; i++) {
                uint32_t off = aoff + kByte + (uint32_t)(i * 16 * STR2);
                uint32_t af[4];
                ldm_x4(af, a_b + off);
                #pragma unroll
                for (int j = 0; j < 4; j++) mma16816(acc[i][j], af, Bf[2*j], Bf[2*j+1]);
            }
        }
        __syncthreads();
    }

    #pragma unroll
    for (int i = 0; i < 4; i++) {
        long r = row0 + wm * 64 + i * 16 + g;
        #pragma unroll
        for (int j = 0; j < 4; j++) {
            long cc = col0 + wn * 32 + j * 8 + 2 * q;
            *(__half2*)(C + r * N + cc)       = __floats2half2_rn(acc[i][j][0], acc[i][j][1]);
            *(__half2*)(C + (r + 8) * N + cc) = __floats2half2_rn(acc[i][j][2], acc[i][j][3]);
        }
    }
}

// ------------------------------- GATv2 edge ops ------------------------------
__global__ void edge_score_kernel(const __half* __restrict__ xl, const __half* __restrict__ xr,
                                  const float* __restrict__ att, float* __restrict__ esc,
                                  int E, int H, int C) {
    int warp = (blockIdx.x * blockDim.x + threadIdx.x) >> 5;
    int lane = threadIdx.x & 31;
    if (warp >= E * H) return;
    int e = warp / H, h = warp % H;
    const __half* pl = xl + (long)g_src[e] * H * C + h * C;
    const __half* pr = xr + (long)g_dst[e] * H * C + h * C;
    const float* pa = att + h * C;
    float sum = 0.0f;
    for (int c = lane * 8; c < C; c += 256) {
        uint4 av = *(const uint4*)(pl + c);
        uint4 bv = *(const uint4*)(pr + c);
        float4 w0 = *(const float4*)(pa + c);
        float4 w1 = *(const float4*)(pa + c + 4);
        const __half2* a2 = (const __half2*)&av;
        const __half2* b2 = (const __half2*)&bv;
        float wv[8] = { w0.x, w0.y, w0.z, w0.w, w1.x, w1.y, w1.z, w1.w };
        #pragma unroll
        for (int t = 0; t < 4; t++) {
            float2 af = __half22float2(a2[t]);
            float2 bf = __half22float2(b2[t]);
            float z0 = af.x + bf.x; z0 = (z0 > 0.f) ? z0 : 0.2f * z0;
            float z1 = af.y + bf.y; z1 = (z1 > 0.f) ? z1 : 0.2f * z1;
            sum += z0 * wv[2 * t] + z1 * wv[2 * t + 1];
        }
    }
    #pragma unroll
    for (int o = 16; o; o >>= 1) sum += __shfl_xor_sync(0xffffffffu, sum, o);
    if (lane == 0) esc[e * H + h] = sum;
}

// per-(node,head) softmax over incoming edges; folds 1/deg for mean-aggr
__global__ void softmax_kernel(const float* __restrict__ esc, float* __restrict__ alpha, int H) {
    int i = blockIdx.x * blockDim.x + threadIdx.x;
    if (i >= NN * H) return;
    int n = i / H, h = i % H;
    int st = g_off[n], en = g_off[n + 1];
    float mx = -3.0e38f;
    for (int p = st; p < en; p++) mx = fmaxf(mx, esc[g_ceid[p] * H + h]);
    float sum = 0.0f;
    for (int p = st; p < en; p++) {
        float v = expf(esc[g_ceid[p] * H + h] - mx);
        alpha[p * H + h] = v;
        sum += v;
    }
    float inv = 1.0f / (sum * (float)(en - st));
    for (int p = st; p < en; p++) alpha[p * H + h] *= inv;
}

// fused gather + weighted-mean aggregate + bias (+relu): block=(node, head)
__global__ __launch_bounds__(128) void aggfin_kernel(
    const __half* __restrict__ xl, const float* __restrict__ alpha,
    const float* __restrict__ bias, float* __restrict__ out,
    int H, int C, int relu)
{
    __shared__ int   ssrc[64];
    __shared__ float sal[64];
    int n = blockIdx.x;
    int h = blockIdx.y;
    int HC = H * C;
    int f0 = h * C + threadIdx.x * 4;
    int st = g_off[n], en = g_off[n + 1];

    float4 acc = make_float4(0.f, 0.f, 0.f, 0.f);
    for (int c0 = st; c0 < en; c0 += 64) {
        int cnt = min(64, en - c0);
        if ((int)threadIdx.x < cnt) {
            ssrc[threadIdx.x] = g_csrc[c0 + threadIdx.x];
            sal[threadIdx.x]  = alpha[(c0 + threadIdx.x) * H + h];
        }
        __syncthreads();
        for (int j = 0; j < cnt; j++) {
            float a = sal[j];
            uint2 raw = *(const uint2*)(xl + (long)ssrc[j] * HC + f0);
            float2 v0 = __half22float2(((const __half2*)&raw)[0]);
            float2 v1 = __half22float2(((const __half2*)&raw)[1]);
            acc.x += a * v0.x; acc.y += a * v0.y;
            acc.z += a * v1.x; acc.w += a * v1.y;
        }
        __syncthreads();
    }
    float4 b = *(const float4*)(bias + f0);
    acc.x += b.x; acc.y += b.y; acc.z += b.z; acc.w += b.w;
    if (relu) {
        acc.x = fmaxf(acc.x, 0.f); acc.y = fmaxf(acc.y, 0.f);
        acc.z = fmaxf(acc.z, 0.f); acc.w = fmaxf(acc.w, 0.f);
    }
    *(float4*)(out + (long)n * HC + f0) = acc;
}

// ------------------------------- head + gather -------------------------------
__global__ void head_kernel(const float* __restrict__ h, const float* __restrict__ Wh,
                            const float* __restrict__ bh, float* __restrict__ pred) {
    int warp = (blockIdx.x * blockDim.x + threadIdx.x) >> 5;
    int lane = threadIdx.x & 31;
    if (warp >= NN) return;
    const float* p = h + (long)warp * 512;
    float s = 0.0f;
    for (int c = lane * 4; c < 512; c += 128) {
        float4 v = *(const float4*)(p + c);
        float4 w = *(const float4*)(Wh + c);
        s += v.x * w.x + v.y * w.y + v.z * w.z + v.w * w.w;
    }
    #pragma unroll
    for (int o = 16; o; o >>= 1) s += __shfl_xor_sync(0xffffffffu, s, o);
    if (lane == 0) pred[warp] = 1.0f / (1.0f + expf(-(s + bh[0])));
}

__global__ void gather_kernel(const float* __restrict__ pred, const float* __restrict__ y,
                              const int* __restrict__ tidx, float* __restrict__ out, int nt) {
    int i = blockIdx.x * blockDim.x + threadIdx.x;
    if (i >= nt) return;
    int n = tidx[i];
    out[i]      = pred[n];
    out[nt + i] = y[n];
}

// --------------------------------- host side ---------------------------------
static inline long cdiv(long a, long b) { return (a + b - 1) / b; }

extern "C" void kernel_launch(void* const* d_in, const int* in_sizes, int n_in,
                              void* d_out, int out_size) {
    const float* x    = (const float*)d_in[0];
    const int*   ei   = (const int*)  d_in[1];
    const float* y    = (const float*)d_in[2];
    const int*   tidx = (const int*)  d_in[3];
    const float* bn0g = (const float*)d_in[4];
    const float* bn0b = (const float*)d_in[5];
    const float* Wl[4] = { (const float*)d_in[6],  (const float*)d_in[12],
                           (const float*)d_in[18], (const float*)d_in[24] };
    const float* Wr[4] = { (const float*)d_in[7],  (const float*)d_in[13],
                           (const float*)d_in[19], (const float*)d_in[25] };
    const float* att[4] = { (const float*)d_in[8],  (const float*)d_in[14],
                            (const float*)d_in[20], (const float*)d_in[26] };
    const float* bia[4] = { (const float*)d_in[9],  (const float*)d_in[15],
                            (const float*)d_in[21], (const float*)d_in[27] };
    const float* bng[3] = { (const float*)d_in[10], (const float*)d_in[16],
                            (const float*)d_in[22] };
    const float* bnb[3] = { (const float*)d_in[11], (const float*)d_in[17],
                            (const float*)d_in[23] };
    const float* Wh = (const float*)d_in[28];
    const float* bh = (const float*)d_in[29];
    float* out = (float*)d_out;

    int E  = in_sizes[1] / 2;
    int nt = in_sizes[3];

    float *h, *esc, *alpha, *pred;
    int *cnt, *cur;
    __half *xl, *xr, *ah, *btl, *btr;
    cudaGetSymbolAddress((void**)&h,     g_h);
    cudaGetSymbolAddress((void**)&xl,    g_xl);
    cudaGetSymbolAddress((void**)&xr,    g_xr);
    cudaGetSymbolAddress((void**)&esc,   g_e);
    cudaGetSymbolAddress((void**)&alpha, g_alpha);
    cudaGetSymbolAddress((void**)&pred,  g_pred);
    cudaGetSymbolAddress((void**)&cnt,   g_cnt);
    cudaGetSymbolAddress((void**)&cur,   g_cur);
    cudaGetSymbolAddress((void**)&ah,    g_Ah);
    cudaGetSymbolAddress((void**)&btl,   g_Btl);
    cudaGetSymbolAddress((void**)&btr,   g_Btr);

    cudaFuncSetAttribute(gemm_fp16_dual, cudaFuncAttributeMaxDynamicSharedMemorySize, GSMEM);

    const int T = 256;
    int Etot = E + NN;

    // edges -> CSR (once per launch)
    fill_int_kernel<<<cdiv(NN + 32, T), T>>>(cnt, 0, NN + 32);
    fill_int_kernel<<<cdiv(NN, T), T>>>(cur, 0, NN);
    build_edges_kernel<<<cdiv(Etot, T), T>>>(ei, E);
    scan_kernel<<<1, 256>>>();
    scatter_kernel<<<cdiv(Etot, T), T>>>(ei, E);

    int Kin [4] = { FIN, 1024, 512, 512 };
    int K2s [4] = { K2MAX, 1024, 512, 512 };
    int Ncs [4] = { 1024, 512, 512, 512 };
    int heads[4] = { 2, 1, 1, 1 };

    for (int L = 0; L < 4; L++) {
        int KI = Kin[L], K2 = K2s[L], Nc = Ncs[L];
        int H = heads[L], C = Nc / H;

        // weight transpose -> fp16
        {
            dim3 grid(K2 / 32, Nc / 32), blk(32, 8);
            transpose_half_kernel<<<grid, blk>>>(Wl[L], KI, Nc, K2, btl);
            transpose_half_kernel<<<grid, blk>>>(Wr[L], KI, Nc, K2, btr);
        }

        // BN stats + apply/quantize/pad
        {
            const float* src = (L == 0) ? x : h;
            const float* g = (L == 0) ? bn0g : bng[L - 1];
            const float* b = (L == 0) ? bn0b : bnb[L - 1];
            int relu = (L == 0) ? 0 : 1;
            dim3 grid(cdiv(KI, T), BN_CHUNKS);
            bn_partial_kernel<<<grid, T>>>(src, KI, KI);
            bn_final_kernel<<<cdiv(KI, T), T>>>(KI);
            bn_apply_half_kernel<<<cdiv((long)MPAD * K2, T), T>>>(src, KI, K2, g, b, relu, ah);
        }

        // fused GEMM pair: xl = A @ Wl, xr = A @ Wr
        {
            dim3 grid(Nc / 128, MPAD / 128, 2);
            gemm_fp16_dual<<<grid, 256, GSMEM>>>(ah, btl, btr, xl, xr, Nc, K2);
        }

        // attention: scores -> per-node softmax -> fused aggregate
        edge_score_kernel<<<cdiv((long)Etot * H * 32, T), T>>>(xl, xr, att[L], esc, Etot, H, C);
        softmax_kernel<<<cdiv(NN * H, T), T>>>(esc, alpha, H);
        {
            dim3 grid(NN, H);
            int relu_here = (L == 3) ? 1 : 0;
            aggfin_kernel<<<grid, 128>>>(xl, alpha, bia[L], h, H, C, relu_here);
        }
    }

    head_kernel<<<cdiv((long)NN * 32, T), T>>>(h, Wh, bh, pred);
    gather_kernel<<<cdiv(nt, T), T>>>(pred, y, tidx, out, nt);
}

// round 11
// speedup vs baseline: 14.7866x; 1.0519x over previous
#include <cuda_runtime.h>
#include <cuda_fp16.h>
#include <math.h>
#include <stdint.h>

// Problem constants (fixed by the dataset)
#define NN      8000
#define MPAD    8064        // 63 * 128
#define ERAW    64000
#define ETOT    (ERAW + NN)
#define FIN     3201
#define K2MAX   3264        // FIN padded to multiple of 64
#define HMAX    1024
#define BN_CHUNKS 20
#define BN_ROWS   (NN / BN_CHUNKS)

// ---------------- scratch (static device globals; no allocation) -------------
__device__ float  g_h    [(long)NN * HMAX];
__device__ __half g_xl   [(long)MPAD * HMAX];
__device__ __half g_xr   [(long)MPAD * HMAX];
__device__ __half g_Ah   [(long)MPAD * K2MAX];
__device__ __half g_Btl  [(long)HMAX * K2MAX];
__device__ __half g_Btr  [(long)HMAX * K2MAX];
__device__ int    g_cnt  [NN + 32];
__device__ int    g_cur  [NN];
__device__ int    g_off  [NN + 1];
__device__ int    g_csrc [ETOT];
__device__ float  g_bnp1 [BN_CHUNKS * K2MAX];
__device__ float  g_bnp2 [BN_CHUNKS * K2MAX];
__device__ float  g_mean [FIN];
__device__ float  g_rstd [FIN];
__device__ float  g_pred [NN];

// ------------------------------ PTX helpers ----------------------------------
__device__ __forceinline__ uint32_t smem_u32(const void* p) {
    uint32_t a;
    asm("{ .reg .u64 t; cvta.to.shared.u64 t, %1; cvt.u32.u64 %0, t; }"
        : "=r"(a) : "l"(p));
    return a;
}
__device__ __forceinline__ void cp_async16(uint32_t dst, const void* src) {
    asm volatile("cp.async.ca.shared.global [%0], [%1], 16;"
                 :: "r"(dst), "l"(src) : "memory");
}
__device__ __forceinline__ void cp_commit() {
    asm volatile("cp.async.commit_group;" ::: "memory");
}
template<int NG> __device__ __forceinline__ void cp_wait() {
    asm volatile("cp.async.wait_group %0;" :: "n"(NG) : "memory");
}
__device__ __forceinline__ void mma16816(float* c, const uint32_t* a,
                                         uint32_t b0, uint32_t b1) {
    asm volatile(
        "mma.sync.aligned.m16n8k16.row.col.f32.f16.f16.f32 "
        "{%0,%1,%2,%3}, {%4,%5,%6,%7}, {%8,%9}, {%0,%1,%2,%3};"
        : "+f"(c[0]), "+f"(c[1]), "+f"(c[2]), "+f"(c[3])
        : "r"(a[0]), "r"(a[1]), "r"(a[2]), "r"(a[3]), "r"(b0), "r"(b1));
}
__device__ __forceinline__ void ldm_x4(uint32_t* r, uint32_t addr) {
    asm volatile("ldmatrix.sync.aligned.m8n8.x4.shared.b16 {%0,%1,%2,%3}, [%4];"
                 : "=r"(r[0]), "=r"(r[1]), "=r"(r[2]), "=r"(r[3]) : "r"(addr));
}

// ------------------------------- small utils --------------------------------
__global__ void fill_int_kernel(int* p, int v, int n) {
    int i = blockIdx.x * blockDim.x + threadIdx.x;
    if (i < n) p[i] = v;
}

__global__ void count_edges_kernel(const int* __restrict__ ei, int E) {
    int i = blockIdx.x * blockDim.x + threadIdx.x;
    if (i >= E + NN) return;
    int d = (i < E) ? ei[E + i] : (i - E);
    atomicAdd(&g_cnt[d], 1);
}

// single-block exclusive scan over g_cnt -> g_off (shfl + vectorized loads)
__global__ void scan_kernel() {
    __shared__ int wsum[8];
    int tid = threadIdx.x;
    int lane = tid & 31, wid = tid >> 5;
    const int CH = 32;
    int base = tid * CH;
    int vals[CH];
    #pragma unroll
    for (int i = 0; i < CH / 4; i++) {
        int4 v = *(const int4*)&g_cnt[base + i * 4];
        vals[i * 4 + 0] = v.x; vals[i * 4 + 1] = v.y;
        vals[i * 4 + 2] = v.z; vals[i * 4 + 3] = v.w;
    }
    int s = 0;
    #pragma unroll
    for (int i = 0; i < CH; i++) s += vals[i];
    int own = s;
    #pragma unroll
    for (int o = 1; o < 32; o <<= 1) {
        int v = __shfl_up_sync(0xffffffffu, s, o);
        if (lane >= o) s += v;
    }
    if (lane == 31) wsum[wid] = s;
    __syncthreads();
    if (wid == 0 && lane < 8) {
        int w = wsum[lane];
        #pragma unroll
        for (int o = 1; o < 8; o <<= 1) {
            int v = __shfl_up_sync(0xffu, w, o);
            if (lane >= o) w += v;
        }
        wsum[lane] = w - wsum[lane];
    }
    __syncthreads();
    int acc = wsum[wid] + s - own;
    #pragma unroll
    for (int i = 0; i < CH; i++) {
        int n = base + i;
        if (n < NN) { g_off[n] = acc; acc += vals[i]; }
    }
    if (tid == 255) g_off[NN] = acc;
}

__global__ void scatter_kernel(const int* __restrict__ ei, int E) {
    int i = blockIdx.x * blockDim.x + threadIdx.x;
    if (i >= E + NN) return;
    int s, d;
    if (i < E) { s = ei[i]; d = ei[E + i]; }
    else       { s = d = i - E; }
    int pos = g_off[d] + atomicAdd(&g_cur[d], 1);
    g_csrc[pos] = s;
}

// W [Kin x Ncol] fp32 -> Bt [Ncol x K2] fp16 (transposed, zero-padded in K)
__global__ void transpose_half_kernel(const float* __restrict__ W, int Kin, int Ncol, int K2,
                                      __half* __restrict__ o) {
    __shared__ float tile[32][33];
    int k0 = blockIdx.x * 32;
    int n0 = blockIdx.y * 32;
    int tx = threadIdx.x, ty = threadIdx.y;
    #pragma unroll
    for (int j = 0; j < 4; j++) {
        int k = k0 + ty + 8 * j;
        float v = 0.0f;
        if (k < Kin) v = W[(long)k * Ncol + n0 + tx];
        tile[ty + 8 * j][tx] = v;
    }
    __syncthreads();
    #pragma unroll
    for (int j = 0; j < 4; j++) {
        int n = n0 + ty + 8 * j;
        o[(long)n * K2 + k0 + tx] = __float2half(tile[tx][ty + 8 * j]);
    }
}

// ------------------------------- batchnorm ----------------------------------
__global__ void bn_partial_kernel(const float* __restrict__ h, int F, int stride) {
    int f = blockIdx.x * blockDim.x + threadIdx.x;
    if (f >= F) return;
    int r0 = blockIdx.y * BN_ROWS;
    float s = 0.0f, s2 = 0.0f;
    for (int r = r0; r < r0 + BN_ROWS; r++) {
        float v = h[(long)r * stride + f];
        s += v;
        s2 += v * v;
    }
    g_bnp1[blockIdx.y * F + f] = s;
    g_bnp2[blockIdx.y * F + f] = s2;
}

__global__ void bn_final_kernel(int F) {
    int f = blockIdx.x * blockDim.x + threadIdx.x;
    if (f >= F) return;
    float s = 0.0f, s2 = 0.0f;
    #pragma unroll
    for (int c = 0; c < BN_CHUNKS; c++) { s += g_bnp1[c * F + f]; s2 += g_bnp2[c * F + f]; }
    float m = s / (float)NN;
    float var = s2 / (float)NN - m * m;
    g_mean[f] = m;
    g_rstd[f] = rsqrtf(var + 1e-5f);
}

// BN-apply + optional relu + fp16 quantize + padding, writing A [MPAD x K2]
__global__ void bn_apply_half_kernel(const float* __restrict__ in, int Fin, int K2,
                                     const float* __restrict__ gam, const float* __restrict__ bet,
                                     int relu, __half* __restrict__ A) {
    long i = (long)blockIdx.x * blockDim.x + threadIdx.x;
    long total = (long)MPAD * K2;
    if (i >= total) return;
    int row = (int)(i / K2);
    int col = (int)(i % K2);
    float v = 0.0f;
    if (row < NN && col < Fin) {
        v = (in[(long)row * Fin + col] - g_mean[col]) * g_rstd[col] * gam[col] + bet[col];
        if (relu) v = fmaxf(v, 0.0f);
    }
    A[i] = __float2half(v);
}

// ------------------ mma.sync fp16 GEMM, fused xl/xr (z-dim) ------------------
#define STR       40
#define STR2      (STR * 2)
#define BUF_B     (128 * STR2)
#define A_OFF     0
#define B_OFF     (2 * BUF_B)
#define GSMEM     (4 * BUF_B)               // 40960 bytes

__global__ __launch_bounds__(256) void gemm_fp16_dual(
    const __half* __restrict__ Ah,
    const __half* __restrict__ Bt0, const __half* __restrict__ Bt1,
    __half* __restrict__ C0, __half* __restrict__ C1, int N, int K2)
{
    extern __shared__ char sm[];
    uint32_t sb = smem_u32(sm);
    const int tid = threadIdx.x;
    const int wid = tid >> 5, lane = tid & 31;
    const int wm = wid & 1, wn = wid >> 1;
    const int g = lane >> 2, q = lane & 3;
    const long row0 = (long)blockIdx.y * 128;
    const long col0 = (long)blockIdx.x * 128;
    const __half* Bt = blockIdx.z ? Bt1 : Bt0;
    __half* C = blockIdx.z ? C1 : C0;

    float acc[4][4][4];
    #pragma unroll
    for (int i = 0; i < 4; i++)
        #pragma unroll
        for (int j = 0; j < 4; j++)
            #pragma unroll
            for (int t = 0; t < 4; t++) acc[i][j][t] = 0.0f;

    const int NS = K2 >> 5;

    auto issue = [&](int s, int buf) {
        int k0 = s << 5;
        #pragma unroll
        for (int it = 0; it < 2; it++) {
            int c = tid + (it << 8);
            int row = c >> 2;
            int kc = (c & 3) * 8;
            uint32_t so = (uint32_t)(buf * BUF_B + row * STR2 + kc * 2);
            long ga = (row0 + row) * K2 + k0 + kc;
            long gb = (col0 + row) * K2 + k0 + kc;
            cp_async16(sb + A_OFF + so, Ah + ga);
            cp_async16(sb + B_OFF + so, Bt + gb);
        }
        cp_commit();
    };

    const uint32_t aoff = (uint32_t)((wm * 64 + (lane & 15)) * STR2 + (lane >> 4) * 16);
    const uint32_t boff = (uint32_t)((wn * 32 + ((lane >> 4) & 1) * 8 + (lane & 7)) * STR2
                                     + ((lane >> 3) & 1) * 16);

    issue(0, 0);

    for (int s = 0; s < NS; s++) {
        int buf = s & 1;
        if (s + 1 < NS) { issue(s + 1, buf ^ 1); cp_wait<1>(); }
        else            { cp_wait<0>(); }
        __syncthreads();

        uint32_t a_b = sb + A_OFF + buf * BUF_B;
        uint32_t b_b = sb + B_OFF + buf * BUF_B;

        #pragma unroll
        for (int kk = 0; kk < 2; kk++) {
            uint32_t kByte = (uint32_t)(kk * 32);
            uint32_t Bf[8];
            #pragma unroll
            for (int jp = 0; jp < 2; jp++) {
                uint32_t off = boff + kByte + (uint32_t)(jp * 16 * STR2);
                ldm_x4(&Bf[jp * 4], b_b + off);
            }
            #pragma unroll
            for (int i = 0; i < 4; i++) {
                uint32_t off = aoff + kByte + (uint32_t)(i * 16 * STR2);
                uint32_t af[4];
                ldm_x4(af, a_b + off);
                #pragma unroll
                for (int j = 0; j < 4; j++) mma16816(acc[i][j], af, Bf[2*j], Bf[2*j+1]);
            }
        }
        __syncthreads();
    }

    #pragma unroll
    for (int i = 0; i < 4; i++) {
        long r = row0 + wm * 64 + i * 16 + g;
        #pragma unroll
        for (int j = 0; j < 4; j++) {
            long cc = col0 + wn * 32 + j * 8 + 2 * q;
            *(__half2*)(C + r * N + cc)       = __floats2half2_rn(acc[i][j][0], acc[i][j][1]);
            *(__half2*)(C + (r + 8) * N + cc) = __floats2half2_rn(acc[i][j][2], acc[i][j][3]);
        }
    }
}

// -------------- fused attention: score + online softmax + aggregate ----------
// block = (node n, head h); 128 threads, 4 features each (C = 512 always)
__global__ __launch_bounds__(128) void attn_fused_kernel(
    const __half* __restrict__ xl, const __half* __restrict__ xr,
    const float* __restrict__ att, const float* __restrict__ bias,
    float* __restrict__ out, int H, int C, int relu)
{
    __shared__ float red[2][4];
    const int tid = threadIdx.x;
    const int lane = tid & 31, wid = tid >> 5;
    const int n = blockIdx.x, h = blockIdx.y;
    const int HC = H * C;
    const int f0 = h * C + tid * 4;

    // per-thread constants
    float4 attv = *(const float4*)(att + h * C + tid * 4);
    uint2 xr_raw = *(const uint2*)(xr + (long)n * HC + f0);
    float2 xr0 = __half22float2(((const __half2*)&xr_raw)[0]);
    float2 xr1 = __half22float2(((const __half2*)&xr_raw)[1]);

    const int st = g_off[n], en = g_off[n + 1];

    float m = -3.0e38f, ssum = 0.0f;
    float4 acc = make_float4(0.f, 0.f, 0.f, 0.f);

    uint2 raw = *(const uint2*)(xl + (long)g_csrc[st] * HC + f0);
    int par = 0;
    for (int p = st; p < en; p++, par ^= 1) {
        uint2 cur = raw;
        if (p + 1 < en)
            raw = *(const uint2*)(xl + (long)g_csrc[p + 1] * HC + f0);

        float2 a0 = __half22float2(((const __half2*)&cur)[0]);
        float2 a1 = __half22float2(((const __half2*)&cur)[1]);

        float z0 = a0.x + xr0.x; z0 = (z0 > 0.f) ? z0 : 0.2f * z0;
        float z1 = a0.y + xr0.y; z1 = (z1 > 0.f) ? z1 : 0.2f * z1;
        float z2 = a1.x + xr1.x; z2 = (z2 > 0.f) ? z2 : 0.2f * z2;
        float z3 = a1.y + xr1.y; z3 = (z3 > 0.f) ? z3 : 0.2f * z3;
        float part = z0 * attv.x + z1 * attv.y + z2 * attv.z + z3 * attv.w;

        // block reduction (4 warps), double-buffered smem
        #pragma unroll
        for (int o = 16; o; o >>= 1) part += __shfl_xor_sync(0xffffffffu, part, o);
        if (lane == 0) red[par][wid] = part;
        __syncthreads();
        float e = red[par][0] + red[par][1] + red[par][2] + red[par][3];

        // online softmax update
        float mnew = fmaxf(m, e);
        float corr = __expf(m - mnew);
        float w = __expf(e - mnew);
        ssum = ssum * corr + w;
        acc.x = acc.x * corr + w * a0.x;
        acc.y = acc.y * corr + w * a0.y;
        acc.z = acc.z * corr + w * a1.x;
        acc.w = acc.w * corr + w * a1.y;
        m = mnew;
    }

    float inv = 1.0f / (ssum * (float)(en - st));
    float4 b = *(const float4*)(bias + f0);
    acc.x = acc.x * inv + b.x;
    acc.y = acc.y * inv + b.y;
    acc.z = acc.z * inv + b.z;
    acc.w = acc.w * inv + b.w;
    if (relu) {
        acc.x = fmaxf(acc.x, 0.f); acc.y = fmaxf(acc.y, 0.f);
        acc.z = fmaxf(acc.z, 0.f); acc.w = fmaxf(acc.w, 0.f);
    }
    *(float4*)(out + (long)n * HC + f0) = acc;
}

// ------------------------------- head + gather -------------------------------
__global__ void head_kernel(const float* __restrict__ h, const float* __restrict__ Wh,
                            const float* __restrict__ bh, float* __restrict__ pred) {
    int warp = (blockIdx.x * blockDim.x + threadIdx.x) >> 5;
    int lane = threadIdx.x & 31;
    if (warp >= NN) return;
    const float* p = h + (long)warp * 512;
    float s = 0.0f;
    for (int c = lane * 4; c < 512; c += 128) {
        float4 v = *(const float4*)(p + c);
        float4 w = *(const float4*)(Wh + c);
        s += v.x * w.x + v.y * w.y + v.z * w.z + v.w * w.w;
    }
    #pragma unroll
    for (int o = 16; o; o >>= 1) s += __shfl_xor_sync(0xffffffffu, s, o);
    if (lane == 0) pred[warp] = 1.0f / (1.0f + expf(-(s + bh[0])));
}

__global__ void gather_kernel(const float* __restrict__ pred, const float* __restrict__ y,
                              const int* __restrict__ tidx, float* __restrict__ out, int nt) {
    int i = blockIdx.x * blockDim.x + threadIdx.x;
    if (i >= nt) return;
    int n = tidx[i];
    out[i]      = pred[n];
    out[nt + i] = y[n];
}

// --------------------------------- host side ---------------------------------
static inline long cdiv(long a, long b) { return (a + b - 1) / b; }

extern "C" void kernel_launch(void* const* d_in, const int* in_sizes, int n_in,
                              void* d_out, int out_size) {
    const float* x    = (const float*)d_in[0];
    const int*   ei   = (const int*)  d_in[1];
    const float* y    = (const float*)d_in[2];
    const int*   tidx = (const int*)  d_in[3];
    const float* bn0g = (const float*)d_in[4];
    const float* bn0b = (const float*)d_in[5];
    const float* Wl[4] = { (const float*)d_in[6],  (const float*)d_in[12],
                           (const float*)d_in[18], (const float*)d_in[24] };
    const float* Wr[4] = { (const float*)d_in[7],  (const float*)d_in[13],
                           (const float*)d_in[19], (const float*)d_in[25] };
    const float* att[4] = { (const float*)d_in[8],  (const float*)d_in[14],
                            (const float*)d_in[20], (const float*)d_in[26] };
    const float* bia[4] = { (const float*)d_in[9],  (const float*)d_in[15],
                            (const float*)d_in[21], (const float*)d_in[27] };
    const float* bng[3] = { (const float*)d_in[10], (const float*)d_in[16],
                            (const float*)d_in[22] };
    const float* bnb[3] = { (const float*)d_in[11], (const float*)d_in[17],
                            (const float*)d_in[23] };
    const float* Wh = (const float*)d_in[28];
    const float* bh = (const float*)d_in[29];
    float* out = (float*)d_out;

    int E  = in_sizes[1] / 2;
    int nt = in_sizes[3];

    float *h, *pred;
    int *cnt, *cur;
    __half *xl, *xr, *ah, *btl, *btr;
    cudaGetSymbolAddress((void**)&h,     g_h);
    cudaGetSymbolAddress((void**)&xl,    g_xl);
    cudaGetSymbolAddress((void**)&xr,    g_xr);
    cudaGetSymbolAddress((void**)&pred,  g_pred);
    cudaGetSymbolAddress((void**)&cnt,   g_cnt);
    cudaGetSymbolAddress((void**)&cur,   g_cur);
    cudaGetSymbolAddress((void**)&ah,    g_Ah);
    cudaGetSymbolAddress((void**)&btl,   g_Btl);
    cudaGetSymbolAddress((void**)&btr,   g_Btr);

    cudaFuncSetAttribute(gemm_fp16_dual, cudaFuncAttributeMaxDynamicSharedMemorySize, GSMEM);

    const int T = 256;
    int Etot = E + NN;

    // edges -> CSR (once per launch)
    fill_int_kernel<<<cdiv(NN + 32, T), T>>>(cnt, 0, NN + 32);
    fill_int_kernel<<<cdiv(NN, T), T>>>(cur, 0, NN);
    count_edges_kernel<<<cdiv(Etot, T), T>>>(ei, E);
    scan_kernel<<<1, 256>>>();
    scatter_kernel<<<cdiv(Etot, T), T>>>(ei, E);

    int Kin [4] = { FIN, 1024, 512, 512 };
    int K2s [4] = { K2MAX, 1024, 512, 512 };
    int Ncs [4] = { 1024, 512, 512, 512 };
    int heads[4] = { 2, 1, 1, 1 };

    for (int L = 0; L < 4; L++) {
        int KI = Kin[L], K2 = K2s[L], Nc = Ncs[L];
        int H = heads[L], C = Nc / H;

        // weight transpose -> fp16
        {
            dim3 grid(K2 / 32, Nc / 32), blk(32, 8);
            transpose_half_kernel<<<grid, blk>>>(Wl[L], KI, Nc, K2, btl);
            transpose_half_kernel<<<grid, blk>>>(Wr[L], KI, Nc, K2, btr);
        }

        // BN stats + apply/quantize/pad
        {
            const float* src = (L == 0) ? x : h;
            const float* g = (L == 0) ? bn0g : bng[L - 1];
            const float* b = (L == 0) ? bn0b : bnb[L - 1];
            int relu = (L == 0) ? 0 : 1;
            dim3 grid(cdiv(KI, T), BN_CHUNKS);
            bn_partial_kernel<<<grid, T>>>(src, KI, KI);
            bn_final_kernel<<<cdiv(KI, T), T>>>(KI);
            bn_apply_half_kernel<<<cdiv((long)MPAD * K2, T), T>>>(src, KI, K2, g, b, relu, ah);
        }

        // fused GEMM pair: xl = A @ Wl, xr = A @ Wr
        {
            dim3 grid(Nc / 128, MPAD / 128, 2);
            gemm_fp16_dual<<<grid, 256, GSMEM>>>(ah, btl, btr, xl, xr, Nc, K2);
        }

        // fused attention (score + online softmax + mean-aggregate + bias)
        {
            dim3 grid(NN, H);
            int relu_here = (L == 3) ? 1 : 0;
            attn_fused_kernel<<<grid, 128>>>(xl, xr, att[L], bia[L], h, H, C, relu_here);
        }
    }

    head_kernel<<<cdiv((long)NN * 32, T), T>>>(h, Wh, bh, pred);
    gather_kernel<<<cdiv(nt, T), T>>>(pred, y, tidx, out, nt);
}

// round 12
// speedup vs baseline: 15.0863x; 1.0203x over previous
#include <cuda_runtime.h>
#include <cuda_fp16.h>
#include <math.h>
#include <stdint.h>

// Problem constants (fixed by the dataset)
#define NN      8000
#define MPAD    8064        // 63 * 128
#define ERAW    64000
#define ETOT    (ERAW + NN)
#define FIN     3201
#define K2MAX   3264        // FIN padded to multiple of 64
#define HMAX    1024
#define BN_CHUNKS 20
#define BN_ROWS   (NN / BN_CHUNKS)

// ---------------- scratch (static device globals; no allocation) -------------
__device__ float  g_h    [(long)NN * HMAX];
__device__ __half g_xl   [(long)MPAD * HMAX];
__device__ __half g_xr   [(long)MPAD * HMAX];
__device__ __half g_Ah   [(long)MPAD * K2MAX];
__device__ __half g_Btl  [(long)HMAX * K2MAX];
__device__ __half g_Btr  [(long)HMAX * K2MAX];
__device__ int    g_cnt  [NN + 32];
__device__ int    g_cur  [NN];
__device__ int    g_off  [NN + 1];
__device__ int    g_csrc [ETOT];
__device__ float  g_bnp1 [BN_CHUNKS * K2MAX];
__device__ float  g_bnp2 [BN_CHUNKS * K2MAX];
__device__ float  g_mean [FIN];
__device__ float  g_rstd [FIN];

// ------------------------------ PTX helpers ----------------------------------
__device__ __forceinline__ uint32_t smem_u32(const void* p) {
    uint32_t a;
    asm("{ .reg .u64 t; cvta.to.shared.u64 t, %1; cvt.u32.u64 %0, t; }"
        : "=r"(a) : "l"(p));
    return a;
}
__device__ __forceinline__ void cp_async16(uint32_t dst, const void* src) {
    asm volatile("cp.async.ca.shared.global [%0], [%1], 16;"
                 :: "r"(dst), "l"(src) : "memory");
}
__device__ __forceinline__ void cp_commit() {
    asm volatile("cp.async.commit_group;" ::: "memory");
}
template<int NG> __device__ __forceinline__ void cp_wait() {
    asm volatile("cp.async.wait_group %0;" :: "n"(NG) : "memory");
}
__device__ __forceinline__ void mma16816(float* c, const uint32_t* a,
                                         uint32_t b0, uint32_t b1) {
    asm volatile(
        "mma.sync.aligned.m16n8k16.row.col.f32.f16.f16.f32 "
        "{%0,%1,%2,%3}, {%4,%5,%6,%7}, {%8,%9}, {%0,%1,%2,%3};"
        : "+f"(c[0]), "+f"(c[1]), "+f"(c[2]), "+f"(c[3])
        : "r"(a[0]), "r"(a[1]), "r"(a[2]), "r"(a[3]), "r"(b0), "r"(b1));
}
__device__ __forceinline__ void ldm_x4(uint32_t* r, uint32_t addr) {
    asm volatile("ldmatrix.sync.aligned.m8n8.x4.shared.b16 {%0,%1,%2,%3}, [%4];"
                 : "=r"(r[0]), "=r"(r[1]), "=r"(r[2]), "=r"(r[3]) : "r"(addr));
}

// ------------------------------- small utils --------------------------------
__global__ void fill_int_kernel(int* p, int v, int n) {
    int i = blockIdx.x * blockDim.x + threadIdx.x;
    if (i < n) p[i] = v;
}

__global__ void count_edges_kernel(const int* __restrict__ ei, int E) {
    int i = blockIdx.x * blockDim.x + threadIdx.x;
    if (i >= E + NN) return;
    int d = (i < E) ? ei[E + i] : (i - E);
    atomicAdd(&g_cnt[d], 1);
}

// single-block exclusive scan over g_cnt -> g_off (shfl + vectorized loads)
__global__ void scan_kernel() {
    __shared__ int wsum[8];
    int tid = threadIdx.x;
    int lane = tid & 31, wid = tid >> 5;
    const int CH = 32;
    int base = tid * CH;
    int vals[CH];
    #pragma unroll
    for (int i = 0; i < CH / 4; i++) {
        int4 v = *(const int4*)&g_cnt[base + i * 4];
        vals[i * 4 + 0] = v.x; vals[i * 4 + 1] = v.y;
        vals[i * 4 + 2] = v.z; vals[i * 4 + 3] = v.w;
    }
    int s = 0;
    #pragma unroll
    for (int i = 0; i < CH; i++) s += vals[i];
    int own = s;
    #pragma unroll
    for (int o = 1; o < 32; o <<= 1) {
        int v = __shfl_up_sync(0xffffffffu, s, o);
        if (lane >= o) s += v;
    }
    if (lane == 31) wsum[wid] = s;
    __syncthreads();
    if (wid == 0 && lane < 8) {
        int w = wsum[lane];
        #pragma unroll
        for (int o = 1; o < 8; o <<= 1) {
            int v = __shfl_up_sync(0xffu, w, o);
            if (lane >= o) w += v;
        }
        wsum[lane] = w - wsum[lane];
    }
    __syncthreads();
    int acc = wsum[wid] + s - own;
    #pragma unroll
    for (int i = 0; i < CH; i++) {
        int n = base + i;
        if (n < NN) { g_off[n] = acc; acc += vals[i]; }
    }
    if (tid == 255) g_off[NN] = acc;
}

__global__ void scatter_kernel(const int* __restrict__ ei, int E) {
    int i = blockIdx.x * blockDim.x + threadIdx.x;
    if (i >= E + NN) return;
    int s, d;
    if (i < E) { s = ei[i]; d = ei[E + i]; }
    else       { s = d = i - E; }
    int pos = g_off[d] + atomicAdd(&g_cur[d], 1);
    g_csrc[pos] = s;
}

// W [Kin x Ncol] fp32 -> Bt [Ncol x K2] fp16 (transposed, zero-padded in K)
__global__ void transpose_half_kernel(const float* __restrict__ W, int Kin, int Ncol, int K2,
                                      __half* __restrict__ o) {
    __shared__ float tile[32][33];
    int k0 = blockIdx.x * 32;
    int n0 = blockIdx.y * 32;
    int tx = threadIdx.x, ty = threadIdx.y;
    #pragma unroll
    for (int j = 0; j < 4; j++) {
        int k = k0 + ty + 8 * j;
        float v = 0.0f;
        if (k < Kin) v = W[(long)k * Ncol + n0 + tx];
        tile[ty + 8 * j][tx] = v;
    }
    __syncthreads();
    #pragma unroll
    for (int j = 0; j < 4; j++) {
        int n = n0 + ty + 8 * j;
        o[(long)n * K2 + k0 + tx] = __float2half(tile[tx][ty + 8 * j]);
    }
}

// ------------------------------- batchnorm ----------------------------------
__global__ void bn_partial_kernel(const float* __restrict__ h, int F, int stride) {
    int f = blockIdx.x * blockDim.x + threadIdx.x;
    if (f >= F) return;
    int r0 = blockIdx.y * BN_ROWS;
    float s = 0.0f, s2 = 0.0f;
    for (int r = r0; r < r0 + BN_ROWS; r++) {
        float v = h[(long)r * stride + f];
        s += v;
        s2 += v * v;
    }
    g_bnp1[blockIdx.y * F + f] = s;
    g_bnp2[blockIdx.y * F + f] = s2;
}

__global__ void bn_final_kernel(int F) {
    int f = blockIdx.x * blockDim.x + threadIdx.x;
    if (f >= F) return;
    float s = 0.0f, s2 = 0.0f;
    #pragma unroll
    for (int c = 0; c < BN_CHUNKS; c++) { s += g_bnp1[c * F + f]; s2 += g_bnp2[c * F + f]; }
    float m = s / (float)NN;
    float var = s2 / (float)NN - m * m;
    g_mean[f] = m;
    g_rstd[f] = rsqrtf(var + 1e-5f);
}

// BN-apply + optional relu + fp16 quantize + padding, writing A [MPAD x K2]
__global__ void bn_apply_half_kernel(const float* __restrict__ in, int Fin, int K2,
                                     const float* __restrict__ gam, const float* __restrict__ bet,
                                     int relu, __half* __restrict__ A) {
    long i = (long)blockIdx.x * blockDim.x + threadIdx.x;
    long total = (long)MPAD * K2;
    if (i >= total) return;
    int row = (int)(i / K2);
    int col = (int)(i % K2);
    float v = 0.0f;
    if (row < NN && col < Fin) {
        v = (in[(long)row * Fin + col] - g_mean[col]) * g_rstd[col] * gam[col] + bet[col];
        if (relu) v = fmaxf(v, 0.0f);
    }
    A[i] = __float2half(v);
}

// ------------------ mma.sync fp16 GEMM, fused xl/xr (z-dim) ------------------
#define STR       40
#define STR2      (STR * 2)
#define BUF_B     (128 * STR2)
#define A_OFF     0
#define B_OFF     (2 * BUF_B)
#define GSMEM     (4 * BUF_B)               // 40960 bytes

__global__ __launch_bounds__(256) void gemm_fp16_dual(
    const __half* __restrict__ Ah,
    const __half* __restrict__ Bt0, const __half* __restrict__ Bt1,
    __half* __restrict__ C0, __half* __restrict__ C1, int N, int K2)
{
    extern __shared__ char sm[];
    uint32_t sb = smem_u32(sm);
    const int tid = threadIdx.x;
    const int wid = tid >> 5, lane = tid & 31;
    const int wm = wid & 1, wn = wid >> 1;
    const int g = lane >> 2, q = lane & 3;
    const long row0 = (long)blockIdx.y * 128;
    const long col0 = (long)blockIdx.x * 128;
    const __half* Bt = blockIdx.z ? Bt1 : Bt0;
    __half* C = blockIdx.z ? C1 : C0;

    float acc[4][4][4];
    #pragma unroll
    for (int i = 0; i < 4; i++)
        #pragma unroll
        for (int j = 0; j < 4; j++)
            #pragma unroll
            for (int t = 0; t < 4; t++) acc[i][j][t] = 0.0f;

    const int NS = K2 >> 5;

    auto issue = [&](int s, int buf) {
        int k0 = s << 5;
        #pragma unroll
        for (int it = 0; it < 2; it++) {
            int c = tid + (it << 8);
            int row = c >> 2;
            int kc = (c & 3) * 8;
            uint32_t so = (uint32_t)(buf * BUF_B + row * STR2 + kc * 2);
            long ga = (row0 + row) * K2 + k0 + kc;
            long gb = (col0 + row) * K2 + k0 + kc;
            cp_async16(sb + A_OFF + so, Ah + ga);
            cp_async16(sb + B_OFF + so, Bt + gb);
        }
        cp_commit();
    };

    const uint32_t aoff = (uint32_t)((wm * 64 + (lane & 15)) * STR2 + (lane >> 4) * 16);
    const uint32_t boff = (uint32_t)((wn * 32 + ((lane >> 4) & 1) * 8 + (lane & 7)) * STR2
                                     + ((lane >> 3) & 1) * 16);

    issue(0, 0);

    for (int s = 0; s < NS; s++) {
        int buf = s & 1;
        if (s + 1 < NS) { issue(s + 1, buf ^ 1); cp_wait<1>(); }
        else            { cp_wait<0>(); }
        __syncthreads();

        uint32_t a_b = sb + A_OFF + buf * BUF_B;
        uint32_t b_b = sb + B_OFF + buf * BUF_B;

        #pragma unroll
        for (int kk = 0; kk < 2; kk++) {
            uint32_t kByte = (uint32_t)(kk * 32);
            uint32_t Bf[8];
            #pragma unroll
            for (int jp = 0; jp < 2; jp++) {
                uint32_t off = boff + kByte + (uint32_t)(jp * 16 * STR2);
                ldm_x4(&Bf[jp * 4], b_b + off);
            }
            #pragma unroll
            for (int i = 0; i < 4; i++) {
                uint32_t off = aoff + kByte + (uint32_t)(i * 16 * STR2);
                uint32_t af[4];
                ldm_x4(af, a_b + off);
                #pragma unroll
                for (int j = 0; j < 4; j++) mma16816(acc[i][j], af, Bf[2*j], Bf[2*j+1]);
            }
        }
        __syncthreads();
    }

    #pragma unroll
    for (int i = 0; i < 4; i++) {
        long r = row0 + wm * 64 + i * 16 + g;
        #pragma unroll
        for (int j = 0; j < 4; j++) {
            long cc = col0 + wn * 32 + j * 8 + 2 * q;
            *(__half2*)(C + r * N + cc)       = __floats2half2_rn(acc[i][j][0], acc[i][j][1]);
            *(__half2*)(C + (r + 8) * N + cc) = __floats2half2_rn(acc[i][j][2], acc[i][j][3]);
        }
    }
}

// -------- fused attention: warp per (node, head), online softmax -------------
// C = 512 always; 16 features per lane; butterfly shfl reduction (no smem/sync)
__device__ __forceinline__ void unpack16(const uint4& a, const uint4& b, float* v) {
    const __half2* pa = (const __half2*)&a;
    const __half2* pb = (const __half2*)&b;
    #pragma unroll
    for (int t = 0; t < 4; t++) {
        float2 f = __half22float2(pa[t]);
        v[2 * t] = f.x; v[2 * t + 1] = f.y;
    }
    #pragma unroll
    for (int t = 0; t < 4; t++) {
        float2 f = __half22float2(pb[t]);
        v[8 + 2 * t] = f.x; v[8 + 2 * t + 1] = f.y;
    }
}

__global__ __launch_bounds__(256) void attn_warp_kernel(
    const __half* __restrict__ xl, const __half* __restrict__ xr,
    const float* __restrict__ att, const float* __restrict__ bias,
    float* __restrict__ out, int H, int relu)
{
    const int gw = (blockIdx.x * blockDim.x + threadIdx.x) >> 5;
    const int lane = threadIdx.x & 31;
    if (gw >= NN * H) return;
    const int n = gw / H, h = gw % H;
    const int C = 512;
    const int HC = H * C;
    const int f0 = h * C + lane * 16;

    float attv[16], xrv[16];
    #pragma unroll
    for (int j = 0; j < 16; j += 4) {
        float4 w = *(const float4*)(att + f0 + j - h * C + h * C); // att[h*C + lane*16 + j]
        attv[j] = w.x; attv[j + 1] = w.y; attv[j + 2] = w.z; attv[j + 3] = w.w;
    }
    {
        uint4 xa = *(const uint4*)(xr + (long)n * HC + f0);
        uint4 xb = *(const uint4*)(xr + (long)n * HC + f0 + 8);
        unpack16(xa, xb, xrv);
    }

    const int st = g_off[n], en = g_off[n + 1];

    float m = -3.0e38f, ssum = 0.0f;
    float acc[16];
    #pragma unroll
    for (int j = 0; j < 16; j++) acc[j] = 0.0f;

    long base0 = (long)g_csrc[st] * HC + f0;
    uint4 ra = *(const uint4*)(xl + base0);
    uint4 rb = *(const uint4*)(xl + base0 + 8);

    for (int p = st; p < en; p++) {
        uint4 ca = ra, cb = rb;
        if (p + 1 < en) {
            long b = (long)g_csrc[p + 1] * HC + f0;
            ra = *(const uint4*)(xl + b);
            rb = *(const uint4*)(xl + b + 8);
        }
        float av[16];
        unpack16(ca, cb, av);

        float part = 0.0f;
        #pragma unroll
        for (int j = 0; j < 16; j++) {
            float z = av[j] + xrv[j];
            z = (z > 0.f) ? z : 0.2f * z;
            part = fmaf(z, attv[j], part);
        }
        #pragma unroll
        for (int o = 16; o; o >>= 1) part += __shfl_xor_sync(0xffffffffu, part, o);

        float mnew = fmaxf(m, part);
        float corr = __expf(m - mnew);
        float w = __expf(part - mnew);
        ssum = ssum * corr + w;
        #pragma unroll
        for (int j = 0; j < 16; j++) acc[j] = fmaf(acc[j], corr, w * av[j]);
        m = mnew;
    }

    float inv = 1.0f / (ssum * (float)(en - st));
    #pragma unroll
    for (int j = 0; j < 16; j += 4) {
        float4 b = *(const float4*)(bias + f0 + j);
        float4 o4;
        o4.x = acc[j]     * inv + b.x;
        o4.y = acc[j + 1] * inv + b.y;
        o4.z = acc[j + 2] * inv + b.z;
        o4.w = acc[j + 3] * inv + b.w;
        if (relu) {
            o4.x = fmaxf(o4.x, 0.f); o4.y = fmaxf(o4.y, 0.f);
            o4.z = fmaxf(o4.z, 0.f); o4.w = fmaxf(o4.w, 0.f);
        }
        *(float4*)(out + (long)n * HC + f0 + j) = o4;
    }
}

// -------------------- fused head + gather: warp per train idx ----------------
__global__ void head_gather_kernel(const float* __restrict__ h, const float* __restrict__ Wh,
                                   const float* __restrict__ bh,
                                   const float* __restrict__ y, const int* __restrict__ tidx,
                                   float* __restrict__ out, int nt) {
    int warp = (blockIdx.x * blockDim.x + threadIdx.x) >> 5;
    int lane = threadIdx.x & 31;
    if (warp >= nt) return;
    int n = tidx[warp];
    const float* p = h + (long)n * 512;
    float s = 0.0f;
    for (int c = lane * 4; c < 512; c += 128) {
        float4 v = *(const float4*)(p + c);
        float4 w = *(const float4*)(Wh + c);
        s += v.x * w.x + v.y * w.y + v.z * w.z + v.w * w.w;
    }
    #pragma unroll
    for (int o = 16; o; o >>= 1) s += __shfl_xor_sync(0xffffffffu, s, o);
    if (lane == 0) {
        out[warp]      = 1.0f / (1.0f + expf(-(s + bh[0])));
        out[nt + warp] = y[n];
    }
}

// --------------------------------- host side ---------------------------------
static inline long cdiv(long a, long b) { return (a + b - 1) / b; }

extern "C" void kernel_launch(void* const* d_in, const int* in_sizes, int n_in,
                              void* d_out, int out_size) {
    const float* x    = (const float*)d_in[0];
    const int*   ei   = (const int*)  d_in[1];
    const float* y    = (const float*)d_in[2];
    const int*   tidx = (const int*)  d_in[3];
    const float* bn0g = (const float*)d_in[4];
    const float* bn0b = (const float*)d_in[5];
    const float* Wl[4] = { (const float*)d_in[6],  (const float*)d_in[12],
                           (const float*)d_in[18], (const float*)d_in[24] };
    const float* Wr[4] = { (const float*)d_in[7],  (const float*)d_in[13],
                           (const float*)d_in[19], (const float*)d_in[25] };
    const float* att[4] = { (const float*)d_in[8],  (const float*)d_in[14],
                            (const float*)d_in[20], (const float*)d_in[26] };
    const float* bia[4] = { (const float*)d_in[9],  (const float*)d_in[15],
                            (const float*)d_in[21], (const float*)d_in[27] };
    const float* bng[3] = { (const float*)d_in[10], (const float*)d_in[16],
                            (const float*)d_in[22] };
    const float* bnb[3] = { (const float*)d_in[11], (const float*)d_in[17],
                            (const float*)d_in[23] };
    const float* Wh = (const float*)d_in[28];
    const float* bh = (const float*)d_in[29];
    float* out = (float*)d_out;

    int E  = in_sizes[1] / 2;
    int nt = in_sizes[3];

    float *h;
    int *cnt, *cur;
    __half *xl, *xr, *ah, *btl, *btr;
    cudaGetSymbolAddress((void**)&h,     g_h);
    cudaGetSymbolAddress((void**)&xl,    g_xl);
    cudaGetSymbolAddress((void**)&xr,    g_xr);
    cudaGetSymbolAddress((void**)&cnt,   g_cnt);
    cudaGetSymbolAddress((void**)&cur,   g_cur);
    cudaGetSymbolAddress((void**)&ah,    g_Ah);
    cudaGetSymbolAddress((void**)&btl,   g_Btl);
    cudaGetSymbolAddress((void**)&btr,   g_Btr);

    cudaFuncSetAttribute(gemm_fp16_dual, cudaFuncAttributeMaxDynamicSharedMemorySize, GSMEM);

    const int T = 256;
    int Etot = E + NN;

    // edges -> CSR (once per launch)
    fill_int_kernel<<<cdiv(NN + 32, T), T>>>(cnt, 0, NN + 32);
    fill_int_kernel<<<cdiv(NN, T), T>>>(cur, 0, NN);
    count_edges_kernel<<<cdiv(Etot, T), T>>>(ei, E);
    scan_kernel<<<1, 256>>>();
    scatter_kernel<<<cdiv(Etot, T), T>>>(ei, E);

    int Kin [4] = { FIN, 1024, 512, 512 };
    int K2s [4] = { K2MAX, 1024, 512, 512 };
    int Ncs [4] = { 1024, 512, 512, 512 };
    int heads[4] = { 2, 1, 1, 1 };

    for (int L = 0; L < 4; L++) {
        int KI = Kin[L], K2 = K2s[L], Nc = Ncs[L];
        int H = heads[L];

        // weight transpose -> fp16
        {
            dim3 grid(K2 / 32, Nc / 32), blk(32, 8);
            transpose_half_kernel<<<grid, blk>>>(Wl[L], KI, Nc, K2, btl);
            transpose_half_kernel<<<grid, blk>>>(Wr[L], KI, Nc, K2, btr);
        }

        // BN stats + apply/quantize/pad
        {
            const float* src = (L == 0) ? x : h;
            const float* g = (L == 0) ? bn0g : bng[L - 1];
            const float* b = (L == 0) ? bn0b : bnb[L - 1];
            int relu = (L == 0) ? 0 : 1;
            dim3 grid(cdiv(KI, T), BN_CHUNKS);
            bn_partial_kernel<<<grid, T>>>(src, KI, KI);
            bn_final_kernel<<<cdiv(KI, T), T>>>(KI);
            bn_apply_half_kernel<<<cdiv((long)MPAD * K2, T), T>>>(src, KI, K2, g, b, relu, ah);
        }

        // fused GEMM pair: xl = A @ Wl, xr = A @ Wr
        {
            dim3 grid(Nc / 128, MPAD / 128, 2);
            gemm_fp16_dual<<<grid, 256, GSMEM>>>(ah, btl, btr, xl, xr, Nc, K2);
        }

        // fused attention: warp per (node, head)
        {
            int relu_here = (L == 3) ? 1 : 0;
            int warps = NN * H;
            attn_warp_kernel<<<cdiv((long)warps * 32, T), T>>>(xl, xr, att[L], bia[L],
                                                               h, H, relu_here);
        }
    }

    head_gather_kernel<<<cdiv((long)nt * 32, T), T>>>(h, Wh, bh, y, tidx, out, nt);
}